// round 6
// baseline (speedup 1.0000x reference)
#include <cuda_runtime.h>
#include <cuda_bf16.h>
#include <stdint.h>
#include <math.h>

using bf16 = __nv_bfloat16;

constexpr int BATCH = 4, SEQ = 1024, CDIM = 2048, NHEAD = 16, HS = 128;
constexpr int NLQ = 512, NLKV = 512, DHR = 64, QKDIM = 576;

// ---- scratch (hi/lo bf16 split pairs) ----
__device__ __align__(128) bf16 g_x_h[8388608],   g_x_l[8388608];
__device__ __align__(128) bf16 g_Wdq_h[1048576], g_Wdq_l[1048576];
__device__ __align__(128) bf16 g_Wdkv_h[1048576],g_Wdkv_l[1048576];
__device__ __align__(128) bf16 g_Wkr_h[131072],  g_Wkr_l[131072];
__device__ __align__(128) bf16 g_Wqr_h[524288],  g_Wqr_l[524288];
__device__ __align__(128) bf16 g_Wuq_h[1048576], g_Wuq_l[1048576];
__device__ __align__(128) bf16 g_Wo_h[4194304],  g_Wo_l[4194304];
__device__ __align__(128) bf16 g_WuvT_h[1048576],g_WuvT_l[1048576];
__device__ __align__(128) bf16 g_WukT_h[1048576],g_WukT_l[1048576];
__device__ __align__(128) bf16 g_Z_h[1048576],   g_Z_l[1048576];
__device__ __align__(128) bf16 g_keffT_h[4194304],g_keffT_l[4194304];
__device__ __align__(128) bf16 g_cq_h[2097152],  g_cq_l[2097152];
__device__ __align__(128) bf16 g_KC_h[2359296],  g_KC_l[2359296];
__device__ __align__(128) bf16 g_QC_h[37748736], g_QC_l[37748736];
__device__ __align__(128) bf16 g_P_h[67108864],  g_P_l[67108864];
__device__ __align__(128) bf16 g_vT_h[8388608],  g_vT_l[8388608];   // [b,h] 128x1024
__device__ __align__(128) float g_cqr[4194304], g_ckr[262144], g_S[67108864];

// ---- helpers ----
__device__ __forceinline__ void split2(float v, bf16& h, bf16& l) {
    h = __float2bfloat16(v);
    l = __float2bfloat16(v - __bfloat162float(h));
}
__device__ __forceinline__ void ldsm4(uint32_t* r, uint32_t addr) {
    asm volatile("ldmatrix.sync.aligned.m8n8.x4.shared.b16 {%0,%1,%2,%3}, [%4];"
        : "=r"(r[0]), "=r"(r[1]), "=r"(r[2]), "=r"(r[3]) : "r"(addr));
}
__device__ __forceinline__ void mma16816(float* d, const uint32_t* a, const uint32_t* b) {
    asm volatile("mma.sync.aligned.m16n8k16.row.col.f32.bf16.bf16.f32 "
        "{%0,%1,%2,%3}, {%4,%5,%6,%7}, {%8,%9}, {%0,%1,%2,%3};"
        : "+f"(d[0]), "+f"(d[1]), "+f"(d[2]), "+f"(d[3])
        : "r"(a[0]), "r"(a[1]), "r"(a[2]), "r"(a[3]), "r"(b[0]), "r"(b[1]));
}
__device__ __forceinline__ uint32_t swz(uint32_t tile_base, int r, int kb16) {
    uint32_t byte = (uint32_t)(r * 128 + kb16 * 16);
    return tile_base + (byte ^ ((byte >> 3) & 0x70));
}

// ---- HMMA batched GEMM: D = (Ah+Al) @ (Bh+Bl)^T (3-term split) ----
// CTA tile 256x128, warp tile 64x64 (8 warps, 4x2). K-chunks of 64.
// A: MxK (lda), B: NxK (ldb), K-contiguous. Batch z: z0=z/zdiv, z1=z%zdiv.
// mode 0: fp32 C; mode 1: split Chi/Clo. causal 1: skip masked tiles; 2: clip K.
constexpr int BM = 256, BN = 128, BKC = 64;
constexpr int A_T = 32768;                    // 256x64 bf16
constexpr int B_T = 16384;                    // 128x64 bf16
constexpr int BUF_B  = 2*A_T + 2*B_T;         // Ah, Al, Bh, Bl = 96 KB
constexpr int NSTAGE = 2;
constexpr int SMEM_GEMM = NSTAGE * BUF_B;     // 192 KB

__global__ __launch_bounds__(256, 1)
void gemm3(const bf16* __restrict__ Ah, const bf16* __restrict__ Al,
           long long sA0, long long sA1, int lda,
           const bf16* __restrict__ Bh, const bf16* __restrict__ Bl,
           long long sB0, long long sB1, int ldb,
           float* __restrict__ C, bf16* __restrict__ Chi, bf16* __restrict__ Clo,
           long long sC0, long long sC1, int ldc,
           int M, int N, int K, int zdiv, int mode, int causal)
{
    const int m0 = blockIdx.y * BM, n0 = blockIdx.x * BN;
    if (causal == 1 && n0 >= m0 + BM) return;
    const int z = blockIdx.z, z0 = z / zdiv, z1 = z % zdiv;
    Ah += z0*sA0 + z1*sA1;  Al += z0*sA0 + z1*sA1;
    Bh += z0*sB0 + z1*sB1;  Bl += z0*sB0 + z1*sB1;
    const long long coff = z0*sC0 + z1*sC1;

    extern __shared__ __align__(1024) char smem[];
    const uint32_t sb = (uint32_t)__cvta_generic_to_shared(smem);
    const int tid = threadIdx.x, wid = tid >> 5, lane = tid & 31;
    const int wm = (wid & 3) * 64;      // warp m-offset
    const int wn = (wid >> 2) * 64;     // warp n-offset

    const int Keff = (causal == 2) ? min(K, m0 + BM) : K;
    const int nch = Keff / BKC;

    // fill one 96KB stage: Ah(2048 ch16), Al(2048), Bh(1024), Bl(1024)
    auto fill = [&](int buf, int k0) {
        const uint32_t bb = sb + buf * BUF_B;
#pragma unroll
        for (int it = 0; it < 24; it++) {
            int idx = tid + it * 256;           // 0..6143 chunks of 16B
            const bf16* src;
            uint32_t dst;
            bool ok;
            if (idx < 4096) {                   // A tiles
                int sub = idx >> 11;            // 0=Ah,1=Al
                int li  = idx & 2047;
                int r = li >> 3, c16 = li & 7;
                uint32_t byte = (uint32_t)(r*128 + c16*16);
                dst = bb + sub*A_T + (byte ^ ((byte >> 3) & 0x70));
                ok = (m0 + r) < M;
                src = (sub == 0 ? Ah : Al) + (long long)(m0 + r)*lda + k0 + c16*8;
            } else {                            // B tiles
                int li = idx - 4096;
                int sub = li >> 10;             // 0=Bh,1=Bl
                li &= 1023;
                int r = li >> 3, c16 = li & 7;
                uint32_t byte = (uint32_t)(r*128 + c16*16);
                dst = bb + 2*A_T + sub*B_T + (byte ^ ((byte >> 3) & 0x70));
                ok = (n0 + r) < N;
                src = (sub == 0 ? Bh : Bl) + (long long)(n0 + r)*ldb + k0 + c16*8;
            }
            if (ok)
                asm volatile("cp.async.cg.shared.global [%0], [%1], 16;"::"r"(dst),"l"(src):"memory");
            else
                asm volatile("st.shared.v4.b32 [%0], {%1,%1,%1,%1};"::"r"(dst),"r"(0u):"memory");
        }
        asm volatile("cp.async.commit_group;" ::: "memory");
    };

    float acc[4][8][4];
#pragma unroll
    for (int i = 0; i < 4; i++)
#pragma unroll
        for (int j = 0; j < 8; j++)
#pragma unroll
            for (int q = 0; q < 4; q++) acc[i][j][q] = 0.f;

    fill(0, 0);

    for (int ci = 0; ci < nch; ci++) {
        if (ci + 1 < nch) {
            fill((ci + 1) & 1, (ci + 1) * BKC);
            asm volatile("cp.async.wait_group 1;" ::: "memory");
        } else {
            asm volatile("cp.async.wait_group 0;" ::: "memory");
        }
        __syncthreads();

        const uint32_t bb = sb + (ci & 1) * BUF_B;
        const uint32_t tAh = bb, tAl = bb + A_T, tBh = bb + 2*A_T, tBl = bb + 2*A_T + B_T;
        const int arow = wm + (lane & 15);
        const int brow = wn + (lane & 7) + ((lane >> 4) << 3);

#pragma unroll
        for (int ks = 0; ks < 4; ks++) {
            const int akb = ks*2 + (lane >> 4);
            const int bkb = ks*2 + ((lane >> 3) & 1);
            uint32_t ah[4][4], al[4][4], bh[4][4], bl[4][4];
#pragma unroll
            for (int mi = 0; mi < 4; mi++) {
                ldsm4(ah[mi], swz(tAh, arow + mi*16, akb));
                ldsm4(al[mi], swz(tAl, arow + mi*16, akb));
            }
#pragma unroll
            for (int nj = 0; nj < 4; nj++) {
                ldsm4(bh[nj], swz(tBh, brow + nj*16, bkb));
                ldsm4(bl[nj], swz(tBl, brow + nj*16, bkb));
            }
#pragma unroll
            for (int mi = 0; mi < 4; mi++)
#pragma unroll
                for (int nj = 0; nj < 4; nj++) {
                    mma16816(acc[mi][2*nj],   ah[mi], &bh[nj][0]);
                    mma16816(acc[mi][2*nj+1], ah[mi], &bh[nj][2]);
                    mma16816(acc[mi][2*nj],   ah[mi], &bl[nj][0]);
                    mma16816(acc[mi][2*nj+1], ah[mi], &bl[nj][2]);
                    mma16816(acc[mi][2*nj],   al[mi], &bh[nj][0]);
                    mma16816(acc[mi][2*nj+1], al[mi], &bh[nj][2]);
                }
        }
        __syncthreads();
    }

    // epilogue straight from register fragments
#pragma unroll
    for (int mi = 0; mi < 4; mi++) {
        const int r0 = m0 + wm + mi*16 + (lane >> 2);
        const bool ok0 = r0 < M, ok1 = (r0 + 8) < M;
#pragma unroll
        for (int nb = 0; nb < 8; nb++) {
            const int c = n0 + wn + nb*8 + (lane & 3)*2;
            if (c < N) {
                const float* a = acc[mi][nb];
                const long long off0 = coff + (long long)r0 * ldc + c;
                const long long off1 = off0 + 8LL * ldc;
                if (mode == 0) {
                    if (ok0) *(float2*)(C + off0) = make_float2(a[0], a[1]);
                    if (ok1) *(float2*)(C + off1) = make_float2(a[2], a[3]);
                } else {
                    bf16 h0,l0,h1,l1;
                    if (ok0) {
                        split2(a[0],h0,l0); split2(a[1],h1,l1);
                        *(__nv_bfloat162*)(Chi+off0) = __halves2bfloat162(h0,h1);
                        *(__nv_bfloat162*)(Clo+off0) = __halves2bfloat162(l0,l1);
                    }
                    if (ok1) {
                        split2(a[2],h0,l0); split2(a[3],h1,l1);
                        *(__nv_bfloat162*)(Chi+off1) = __halves2bfloat162(h0,h1);
                        *(__nv_bfloat162*)(Clo+off1) = __halves2bfloat162(l0,l1);
                    }
                }
            }
        }
    }
}

// ---- prep kernels ----
__global__ void split_copy4(const float4* __restrict__ s, __nv_bfloat162* __restrict__ h,
                            __nv_bfloat162* __restrict__ l, long long n4)
{
    long long i = (long long)blockIdx.x*256 + threadIdx.x;
    if (i >= n4) return;
    float4 v = s[i];
    bf16 h0,l0,h1,l1;
    split2(v.x,h0,l0); split2(v.y,h1,l1);
    h[2*i]   = __halves2bfloat162(h0,h1);
    l[2*i]   = __halves2bfloat162(l0,l1);
    split2(v.z,h0,l0); split2(v.w,h1,l1);
    h[2*i+1] = __halves2bfloat162(h0,h1);
    l[2*i+1] = __halves2bfloat162(l0,l1);
}

// fp32 src [b][R][C] -> split bf16 dst [b][C][R]
__global__ void split_transpose(const float* __restrict__ src, bf16* __restrict__ hi,
                                bf16* __restrict__ lo, int R, int C,
                                long long sIn, long long sOut)
{
    __shared__ float t[32][33];
    int b = blockIdx.z, c0 = blockIdx.x*32, r0 = blockIdx.y*32;
    int tx = threadIdx.x, ty = threadIdx.y;
    const float* s = src + (long long)b*sIn;
#pragma unroll
    for (int j = 0; j < 4; j++)
        t[ty + j*8][tx] = s[(long long)(r0 + ty + j*8)*C + c0 + tx];
    __syncthreads();
#pragma unroll
    for (int j = 0; j < 4; j++) {
        long long o = (long long)b*sOut + (long long)(c0 + ty + j*8)*R + r0 + tx;
        bf16 h, l; split2(t[tx][ty + j*8], h, l);
        hi[o] = h; lo[o] = l;
    }
}

__global__ void rope_q_kernel(const float* __restrict__ cqr, const float* __restrict__ fc,
                              const float* __restrict__ fs, bf16* __restrict__ QCh,
                              bf16* __restrict__ QCl)
{
    int idx = blockIdx.x*256 + threadIdx.x;
    if (idx >= BATCH*SEQ*NHEAD*32) return;
    int j = idx & 31, h = (idx >> 5) & 15, bt = idx >> 9;
    int t = bt & (SEQ-1), b = bt >> 10;
    long long src = (long long)bt*(NHEAD*DHR) + h*DHR + 2*j;
    float re = cqr[src], im = cqr[src+1];
    float c = fc[t*32 + j], s = fs[t*32 + j];
    long long row = ((long long)(b*NHEAD + h)*SEQ + t)*QKDIM + NLKV + 2*j;
    bf16 h0,l0,h1,l1;
    split2(re*c - im*s, h0, l0); split2(re*s + im*c, h1, l1);
    QCh[row] = h0; QCl[row] = l0; QCh[row+1] = h1; QCl[row+1] = l1;
}

__global__ void rope_k_kernel(const float* __restrict__ ckr, const float* __restrict__ fc,
                              const float* __restrict__ fs, bf16* __restrict__ KCh,
                              bf16* __restrict__ KCl)
{
    int idx = blockIdx.x*256 + threadIdx.x;
    if (idx >= BATCH*SEQ*32) return;
    int j = idx & 31, bt = idx >> 5, t = bt & (SEQ-1);
    long long src = (long long)bt*DHR + 2*j;
    float re = ckr[src], im = ckr[src+1];
    float c = fc[t*32 + j], s = fs[t*32 + j];
    long long row = (long long)bt*QKDIM + NLKV + 2*j;
    bf16 h0,l0,h1,l1;
    split2(re*c - im*s, h0, l0); split2(re*s + im*c, h1, l1);
    KCh[row] = h0; KCl[row] = l0; KCh[row+1] = h1; KCl[row+1] = l1;
}

__global__ __launch_bounds__(256)
void softmax_split(const float* __restrict__ S, bf16* __restrict__ Phi, bf16* __restrict__ Plo)
{
    const float scale = 0.07216878364870322f;  // 1/sqrt(192)
    long long r = blockIdx.x;
    int t = (int)(r & (SEQ-1));
    const float* row = S + r*SEQ;
    bf16* ph = Phi + r*SEQ; bf16* pl = Plo + r*SEQ;
    int tid = threadIdx.x;
    __shared__ float red[256];
    float v[4], m = -1e30f;
#pragma unroll
    for (int j = 0; j < 4; j++) {
        int i = tid + j*256;
        v[j] = (i <= t) ? row[i] : -1e30f;
        m = fmaxf(m, v[j]);
    }
    red[tid] = m; __syncthreads();
    for (int s = 128; s > 0; s >>= 1) { if (tid < s) red[tid] = fmaxf(red[tid], red[tid+s]); __syncthreads(); }
    m = red[0]*scale; __syncthreads();
    float sum = 0.f;
#pragma unroll
    for (int j = 0; j < 4; j++) {
        int i = tid + j*256;
        float e = (i <= t) ? __expf(v[j]*scale - m) : 0.f;
        v[j] = e; sum += e;
    }
    red[tid] = sum; __syncthreads();
    for (int s = 128; s > 0; s >>= 1) { if (tid < s) red[tid] += red[tid+s]; __syncthreads(); }
    float inv = 1.0f / red[0]; __syncthreads();
#pragma unroll
    for (int j = 0; j < 4; j++) {
        int i = tid + j*256;
        bf16 h, l; split2(v[j]*inv, h, l);
        ph[i] = h; pl[i] = l;
    }
}

// ---- launch ----
extern "C" void kernel_launch(void* const* d_in, const int* in_sizes, int n_in,
                              void* d_out, int out_size)
{
    const float* x     = (const float*)d_in[0];
    const float* W_dq  = (const float*)d_in[1];
    const float* W_uq  = (const float*)d_in[2];
    const float* W_dkv = (const float*)d_in[3];
    const float* W_uk  = (const float*)d_in[4];
    const float* W_uv  = (const float*)d_in[5];
    const float* W_o   = (const float*)d_in[6];
    const float* W_qr  = (const float*)d_in[7];
    const float* W_kr  = (const float*)d_in[8];
    const float* fc    = (const float*)d_in[9];
    const float* fs    = (const float*)d_in[10];
    float* out = (float*)d_out;

    cudaFuncSetAttribute(gemm3, cudaFuncAttributeMaxDynamicSharedMemorySize, SMEM_GEMM);

#define SYM(v, s) cudaGetSymbolAddress((void**)&v, s)
    bf16 *xh,*xl,*dqh,*dql,*dkvh,*dkvl,*krh,*krl,*qrh,*qrl,*uqh,*uql,*woh,*wol;
    bf16 *uvTh,*uvTl,*ukTh,*ukTl,*Zh,*Zl,*keh,*kel,*cqh,*cql,*KCh,*KCl,*QCh,*QCl;
    bf16 *Ph,*Pl,*vTh,*vTl;
    float *cqr,*ckr,*S;
    SYM(xh,g_x_h); SYM(xl,g_x_l); SYM(dqh,g_Wdq_h); SYM(dql,g_Wdq_l);
    SYM(dkvh,g_Wdkv_h); SYM(dkvl,g_Wdkv_l); SYM(krh,g_Wkr_h); SYM(krl,g_Wkr_l);
    SYM(qrh,g_Wqr_h); SYM(qrl,g_Wqr_l); SYM(uqh,g_Wuq_h); SYM(uql,g_Wuq_l);
    SYM(woh,g_Wo_h); SYM(wol,g_Wo_l); SYM(uvTh,g_WuvT_h); SYM(uvTl,g_WuvT_l);
    SYM(ukTh,g_WukT_h); SYM(ukTl,g_WukT_l); SYM(Zh,g_Z_h); SYM(Zl,g_Z_l);
    SYM(keh,g_keffT_h); SYM(kel,g_keffT_l); SYM(cqh,g_cq_h); SYM(cql,g_cq_l);
    SYM(KCh,g_KC_h); SYM(KCl,g_KC_l); SYM(QCh,g_QC_h); SYM(QCl,g_QC_l);
    SYM(Ph,g_P_h); SYM(Pl,g_P_l); SYM(vTh,g_vT_h); SYM(vTl,g_vT_l);
    SYM(cqr,g_cqr); SYM(ckr,g_ckr); SYM(S,g_S);
#undef SYM

    auto SC = [](const float* s, bf16* h, bf16* l, long long n) {
        split_copy4<<<(unsigned)((n/4 + 255)/256), 256>>>(
            (const float4*)s, (__nv_bfloat162*)h, (__nv_bfloat162*)l, n/4);
    };
    SC(x, xh, xl, 8388608);
    SC(W_dq, dqh, dql, 1048576);
    SC(W_dkv, dkvh, dkvl, 1048576);
    SC(W_kr, krh, krl, 131072);
    SC(W_qr, qrh, qrl, 524288);
    SC(W_uq, uqh, uql, 1048576);
    SC(W_o, woh, wol, 4194304);
    // W_uv (2048x512) -> WuvT (512x2048); W_uk per head (128x512) -> WukT (512x128)
    split_transpose<<<dim3(16, 64, 1), dim3(32, 8)>>>(W_uv, uvTh, uvTl, 2048, 512, 0, 0);
    split_transpose<<<dim3(16, 4, 16), dim3(32, 8)>>>(W_uk, ukTh, ukTl, 128, 512, 65536, 65536);

    dim3 blk(256);
    // 1. Z = W_o @ W_uv  (2048x512, K=2048) -> split
    gemm3<<<dim3(4, 8, 1), blk, SMEM_GEMM>>>(woh, wol, 0, 0, 2048, uvTh, uvTl, 0, 0, 2048,
        nullptr, Zh, Zl, 0, 0, 512, 2048, 512, 2048, 1, 1, 0);
    // 2. keffT[h] = WukT_h @ Wuq_h^T  (512x512, K=128) -> split
    gemm3<<<dim3(4, 2, 16), blk, SMEM_GEMM>>>(ukTh, ukTl, 0, 65536, 128, uqh, uql, 0, 128, 2048,
        nullptr, keh, kel, 0, 262144, 512, 512, 512, 128, 16, 1, 0);
    // 3. c_q = x @ W_dq^T (4096x512, K=2048) -> split
    gemm3<<<dim3(4, 16, 1), blk, SMEM_GEMM>>>(xh, xl, 0, 0, 2048, dqh, dql, 0, 0, 2048,
        nullptr, cqh, cql, 0, 0, 512, 4096, 512, 2048, 1, 1, 0);
    // 4. c_kv -> KC[:, 0:512] split (ldc=576)
    gemm3<<<dim3(4, 16, 1), blk, SMEM_GEMM>>>(xh, xl, 0, 0, 2048, dkvh, dkvl, 0, 0, 2048,
        nullptr, KCh, KCl, 0, 0, QKDIM, 4096, 512, 2048, 1, 1, 0);
    // 5. vT[b,h] = Z_h (128x512) @ c_kv[b]^T (1024x512) -> split (128x1024)
    gemm3<<<dim3(8, 1, 64), blk, SMEM_GEMM>>>(Zh, Zl, 0, 65536, 512,
        KCh, KCl, 589824, 0, QKDIM,
        nullptr, vTh, vTl, 2097152, 131072, 1024, 128, 1024, 512, 16, 1, 0);
    // 6. c_kr = x @ W_kr^T (4096x64) -> fp32
    gemm3<<<dim3(1, 16, 1), blk, SMEM_GEMM>>>(xh, xl, 0, 0, 2048, krh, krl, 0, 0, 2048,
        ckr, nullptr, nullptr, 0, 0, 64, 4096, 64, 2048, 1, 0, 0);
    // 7. c_qr = c_q @ W_qr^T (4096x1024, K=512) -> fp32
    gemm3<<<dim3(8, 16, 1), blk, SMEM_GEMM>>>(cqh, cql, 0, 0, 512, qrh, qrl, 0, 0, 512,
        cqr, nullptr, nullptr, 0, 0, 1024, 4096, 1024, 512, 1, 0, 0);
    // 8. RoPE tails
    rope_q_kernel<<<(BATCH*SEQ*NHEAD*32 + 255)/256, 256>>>(cqr, fc, fs, QCh, QCl);
    rope_k_kernel<<<(BATCH*SEQ*32 + 255)/256, 256>>>(ckr, fc, fs, KCh, KCl);
    // 9. q_abs[b,h] = c_q[b] @ keffT[h]^T -> QC[:, 0:512] split (ldc=576)
    gemm3<<<dim3(4, 4, 64), blk, SMEM_GEMM>>>(cqh, cql, 524288, 0, 512, keh, kel, 0, 262144, 512,
        nullptr, QCh, QCl, 9437184, 589824, QKDIM, 1024, 512, 512, 16, 1, 0);
    // 10. S[b,h] = QC[b,h] @ KC[b]^T (1024x1024, K=576), causal skip -> fp32
    gemm3<<<dim3(8, 4, 64), blk, SMEM_GEMM>>>(QCh, QCl, 9437184, 589824, QKDIM,
        KCh, KCl, 589824, 0, QKDIM,
        S, nullptr, nullptr, 16777216, 1048576, 1024, 1024, 1024, 576, 16, 0, 1);
    // 11. softmax -> split P
    softmax_split<<<BATCH*NHEAD*SEQ, 256>>>(S, Ph, Pl);
    // 12. out[b][:, h*128:+128] = P[b,h] @ vT[b,h]^T (1024x128, K clipped) -> fp32
    gemm3<<<dim3(1, 4, 64), blk, SMEM_GEMM>>>(Ph, Pl, 16777216, 1048576, 1024,
        vTh, vTl, 2097152, 131072, 1024,
        out, nullptr, nullptr, 2097152, 128, 2048, 1024, 128, 1024, 16, 0, 2);
}

// round 8
// speedup vs baseline: 1.9787x; 1.9787x over previous
#include <cuda_runtime.h>
#include <cuda_bf16.h>
#include <stdint.h>
#include <math.h>

using bf16 = __nv_bfloat16;

constexpr int BATCH = 4, SEQ = 1024, CDIM = 2048, NHEAD = 16, HS = 128;
constexpr int NLQ = 512, NLKV = 512, DHR = 64, QKDIM = 576;

// ---- scratch (hi/lo bf16 split pairs) ----
__device__ __align__(128) bf16 g_x_h[8388608],   g_x_l[8388608];
__device__ __align__(128) bf16 g_Wdq_h[1048576], g_Wdq_l[1048576];
__device__ __align__(128) bf16 g_Wdkv_h[1048576],g_Wdkv_l[1048576];
__device__ __align__(128) bf16 g_Wkr_h[131072],  g_Wkr_l[131072];
__device__ __align__(128) bf16 g_Wqr_h[524288],  g_Wqr_l[524288];
__device__ __align__(128) bf16 g_Wuq_h[1048576], g_Wuq_l[1048576];
__device__ __align__(128) bf16 g_Wo_h[4194304],  g_Wo_l[4194304];
__device__ __align__(128) bf16 g_WuvT_h[1048576],g_WuvT_l[1048576];
__device__ __align__(128) bf16 g_WukT_h[1048576],g_WukT_l[1048576];
__device__ __align__(128) bf16 g_Z_h[1048576],   g_Z_l[1048576];
__device__ __align__(128) bf16 g_keffT_h[4194304],g_keffT_l[4194304];
__device__ __align__(128) bf16 g_cq_h[2097152],  g_cq_l[2097152];
__device__ __align__(128) bf16 g_KC_h[2359296],  g_KC_l[2359296];
__device__ __align__(128) bf16 g_QC_h[37748736], g_QC_l[37748736];
__device__ __align__(128) bf16 g_P_h[67108864],  g_P_l[67108864];
__device__ __align__(128) bf16 g_vT_h[8388608],  g_vT_l[8388608];   // [b,h] 128x1024
__device__ __align__(128) float g_cqr[4194304], g_ckr[262144], g_S[67108864];

// ---- helpers ----
__device__ __forceinline__ void split2(float v, bf16& h, bf16& l) {
    h = __float2bfloat16(v);
    l = __float2bfloat16(v - __bfloat162float(h));
}
__device__ __forceinline__ void ldsm4(uint32_t* r, uint32_t addr) {
    asm volatile("ldmatrix.sync.aligned.m8n8.x4.shared.b16 {%0,%1,%2,%3}, [%4];"
        : "=r"(r[0]), "=r"(r[1]), "=r"(r[2]), "=r"(r[3]) : "r"(addr));
}
__device__ __forceinline__ void mma16816(float* d, const uint32_t* a, const uint32_t* b) {
    asm volatile("mma.sync.aligned.m16n8k16.row.col.f32.bf16.bf16.f32 "
        "{%0,%1,%2,%3}, {%4,%5,%6,%7}, {%8,%9}, {%0,%1,%2,%3};"
        : "+f"(d[0]), "+f"(d[1]), "+f"(d[2]), "+f"(d[3])
        : "r"(a[0]), "r"(a[1]), "r"(a[2]), "r"(a[3]), "r"(b[0]), "r"(b[1]));
}
__device__ __forceinline__ uint32_t swz(uint32_t tile_base, int r, int kb16) {
    uint32_t byte = (uint32_t)(r * 128 + kb16 * 16);
    return tile_base + (byte ^ ((byte >> 3) & 0x70));
}

// ---- HMMA batched GEMM: D = (Ah+Al) @ (Bh+Bl)^T (3-term split) ----
// CTA tile 128x128, warp tile 32x64 (8 warps, 4x2). K-chunks of 64, 3-stage.
// A: MxK (lda), B: NxK (ldb), K-contiguous. Batch z: z0=z/zdiv, z1=z%zdiv.
// mode 0: fp32 C; mode 1: split Chi/Clo. causal 1: skip masked tiles; 2: clip K.
constexpr int BM = 128, BN = 128, BKC = 64;
constexpr int TILE_B = 16384;                 // one 128x64 bf16 tile
constexpr int BUF_B  = 4 * TILE_B;            // Ah, Al, Bh, Bl
constexpr int NSTAGE = 3;
constexpr int SMEM_GEMM = NSTAGE * BUF_B;     // 192 KB

__global__ __launch_bounds__(256, 1)
void gemm3(const bf16* __restrict__ Ah, const bf16* __restrict__ Al,
           long long sA0, long long sA1, int lda,
           const bf16* __restrict__ Bh, const bf16* __restrict__ Bl,
           long long sB0, long long sB1, int ldb,
           float* __restrict__ C, bf16* __restrict__ Chi, bf16* __restrict__ Clo,
           long long sC0, long long sC1, int ldc,
           int M, int N, int K, int zdiv, int mode, int causal)
{
    const int m0 = blockIdx.y * BM, n0 = blockIdx.x * BN;
    if (causal == 1 && n0 >= m0 + BM) return;
    const int z = blockIdx.z, z0 = z / zdiv, z1 = z % zdiv;
    Ah += z0*sA0 + z1*sA1;  Al += z0*sA0 + z1*sA1;
    Bh += z0*sB0 + z1*sB1;  Bl += z0*sB0 + z1*sB1;
    const long long coff = z0*sC0 + z1*sC1;

    extern __shared__ __align__(1024) char smem[];
    const uint32_t sb = (uint32_t)__cvta_generic_to_shared(smem);
    const int tid = threadIdx.x, wid = tid >> 5, lane = tid & 31;
    const int wm = (wid & 3) * 32;      // warp m-offset
    const int wn = (wid >> 2) * 64;     // warp n-offset

    const int Keff = (causal == 2) ? min(K, m0 + BM) : K;
    const int nch = Keff / BKC;

    auto fill = [&](int buf, int k0) {
        const uint32_t bb = sb + buf * BUF_B;
#pragma unroll
        for (int it = 0; it < 16; it++) {
            int idx = tid + it * 256;
            int tile = idx >> 10, r = (idx >> 3) & 127, c16 = idx & 7;
            uint32_t byte = (uint32_t)(r*128 + c16*16);
            uint32_t dst = bb + tile*TILE_B + (byte ^ ((byte >> 3) & 0x70));
            if (tile < 2) {
                const bf16* src = (tile == 0 ? Ah : Al) + (long long)(m0 + r)*lda + k0 + c16*8;
                asm volatile("cp.async.cg.shared.global [%0], [%1], 16;"::"r"(dst),"l"(src):"memory");
            } else if (n0 + r < N) {
                const bf16* src = (tile == 2 ? Bh : Bl) + (long long)(n0 + r)*ldb + k0 + c16*8;
                asm volatile("cp.async.cg.shared.global [%0], [%1], 16;"::"r"(dst),"l"(src):"memory");
            } else {
                asm volatile("st.shared.v4.b32 [%0], {%1,%1,%1,%1};"::"r"(dst),"r"(0u):"memory");
            }
        }
        asm volatile("cp.async.commit_group;" ::: "memory");
    };

    float acc[2][8][4];
#pragma unroll
    for (int i = 0; i < 2; i++)
#pragma unroll
        for (int j = 0; j < 8; j++)
#pragma unroll
            for (int q = 0; q < 4; q++) acc[i][j][q] = 0.f;

    // prefetch 2 stages
    fill(0, 0);
    if (nch > 1) fill(1, BKC);

    for (int ci = 0; ci < nch; ci++) {
        if (ci + 2 < nch) {
            fill((ci + 2) % NSTAGE, (ci + 2) * BKC);
            asm volatile("cp.async.wait_group 2;" ::: "memory");
        } else if (ci + 1 < nch) {
            asm volatile("cp.async.wait_group 1;" ::: "memory");
        } else {
            asm volatile("cp.async.wait_group 0;" ::: "memory");
        }
        __syncthreads();

        const uint32_t bb = sb + (ci % NSTAGE) * BUF_B;
        const uint32_t tAh = bb, tAl = bb + TILE_B, tBh = bb + 2*TILE_B, tBl = bb + 3*TILE_B;
        const int arow = wm + (lane & 15);
        const int brow = wn + (lane & 7) + ((lane >> 4) << 3);

#pragma unroll
        for (int ks = 0; ks < 4; ks++) {
            const int akb = ks*2 + (lane >> 4);
            const int bkb = ks*2 + ((lane >> 3) & 1);
            uint32_t ah[2][4], al[2][4], bh[4][4], bl[4][4];
#pragma unroll
            for (int mi = 0; mi < 2; mi++) {
                ldsm4(ah[mi], swz(tAh, arow + mi*16, akb));
                ldsm4(al[mi], swz(tAl, arow + mi*16, akb));
            }
#pragma unroll
            for (int nj = 0; nj < 4; nj++) {
                ldsm4(bh[nj], swz(tBh, brow + nj*16, bkb));
                ldsm4(bl[nj], swz(tBl, brow + nj*16, bkb));
            }
#pragma unroll
            for (int mi = 0; mi < 2; mi++)
#pragma unroll
                for (int nj = 0; nj < 4; nj++) {
                    mma16816(acc[mi][2*nj],   ah[mi], &bh[nj][0]);
                    mma16816(acc[mi][2*nj+1], ah[mi], &bh[nj][2]);
                    mma16816(acc[mi][2*nj],   ah[mi], &bl[nj][0]);
                    mma16816(acc[mi][2*nj+1], ah[mi], &bl[nj][2]);
                    mma16816(acc[mi][2*nj],   al[mi], &bh[nj][0]);
                    mma16816(acc[mi][2*nj+1], al[mi], &bh[nj][2]);
                }
        }
        __syncthreads();
    }

    // epilogue straight from register fragments
#pragma unroll
    for (int mi = 0; mi < 2; mi++) {
        const int r0 = m0 + wm + mi*16 + (lane >> 2);
#pragma unroll
        for (int nb = 0; nb < 8; nb++) {
            const int c = n0 + wn + nb*8 + (lane & 3)*2;
            if (c < N) {
                const float* a = acc[mi][nb];
                const long long off0 = coff + (long long)r0 * ldc + c;
                const long long off1 = off0 + 8LL * ldc;
                if (mode == 0) {
                    *(float2*)(C + off0) = make_float2(a[0], a[1]);
                    *(float2*)(C + off1) = make_float2(a[2], a[3]);
                } else {
                    bf16 h0,l0,h1,l1;
                    split2(a[0],h0,l0); split2(a[1],h1,l1);
                    *(__nv_bfloat162*)(Chi+off0) = __halves2bfloat162(h0,h1);
                    *(__nv_bfloat162*)(Clo+off0) = __halves2bfloat162(l0,l1);
                    split2(a[2],h0,l0); split2(a[3],h1,l1);
                    *(__nv_bfloat162*)(Chi+off1) = __halves2bfloat162(h0,h1);
                    *(__nv_bfloat162*)(Clo+off1) = __halves2bfloat162(l0,l1);
                }
            }
        }
    }
}

// ---- prep kernels ----
__global__ void split_copy4(const float4* __restrict__ s, __nv_bfloat162* __restrict__ h,
                            __nv_bfloat162* __restrict__ l, long long n4)
{
    long long i = (long long)blockIdx.x*256 + threadIdx.x;
    if (i >= n4) return;
    float4 v = s[i];
    bf16 h0,l0,h1,l1;
    split2(v.x,h0,l0); split2(v.y,h1,l1);
    h[2*i]   = __halves2bfloat162(h0,h1);
    l[2*i]   = __halves2bfloat162(l0,l1);
    split2(v.z,h0,l0); split2(v.w,h1,l1);
    h[2*i+1] = __halves2bfloat162(h0,h1);
    l[2*i+1] = __halves2bfloat162(l0,l1);
}

// fp32 src [b][R][C] -> split bf16 dst [b][C][R]
__global__ void split_transpose(const float* __restrict__ src, bf16* __restrict__ hi,
                                bf16* __restrict__ lo, int R, int C,
                                long long sIn, long long sOut)
{
    __shared__ float t[32][33];
    int b = blockIdx.z, c0 = blockIdx.x*32, r0 = blockIdx.y*32;
    int tx = threadIdx.x, ty = threadIdx.y;
    const float* s = src + (long long)b*sIn;
#pragma unroll
    for (int j = 0; j < 4; j++)
        t[ty + j*8][tx] = s[(long long)(r0 + ty + j*8)*C + c0 + tx];
    __syncthreads();
#pragma unroll
    for (int j = 0; j < 4; j++) {
        long long o = (long long)b*sOut + (long long)(c0 + ty + j*8)*R + r0 + tx;
        bf16 h, l; split2(t[tx][ty + j*8], h, l);
        hi[o] = h; lo[o] = l;
    }
}

__global__ void rope_q_kernel(const float* __restrict__ cqr, const float* __restrict__ fc,
                              const float* __restrict__ fs, bf16* __restrict__ QCh,
                              bf16* __restrict__ QCl)
{
    int idx = blockIdx.x*256 + threadIdx.x;
    if (idx >= BATCH*SEQ*NHEAD*32) return;
    int j = idx & 31, h = (idx >> 5) & 15, bt = idx >> 9;
    int t = bt & (SEQ-1), b = bt >> 10;
    long long src = (long long)bt*(NHEAD*DHR) + h*DHR + 2*j;
    float re = cqr[src], im = cqr[src+1];
    float c = fc[t*32 + j], s = fs[t*32 + j];
    long long row = ((long long)(b*NHEAD + h)*SEQ + t)*QKDIM + NLKV + 2*j;
    bf16 h0,l0,h1,l1;
    split2(re*c - im*s, h0, l0); split2(re*s + im*c, h1, l1);
    QCh[row] = h0; QCl[row] = l0; QCh[row+1] = h1; QCl[row+1] = l1;
}

__global__ void rope_k_kernel(const float* __restrict__ ckr, const float* __restrict__ fc,
                              const float* __restrict__ fs, bf16* __restrict__ KCh,
                              bf16* __restrict__ KCl)
{
    int idx = blockIdx.x*256 + threadIdx.x;
    if (idx >= BATCH*SEQ*32) return;
    int j = idx & 31, bt = idx >> 5, t = bt & (SEQ-1);
    long long src = (long long)bt*DHR + 2*j;
    float re = ckr[src], im = ckr[src+1];
    float c = fc[t*32 + j], s = fs[t*32 + j];
    long long row = (long long)bt*QKDIM + NLKV + 2*j;
    bf16 h0,l0,h1,l1;
    split2(re*c - im*s, h0, l0); split2(re*s + im*c, h1, l1);
    KCh[row] = h0; KCl[row] = l0; KCh[row+1] = h1; KCl[row+1] = l1;
}

__global__ __launch_bounds__(256)
void softmax_split(const float* __restrict__ S, bf16* __restrict__ Phi, bf16* __restrict__ Plo)
{
    const float scale = 0.07216878364870322f;  // 1/sqrt(192)
    long long r = blockIdx.x;
    int t = (int)(r & (SEQ-1));
    const float* row = S + r*SEQ;
    bf16* ph = Phi + r*SEQ; bf16* pl = Plo + r*SEQ;
    int tid = threadIdx.x;
    __shared__ float red[256];
    float v[4], m = -1e30f;
#pragma unroll
    for (int j = 0; j < 4; j++) {
        int i = tid + j*256;
        v[j] = (i <= t) ? row[i] : -1e30f;
        m = fmaxf(m, v[j]);
    }
    red[tid] = m; __syncthreads();
    for (int s = 128; s > 0; s >>= 1) { if (tid < s) red[tid] = fmaxf(red[tid], red[tid+s]); __syncthreads(); }
    m = red[0]*scale; __syncthreads();
    float sum = 0.f;
#pragma unroll
    for (int j = 0; j < 4; j++) {
        int i = tid + j*256;
        float e = (i <= t) ? __expf(v[j]*scale - m) : 0.f;
        v[j] = e; sum += e;
    }
    red[tid] = sum; __syncthreads();
    for (int s = 128; s > 0; s >>= 1) { if (tid < s) red[tid] += red[tid+s]; __syncthreads(); }
    float inv = 1.0f / red[0]; __syncthreads();
#pragma unroll
    for (int j = 0; j < 4; j++) {
        int i = tid + j*256;
        bf16 h, l; split2(v[j]*inv, h, l);
        ph[i] = h; pl[i] = l;
    }
}

// ---- launch ----
extern "C" void kernel_launch(void* const* d_in, const int* in_sizes, int n_in,
                              void* d_out, int out_size)
{
    const float* x     = (const float*)d_in[0];
    const float* W_dq  = (const float*)d_in[1];
    const float* W_uq  = (const float*)d_in[2];
    const float* W_dkv = (const float*)d_in[3];
    const float* W_uk  = (const float*)d_in[4];
    const float* W_uv  = (const float*)d_in[5];
    const float* W_o   = (const float*)d_in[6];
    const float* W_qr  = (const float*)d_in[7];
    const float* W_kr  = (const float*)d_in[8];
    const float* fc    = (const float*)d_in[9];
    const float* fs    = (const float*)d_in[10];
    float* out = (float*)d_out;

    cudaFuncSetAttribute(gemm3, cudaFuncAttributeMaxDynamicSharedMemorySize, SMEM_GEMM);

#define SYM(v, s) cudaGetSymbolAddress((void**)&v, s)
    bf16 *xh,*xl,*dqh,*dql,*dkvh,*dkvl,*krh,*krl,*qrh,*qrl,*uqh,*uql,*woh,*wol;
    bf16 *uvTh,*uvTl,*ukTh,*ukTl,*Zh,*Zl,*keh,*kel,*cqh,*cql,*KCh,*KCl,*QCh,*QCl;
    bf16 *Ph,*Pl,*vTh,*vTl;
    float *cqr,*ckr,*S;
    SYM(xh,g_x_h); SYM(xl,g_x_l); SYM(dqh,g_Wdq_h); SYM(dql,g_Wdq_l);
    SYM(dkvh,g_Wdkv_h); SYM(dkvl,g_Wdkv_l); SYM(krh,g_Wkr_h); SYM(krl,g_Wkr_l);
    SYM(qrh,g_Wqr_h); SYM(qrl,g_Wqr_l); SYM(uqh,g_Wuq_h); SYM(uql,g_Wuq_l);
    SYM(woh,g_Wo_h); SYM(wol,g_Wo_l); SYM(uvTh,g_WuvT_h); SYM(uvTl,g_WuvT_l);
    SYM(ukTh,g_WukT_h); SYM(ukTl,g_WukT_l); SYM(Zh,g_Z_h); SYM(Zl,g_Z_l);
    SYM(keh,g_keffT_h); SYM(kel,g_keffT_l); SYM(cqh,g_cq_h); SYM(cql,g_cq_l);
    SYM(KCh,g_KC_h); SYM(KCl,g_KC_l); SYM(QCh,g_QC_h); SYM(QCl,g_QC_l);
    SYM(Ph,g_P_h); SYM(Pl,g_P_l); SYM(vTh,g_vT_h); SYM(vTl,g_vT_l);
    SYM(cqr,g_cqr); SYM(ckr,g_ckr); SYM(S,g_S);
#undef SYM

    auto SC = [](const float* s, bf16* h, bf16* l, long long n) {
        split_copy4<<<(unsigned)((n/4 + 255)/256), 256>>>(
            (const float4*)s, (__nv_bfloat162*)h, (__nv_bfloat162*)l, n/4);
    };
    dim3 blk(256);

    // Launch order arranged so launch #6 (ncu -s 5 -c 1) is gemm3(c_q).
    SC(x, xh, xl, 8388608);            // 1
    SC(W_dq, dqh, dql, 1048576);       // 2
    SC(W_dkv, dkvh, dkvl, 1048576);    // 3
    SC(W_kr, krh, krl, 131072);        // 4
    SC(W_qr, qrh, qrl, 524288);        // 5
    // 6 (PROFILED). c_q = x @ W_dq^T (4096x512, K=2048) -> split
    gemm3<<<dim3(4, 32, 1), blk, SMEM_GEMM>>>(xh, xl, 0, 0, 2048, dqh, dql, 0, 0, 2048,
        nullptr, cqh, cql, 0, 0, 512, 4096, 512, 2048, 1, 1, 0);

    SC(W_uq, uqh, uql, 1048576);
    SC(W_o, woh, wol, 4194304);
    // W_uv (2048x512) -> WuvT (512x2048); W_uk per head (128x512) -> WukT (512x128)
    split_transpose<<<dim3(16, 64, 1), dim3(32, 8)>>>(W_uv, uvTh, uvTl, 2048, 512, 0, 0);
    split_transpose<<<dim3(16, 4, 16), dim3(32, 8)>>>(W_uk, ukTh, ukTl, 128, 512, 65536, 65536);

    // Z = W_o @ W_uv  (2048x512, K=2048) -> split
    gemm3<<<dim3(4, 16, 1), blk, SMEM_GEMM>>>(woh, wol, 0, 0, 2048, uvTh, uvTl, 0, 0, 2048,
        nullptr, Zh, Zl, 0, 0, 512, 2048, 512, 2048, 1, 1, 0);
    // keffT[h] = WukT_h @ Wuq_h^T  (512x512, K=128) -> split
    gemm3<<<dim3(4, 4, 16), blk, SMEM_GEMM>>>(ukTh, ukTl, 0, 65536, 128, uqh, uql, 0, 128, 2048,
        nullptr, keh, kel, 0, 262144, 512, 512, 512, 128, 16, 1, 0);
    // c_kv -> KC[:, 0:512] split (ldc=576)
    gemm3<<<dim3(4, 32, 1), blk, SMEM_GEMM>>>(xh, xl, 0, 0, 2048, dkvh, dkvl, 0, 0, 2048,
        nullptr, KCh, KCl, 0, 0, QKDIM, 4096, 512, 2048, 1, 1, 0);
    // vT[b,h] = Z_h (128x512) @ c_kv[b]^T (1024x512) -> split (128x1024)
    gemm3<<<dim3(8, 1, 64), blk, SMEM_GEMM>>>(Zh, Zl, 0, 65536, 512,
        KCh, KCl, 589824, 0, QKDIM,
        nullptr, vTh, vTl, 2097152, 131072, 1024, 128, 1024, 512, 16, 1, 0);
    // c_kr = x @ W_kr^T (4096x64) -> fp32
    gemm3<<<dim3(1, 32, 1), blk, SMEM_GEMM>>>(xh, xl, 0, 0, 2048, krh, krl, 0, 0, 2048,
        ckr, nullptr, nullptr, 0, 0, 64, 4096, 64, 2048, 1, 0, 0);
    // c_qr = c_q @ W_qr^T (4096x1024, K=512) -> fp32
    gemm3<<<dim3(8, 32, 1), blk, SMEM_GEMM>>>(cqh, cql, 0, 0, 512, qrh, qrl, 0, 0, 512,
        cqr, nullptr, nullptr, 0, 0, 1024, 4096, 1024, 512, 1, 0, 0);
    // RoPE tails
    rope_q_kernel<<<(BATCH*SEQ*NHEAD*32 + 255)/256, 256>>>(cqr, fc, fs, QCh, QCl);
    rope_k_kernel<<<(BATCH*SEQ*32 + 255)/256, 256>>>(ckr, fc, fs, KCh, KCl);
    // q_abs[b,h] = c_q[b] @ keffT[h]^T -> QC[:, 0:512] split (ldc=576)
    gemm3<<<dim3(4, 8, 64), blk, SMEM_GEMM>>>(cqh, cql, 524288, 0, 512, keh, kel, 0, 262144, 512,
        nullptr, QCh, QCl, 9437184, 589824, QKDIM, 1024, 512, 512, 16, 1, 0);
    // S[b,h] = QC[b,h] @ KC[b]^T (1024x1024, K=576), causal skip -> fp32
    gemm3<<<dim3(8, 8, 64), blk, SMEM_GEMM>>>(QCh, QCl, 9437184, 589824, QKDIM,
        KCh, KCl, 589824, 0, QKDIM,
        S, nullptr, nullptr, 16777216, 1048576, 1024, 1024, 1024, 576, 16, 0, 1);
    // softmax -> split P
    softmax_split<<<BATCH*NHEAD*SEQ, 256>>>(S, Ph, Pl);
    // out[b][:, h*128:+128] = P[b,h] @ vT[b,h]^T (1024x128, K clipped) -> fp32
    gemm3<<<dim3(1, 8, 64), blk, SMEM_GEMM>>>(Ph, Pl, 16777216, 1048576, 1024,
        vTh, vTl, 2097152, 131072, 1024,
        out, nullptr, nullptr, 2097152, 128, 2048, 1024, 128, 1024, 16, 0, 2);
}

// round 10
// speedup vs baseline: 2.5852x; 1.3065x over previous
#include <cuda_runtime.h>
#include <cuda_bf16.h>
#include <stdint.h>
#include <math.h>

using bf16 = __nv_bfloat16;

constexpr int BATCH = 4, SEQ = 1024, CDIM = 2048, NHEAD = 16, HS = 128;
constexpr int NLQ = 512, NLKV = 512, DHR = 64, QKD = 192;   // per-head [k_h | rope]

// ---- scratch (hi/lo bf16 split pairs) ----
__device__ __align__(128) bf16 g_x_h[8388608],   g_x_l[8388608];
__device__ __align__(128) bf16 g_Wdq_h[1048576], g_Wdq_l[1048576];
__device__ __align__(128) bf16 g_Wdkv_h[1048576],g_Wdkv_l[1048576];
__device__ __align__(128) bf16 g_Wkr_h[131072],  g_Wkr_l[131072];
__device__ __align__(128) bf16 g_Wqr_h[524288],  g_Wqr_l[524288];
__device__ __align__(128) bf16 g_WuqT_h[1048576],g_WuqT_l[1048576];  // (2048x512)
__device__ __align__(128) bf16 g_Wuk_h[1048576], g_Wuk_l[1048576];   // raw [h][128][512]
__device__ __align__(128) bf16 g_Wo_h[4194304],  g_Wo_l[4194304];
__device__ __align__(128) bf16 g_WuvT_h[1048576],g_WuvT_l[1048576];
__device__ __align__(128) bf16 g_Z_h[1048576],   g_Z_l[1048576];
__device__ __align__(128) bf16 g_cq_h[2097152],  g_cq_l[2097152];
__device__ __align__(128) bf16 g_KC_h[2359296],  g_KC_l[2359296];    // [b][s][576] c_kv
__device__ __align__(128) bf16 g_QH_h[12582912], g_QH_l[12582912];   // [b][t][h][192]
__device__ __align__(128) bf16 g_KH_h[12582912], g_KH_l[12582912];   // [b][s][h][192]
__device__ __align__(128) bf16 g_P_h[67108864],  g_P_l[67108864];
__device__ __align__(128) bf16 g_vT_h[8388608],  g_vT_l[8388608];    // [b,h] 128x1024
__device__ __align__(128) float g_cqr[4194304], g_ckr[262144], g_S[67108864];

// ---- helpers ----
__device__ __forceinline__ void split2(float v, bf16& h, bf16& l) {
    h = __float2bfloat16(v);
    l = __float2bfloat16(v - __bfloat162float(h));
}
__device__ __forceinline__ void ldsm4(uint32_t* r, uint32_t addr) {
    asm volatile("ldmatrix.sync.aligned.m8n8.x4.shared.b16 {%0,%1,%2,%3}, [%4];"
        : "=r"(r[0]), "=r"(r[1]), "=r"(r[2]), "=r"(r[3]) : "r"(addr));
}
__device__ __forceinline__ void mma16816(float* d, const uint32_t* a, const uint32_t* b) {
    asm volatile("mma.sync.aligned.m16n8k16.row.col.f32.bf16.bf16.f32 "
        "{%0,%1,%2,%3}, {%4,%5,%6,%7}, {%8,%9}, {%0,%1,%2,%3};"
        : "+f"(d[0]), "+f"(d[1]), "+f"(d[2]), "+f"(d[3])
        : "r"(a[0]), "r"(a[1]), "r"(a[2]), "r"(a[3]), "r"(b[0]), "r"(b[1]));
}
__device__ __forceinline__ uint32_t swz(uint32_t tile_base, int r, int kb16) {
    uint32_t byte = (uint32_t)(r * 128 + kb16 * 16);
    return tile_base + (byte ^ ((byte >> 3) & 0x70));
}

// ---- HMMA batched GEMM: D = (Ah+Al) @ (Bh+Bl)^T (3-term split) ----
// CTA 128x128, warp 32x64 (8 warps). K-chunks 64, 3-stage, ONE sync/chunk.
// mode 0: fp32 C; 1: split Chi/Clo; 2: split + column remap c->(c>>7)*192+(c&127).
// causal 1: skip masked tiles; 2: clip K to m0+BM.
constexpr int BM = 128, BN = 128, BKC = 64;
constexpr int TILE_B = 16384;
constexpr int BUF_B  = 4 * TILE_B;
constexpr int NSTAGE = 3;
constexpr int SMEM_GEMM = NSTAGE * BUF_B;     // 192 KB

__global__ __launch_bounds__(256, 1)
void gemm3(const bf16* __restrict__ Ah, const bf16* __restrict__ Al,
           long long sA0, long long sA1, int lda,
           const bf16* __restrict__ Bh, const bf16* __restrict__ Bl,
           long long sB0, long long sB1, int ldb,
           float* __restrict__ C, bf16* __restrict__ Chi, bf16* __restrict__ Clo,
           long long sC0, long long sC1, int ldc,
           int M, int N, int K, int zdiv, int mode, int causal)
{
    const int m0 = blockIdx.y * BM, n0 = blockIdx.x * BN;
    if (causal == 1 && n0 >= m0 + BM) return;
    const int z = blockIdx.z, z0 = z / zdiv, z1 = z % zdiv;
    Ah += z0*sA0 + z1*sA1;  Al += z0*sA0 + z1*sA1;
    Bh += z0*sB0 + z1*sB1;  Bl += z0*sB0 + z1*sB1;
    const long long coff = z0*sC0 + z1*sC1;

    extern __shared__ __align__(1024) char smem[];
    const uint32_t sb = (uint32_t)__cvta_generic_to_shared(smem);
    const int tid = threadIdx.x, wid = tid >> 5, lane = tid & 31;
    const int wm = (wid & 3) * 32;
    const int wn = (wid >> 2) * 64;

    const int Keff = (causal == 2) ? min(K, m0 + BM) : K;
    const int nch = Keff / BKC;

    auto fill = [&](int buf, int k0) {
        const uint32_t bb = sb + buf * BUF_B;
#pragma unroll
        for (int it = 0; it < 16; it++) {
            int idx = tid + it * 256;
            int tile = idx >> 10, r = (idx >> 3) & 127, c16 = idx & 7;
            uint32_t byte = (uint32_t)(r*128 + c16*16);
            uint32_t dst = bb + tile*TILE_B + (byte ^ ((byte >> 3) & 0x70));
            if (tile < 2) {
                const bf16* src = (tile == 0 ? Ah : Al) + (long long)(m0 + r)*lda + k0 + c16*8;
                asm volatile("cp.async.cg.shared.global [%0], [%1], 16;"::"r"(dst),"l"(src):"memory");
            } else if (n0 + r < N) {
                const bf16* src = (tile == 2 ? Bh : Bl) + (long long)(n0 + r)*ldb + k0 + c16*8;
                asm volatile("cp.async.cg.shared.global [%0], [%1], 16;"::"r"(dst),"l"(src):"memory");
            } else {
                asm volatile("st.shared.v4.b32 [%0], {%1,%1,%1,%1};"::"r"(dst),"r"(0u):"memory");
            }
        }
        asm volatile("cp.async.commit_group;" ::: "memory");
    };

    float acc[2][8][4];
#pragma unroll
    for (int i = 0; i < 2; i++)
#pragma unroll
        for (int j = 0; j < 8; j++)
#pragma unroll
            for (int q = 0; q < 4; q++) acc[i][j][q] = 0.f;

    fill(0, 0);
    if (nch > 1) fill(1, BKC);

    for (int ci = 0; ci < nch; ci++) {
        if (ci + 1 < nch) {
            asm volatile("cp.async.wait_group 1;" ::: "memory");
        } else {
            asm volatile("cp.async.wait_group 0;" ::: "memory");
        }
        __syncthreads();
        if (ci + 2 < nch) fill((ci + 2) % NSTAGE, (ci + 2) * BKC);

        const uint32_t bb = sb + (ci % NSTAGE) * BUF_B;
        const uint32_t tAh = bb, tAl = bb + TILE_B, tBh = bb + 2*TILE_B, tBl = bb + 3*TILE_B;
        const int arow = wm + (lane & 15);
        const int brow = wn + (lane & 7) + ((lane >> 4) << 3);

#pragma unroll
        for (int ks = 0; ks < 4; ks++) {
            const int akb = ks*2 + (lane >> 4);
            const int bkb = ks*2 + ((lane >> 3) & 1);
            uint32_t ah[2][4], al[2][4], bh[4][4], bl[4][4];
#pragma unroll
            for (int mi = 0; mi < 2; mi++) {
                ldsm4(ah[mi], swz(tAh, arow + mi*16, akb));
                ldsm4(al[mi], swz(tAl, arow + mi*16, akb));
            }
#pragma unroll
            for (int nj = 0; nj < 4; nj++) {
                ldsm4(bh[nj], swz(tBh, brow + nj*16, bkb));
                ldsm4(bl[nj], swz(tBl, brow + nj*16, bkb));
            }
#pragma unroll
            for (int mi = 0; mi < 2; mi++)
#pragma unroll
                for (int nj = 0; nj < 4; nj++) {
                    mma16816(acc[mi][2*nj],   ah[mi], &bh[nj][0]);
                    mma16816(acc[mi][2*nj+1], ah[mi], &bh[nj][2]);
                    mma16816(acc[mi][2*nj],   ah[mi], &bl[nj][0]);
                    mma16816(acc[mi][2*nj+1], ah[mi], &bl[nj][2]);
                    mma16816(acc[mi][2*nj],   al[mi], &bh[nj][0]);
                    mma16816(acc[mi][2*nj+1], al[mi], &bh[nj][2]);
                }
        }
        __syncthreads();   // protects buffer reuse for the NEXT fill round
    }

    // epilogue from register fragments
#pragma unroll
    for (int mi = 0; mi < 2; mi++) {
        const int r0 = m0 + wm + mi*16 + (lane >> 2);
#pragma unroll
        for (int nb = 0; nb < 8; nb++) {
            const int c = n0 + wn + nb*8 + (lane & 3)*2;
            if (c < N) {
                const float* a = acc[mi][nb];
                const int cc = (mode == 2) ? ((c >> 7) * QKD + (c & 127)) : c;
                const long long off0 = coff + (long long)r0 * ldc + cc;
                const long long off1 = off0 + 8LL * ldc;
                if (mode == 0) {
                    *(float2*)(C + off0) = make_float2(a[0], a[1]);
                    *(float2*)(C + off1) = make_float2(a[2], a[3]);
                } else {
                    bf16 h0,l0,h1,l1;
                    split2(a[0],h0,l0); split2(a[1],h1,l1);
                    *(__nv_bfloat162*)(Chi+off0) = __halves2bfloat162(h0,h1);
                    *(__nv_bfloat162*)(Clo+off0) = __halves2bfloat162(l0,l1);
                    split2(a[2],h0,l0); split2(a[3],h1,l1);
                    *(__nv_bfloat162*)(Chi+off1) = __halves2bfloat162(h0,h1);
                    *(__nv_bfloat162*)(Clo+off1) = __halves2bfloat162(l0,l1);
                }
            }
        }
    }
}

// ---- prep kernels ----
__global__ void split_copy4(const float4* __restrict__ s, __nv_bfloat162* __restrict__ h,
                            __nv_bfloat162* __restrict__ l, long long n4)
{
    long long i = (long long)blockIdx.x*256 + threadIdx.x;
    if (i >= n4) return;
    float4 v = s[i];
    bf16 h0,l0,h1,l1;
    split2(v.x,h0,l0); split2(v.y,h1,l1);
    h[2*i]   = __halves2bfloat162(h0,h1);
    l[2*i]   = __halves2bfloat162(l0,l1);
    split2(v.z,h0,l0); split2(v.w,h1,l1);
    h[2*i+1] = __halves2bfloat162(h0,h1);
    l[2*i+1] = __halves2bfloat162(l0,l1);
}

// fp32 src [R][C] -> split bf16 dst [C][R]
__global__ void split_transpose(const float* __restrict__ src, bf16* __restrict__ hi,
                                bf16* __restrict__ lo, int R, int C,
                                long long sIn, long long sOut)
{
    __shared__ float t[32][33];
    int b = blockIdx.z, c0 = blockIdx.x*32, r0 = blockIdx.y*32;
    int tx = threadIdx.x, ty = threadIdx.y;
    const float* s = src + (long long)b*sIn;
#pragma unroll
    for (int j = 0; j < 4; j++)
        t[ty + j*8][tx] = s[(long long)(r0 + ty + j*8)*C + c0 + tx];
    __syncthreads();
#pragma unroll
    for (int j = 0; j < 4; j++) {
        long long o = (long long)b*sOut + (long long)(c0 + ty + j*8)*R + r0 + tx;
        bf16 h, l; split2(t[tx][ty + j*8], h, l);
        hi[o] = h; lo[o] = l;
    }
}

// rope q: cqr [bt][h*64+2j] -> QH[b][t][h][128+2j]
__global__ void rope_q_kernel(const float* __restrict__ cqr, const float* __restrict__ fc,
                              const float* __restrict__ fs, bf16* __restrict__ QHh,
                              bf16* __restrict__ QHl)
{
    int idx = blockIdx.x*256 + threadIdx.x;
    if (idx >= BATCH*SEQ*NHEAD*32) return;
    int j = idx & 31, h = (idx >> 5) & 15, bt = idx >> 9;
    int t = bt & (SEQ-1);
    long long src = (long long)bt*(NHEAD*DHR) + h*DHR + 2*j;
    float re = cqr[src], im = cqr[src+1];
    float c = fc[t*32 + j], s = fs[t*32 + j];
    long long row = (long long)bt*(NHEAD*QKD) + h*QKD + 128 + 2*j;
    bf16 h0,l0,h1,l1;
    split2(re*c - im*s, h0, l0); split2(re*s + im*c, h1, l1);
    QHh[row] = h0; QHl[row] = l0; QHh[row+1] = h1; QHl[row+1] = l1;
}

// rope k: ckr [bt][2j] -> KH[b][s][h][128+2j] for all 16 h
__global__ void rope_k_kernel(const float* __restrict__ ckr, const float* __restrict__ fc,
                              const float* __restrict__ fs, bf16* __restrict__ KHh,
                              bf16* __restrict__ KHl)
{
    int idx = blockIdx.x*256 + threadIdx.x;
    if (idx >= BATCH*SEQ*32) return;
    int j = idx & 31, bt = idx >> 5, t = bt & (SEQ-1);
    long long src = (long long)bt*DHR + 2*j;
    float re = ckr[src], im = ckr[src+1];
    float c = fc[t*32 + j], s = fs[t*32 + j];
    bf16 h0,l0,h1,l1;
    split2(re*c - im*s, h0, l0); split2(re*s + im*c, h1, l1);
    long long base = (long long)bt*(NHEAD*QKD) + 128 + 2*j;
#pragma unroll
    for (int h = 0; h < NHEAD; h++) {
        long long row = base + h*QKD;
        KHh[row] = h0; KHl[row] = l0; KHh[row+1] = h1; KHl[row+1] = l1;
    }
}

__global__ __launch_bounds__(256)
void softmax_split(const float* __restrict__ S, bf16* __restrict__ Phi, bf16* __restrict__ Plo)
{
    const float scale = 0.07216878364870322f;  // 1/sqrt(192)
    long long r = blockIdx.x;
    int t = (int)(r & (SEQ-1));
    const float* row = S + r*SEQ;
    bf16* ph = Phi + r*SEQ; bf16* pl = Plo + r*SEQ;
    int tid = threadIdx.x;
    __shared__ float red[256];
    float v[4], m = -1e30f;
#pragma unroll
    for (int j = 0; j < 4; j++) {
        int i = tid + j*256;
        v[j] = (i <= t) ? row[i] : -1e30f;
        m = fmaxf(m, v[j]);
    }
    red[tid] = m; __syncthreads();
    for (int s = 128; s > 0; s >>= 1) { if (tid < s) red[tid] = fmaxf(red[tid], red[tid+s]); __syncthreads(); }
    m = red[0]*scale; __syncthreads();
    float sum = 0.f;
#pragma unroll
    for (int j = 0; j < 4; j++) {
        int i = tid + j*256;
        float e = (i <= t) ? __expf(v[j]*scale - m) : 0.f;
        v[j] = e; sum += e;
    }
    red[tid] = sum; __syncthreads();
    for (int s = 128; s > 0; s >>= 1) { if (tid < s) red[tid] += red[tid+s]; __syncthreads(); }
    float inv = 1.0f / red[0]; __syncthreads();
#pragma unroll
    for (int j = 0; j < 4; j++) {
        int i = tid + j*256;
        bf16 h, l; split2(v[j]*inv, h, l);
        ph[i] = h; pl[i] = l;
    }
}

// ---- launch ----
extern "C" void kernel_launch(void* const* d_in, const int* in_sizes, int n_in,
                              void* d_out, int out_size)
{
    const float* x     = (const float*)d_in[0];
    const float* W_dq  = (const float*)d_in[1];
    const float* W_uq  = (const float*)d_in[2];
    const float* W_dkv = (const float*)d_in[3];
    const float* W_uk  = (const float*)d_in[4];
    const float* W_uv  = (const float*)d_in[5];
    const float* W_o   = (const float*)d_in[6];
    const float* W_qr  = (const float*)d_in[7];
    const float* W_kr  = (const float*)d_in[8];
    const float* fc    = (const float*)d_in[9];
    const float* fs    = (const float*)d_in[10];
    float* out = (float*)d_out;

    cudaFuncSetAttribute(gemm3, cudaFuncAttributeMaxDynamicSharedMemorySize, SMEM_GEMM);

#define SYM(v, s) cudaGetSymbolAddress((void**)&v, s)
    bf16 *xh,*xl,*dqh,*dql,*dkvh,*dkvl,*krh,*krl,*qrh,*qrl,*uqTh,*uqTl,*ukh,*ukl;
    bf16 *woh,*wol,*uvTh,*uvTl,*Zh,*Zl,*cqh,*cql,*KCh,*KCl,*QHh,*QHl,*KHh,*KHl;
    bf16 *Ph,*Pl,*vTh,*vTl;
    float *cqr,*ckr,*S;
    SYM(xh,g_x_h); SYM(xl,g_x_l); SYM(dqh,g_Wdq_h); SYM(dql,g_Wdq_l);
    SYM(dkvh,g_Wdkv_h); SYM(dkvl,g_Wdkv_l); SYM(krh,g_Wkr_h); SYM(krl,g_Wkr_l);
    SYM(qrh,g_Wqr_h); SYM(qrl,g_Wqr_l); SYM(uqTh,g_WuqT_h); SYM(uqTl,g_WuqT_l);
    SYM(ukh,g_Wuk_h); SYM(ukl,g_Wuk_l);
    SYM(woh,g_Wo_h); SYM(wol,g_Wo_l); SYM(uvTh,g_WuvT_h); SYM(uvTl,g_WuvT_l);
    SYM(Zh,g_Z_h); SYM(Zl,g_Z_l); SYM(cqh,g_cq_h); SYM(cql,g_cq_l);
    SYM(KCh,g_KC_h); SYM(KCl,g_KC_l); SYM(QHh,g_QH_h); SYM(QHl,g_QH_l);
    SYM(KHh,g_KH_h); SYM(KHl,g_KH_l);
    SYM(Ph,g_P_h); SYM(Pl,g_P_l); SYM(vTh,g_vT_h); SYM(vTl,g_vT_l);
    SYM(cqr,g_cqr); SYM(ckr,g_ckr); SYM(S,g_S);
#undef SYM

    auto SC = [](const float* s, bf16* h, bf16* l, long long n) {
        split_copy4<<<(unsigned)((n/4 + 255)/256), 256>>>(
            (const float4*)s, (__nv_bfloat162*)h, (__nv_bfloat162*)l, n/4);
    };
    dim3 blk(256);
    const int LDH = NHEAD * QKD;                   // 3072
    const long long SB = (long long)SEQ * LDH;     // 3145728 per-batch stride

    // ---- splits / transposes ----
    SC(x, xh, xl, 8388608);
    SC(W_dq, dqh, dql, 1048576);
    SC(W_dkv, dkvh, dkvl, 1048576);
    SC(W_kr, krh, krl, 131072);
    SC(W_qr, qrh, qrl, 524288);
    SC(W_uk, ukh, ukl, 1048576);                   // raw [h][128][512], K-contig
    SC(W_o, woh, wol, 4194304);
    // W_uq viewed (512,2048) -> WuqT (2048x512)
    split_transpose<<<dim3(64, 16, 1), dim3(32, 8)>>>(W_uq, uqTh, uqTl, 512, 2048, 0, 0);
    // W_uv (2048x512) -> WuvT (512x2048)
    split_transpose<<<dim3(16, 64, 1), dim3(32, 8)>>>(W_uv, uvTh, uvTl, 2048, 512, 0, 0);

    // ---- GEMMs ----
    // c_q = x @ W_dq^T (4096x512, K=2048) -> split
    gemm3<<<dim3(4, 32, 1), blk, SMEM_GEMM>>>(xh, xl, 0, 0, 2048, dqh, dql, 0, 0, 2048,
        nullptr, cqh, cql, 0, 0, 512, 4096, 512, 2048, 1, 1, 0);
    // c_kv -> KC[:, 0:512] split (ldc=576)
    gemm3<<<dim3(4, 32, 1), blk, SMEM_GEMM>>>(xh, xl, 0, 0, 2048, dkvh, dkvl, 0, 0, 2048,
        nullptr, KCh, KCl, 0, 0, 576, 4096, 512, 2048, 1, 1, 0);
    // Z = W_o @ W_uv (2048x512, K=2048) -> split
    gemm3<<<dim3(4, 16, 1), blk, SMEM_GEMM>>>(woh, wol, 0, 0, 2048, uvTh, uvTl, 0, 0, 2048,
        nullptr, Zh, Zl, 0, 0, 512, 2048, 512, 2048, 1, 1, 0);
    // vT[b,h] = Z_h (128x512) @ c_kv[b]^T -> split (128x1024)
    gemm3<<<dim3(8, 1, 64), blk, SMEM_GEMM>>>(Zh, Zl, 0, 65536, 512,
        KCh, KCl, 589824, 0, 576,
        nullptr, vTh, vTl, 2097152, 131072, 1024, 128, 1024, 512, 16, 1, 0);
    // c_kr = x @ W_kr^T (4096x64) -> fp32
    gemm3<<<dim3(1, 32, 1), blk, SMEM_GEMM>>>(xh, xl, 0, 0, 2048, krh, krl, 0, 0, 2048,
        ckr, nullptr, nullptr, 0, 0, 64, 4096, 64, 2048, 1, 0, 0);
    // c_qr = c_q @ W_qr^T (4096x1024, K=512) -> fp32
    gemm3<<<dim3(8, 32, 1), blk, SMEM_GEMM>>>(cqh, cql, 0, 0, 512, qrh, qrl, 0, 0, 512,
        cqr, nullptr, nullptr, 0, 0, 1024, 4096, 1024, 512, 1, 0, 0);
    // Q = c_q @ WuqT^T (4096x2048, K=512) -> QH split with col remap, ldc=3072
    gemm3<<<dim3(16, 32, 1), blk, SMEM_GEMM>>>(cqh, cql, 0, 0, 512, uqTh, uqTl, 0, 0, 512,
        nullptr, QHh, QHl, 0, 0, LDH, 4096, 2048, 512, 1, 2, 0);
    // KH[b,h] = c_kv[b] @ W_uk_h^T (1024x128, K=512) -> split, ldc=3072
    gemm3<<<dim3(1, 8, 64), blk, SMEM_GEMM>>>(KCh, KCl, 589824, 0, 576,
        ukh, ukl, 0, 65536, 512,
        nullptr, KHh, KHl, SB, QKD, LDH, 1024, 128, 512, 16, 1, 0);
    // RoPE tails into QH / KH
    rope_q_kernel<<<(BATCH*SEQ*NHEAD*32 + 255)/256, 256>>>(cqr, fc, fs, QHh, QHl);
    rope_k_kernel<<<(BATCH*SEQ*32 + 255)/256, 256>>>(ckr, fc, fs, KHh, KHl);
    // S[b,h] = QH[b,h] @ KH[b,h]^T (1024x1024, K=192), causal skip -> fp32
    gemm3<<<dim3(8, 8, 64), blk, SMEM_GEMM>>>(QHh, QHl, SB, QKD, LDH,
        KHh, KHl, SB, QKD, LDH,
        S, nullptr, nullptr, 16777216, 1048576, 1024, 1024, 1024, QKD, 16, 0, 1);
    // softmax -> split P
    softmax_split<<<BATCH*NHEAD*SEQ, 256>>>(S, Ph, Pl);
    // out[b][:, h*128:+128] = P[b,h] @ vT[b,h]^T (1024x128, K clipped) -> fp32
    gemm3<<<dim3(1, 8, 64), blk, SMEM_GEMM>>>(Ph, Pl, 16777216, 1048576, 1024,
        vTh, vTl, 2097152, 131072, 1024,
        out, nullptr, nullptr, 2097152, 128, 2048, 1024, 128, 1024, 16, 0, 2);
}

// round 11
// speedup vs baseline: 2.8345x; 1.0965x over previous
#include <cuda_runtime.h>
#include <cuda_bf16.h>
#include <stdint.h>
#include <math.h>

using bf16 = __nv_bfloat16;

constexpr int BATCH = 4, SEQ = 1024, CDIM = 2048, NHEAD = 16, HS = 128;
constexpr int NLQ = 512, NLKV = 512, DHR = 64, QKD = 192;   // per-head [k_h | rope]

// ---- scratch (hi/lo bf16 split pairs) ----
__device__ __align__(128) bf16 g_x_h[8388608],   g_x_l[8388608];
__device__ __align__(128) bf16 g_Wdq_h[1048576], g_Wdq_l[1048576];
__device__ __align__(128) bf16 g_Wdkv_h[1048576],g_Wdkv_l[1048576];
__device__ __align__(128) bf16 g_Wkr_h[131072],  g_Wkr_l[131072];
__device__ __align__(128) bf16 g_Wqr_h[524288],  g_Wqr_l[524288];
__device__ __align__(128) bf16 g_WuqT_h[1048576],g_WuqT_l[1048576];  // (2048x512)
__device__ __align__(128) bf16 g_Wuk_h[1048576], g_Wuk_l[1048576];   // raw [h][128][512]
__device__ __align__(128) bf16 g_Wo_h[4194304],  g_Wo_l[4194304];
__device__ __align__(128) bf16 g_WuvT_h[1048576],g_WuvT_l[1048576];
__device__ __align__(128) bf16 g_Z_h[1048576],   g_Z_l[1048576];
__device__ __align__(128) bf16 g_cq_h[2097152],  g_cq_l[2097152];
__device__ __align__(128) bf16 g_KC_h[2359296],  g_KC_l[2359296];    // [b][s][576] c_kv
__device__ __align__(128) bf16 g_QH_h[12582912], g_QH_l[12582912];   // [b][t][h][192]
__device__ __align__(128) bf16 g_KH_h[12582912], g_KH_l[12582912];   // [b][s][h][192]
__device__ __align__(128) bf16 g_vT_h[8388608],  g_vT_l[8388608];    // [b,h] 128x1024
__device__ __align__(128) float g_cqr[4194304], g_ckr[262144], g_S[67108864];

// ---- helpers ----
__device__ __forceinline__ void split2(float v, bf16& h, bf16& l) {
    h = __float2bfloat16(v);
    l = __float2bfloat16(v - __bfloat162float(h));
}
__device__ __forceinline__ uint32_t packbf2(bf16 a, bf16 b) {
    __nv_bfloat162 p = __halves2bfloat162(a, b);
    return *reinterpret_cast<uint32_t*>(&p);
}
__device__ __forceinline__ void ldsm4(uint32_t* r, uint32_t addr) {
    asm volatile("ldmatrix.sync.aligned.m8n8.x4.shared.b16 {%0,%1,%2,%3}, [%4];"
        : "=r"(r[0]), "=r"(r[1]), "=r"(r[2]), "=r"(r[3]) : "r"(addr));
}
__device__ __forceinline__ void mma16816(float* d, const uint32_t* a, const uint32_t* b) {
    asm volatile("mma.sync.aligned.m16n8k16.row.col.f32.bf16.bf16.f32 "
        "{%0,%1,%2,%3}, {%4,%5,%6,%7}, {%8,%9}, {%0,%1,%2,%3};"
        : "+f"(d[0]), "+f"(d[1]), "+f"(d[2]), "+f"(d[3])
        : "r"(a[0]), "r"(a[1]), "r"(a[2]), "r"(a[3]), "r"(b[0]), "r"(b[1]));
}
__device__ __forceinline__ uint32_t swz(uint32_t tile_base, int r, int kb16) {
    uint32_t byte = (uint32_t)(r * 128 + kb16 * 16);
    return tile_base + (byte ^ ((byte >> 3) & 0x70));
}

// ---- HMMA batched GEMM: D = (Ah+Al) @ (Bh+Bl)^T (3-term split) ----
constexpr int BM = 128, BN = 128, BKC = 64;
constexpr int TILE_B = 16384;
constexpr int BUF_B  = 4 * TILE_B;
constexpr int NSTAGE = 3;
constexpr int SMEM_GEMM = NSTAGE * BUF_B;     // 192 KB

__global__ __launch_bounds__(256, 1)
void gemm3(const bf16* __restrict__ Ah, const bf16* __restrict__ Al,
           long long sA0, long long sA1, int lda,
           const bf16* __restrict__ Bh, const bf16* __restrict__ Bl,
           long long sB0, long long sB1, int ldb,
           float* __restrict__ C, bf16* __restrict__ Chi, bf16* __restrict__ Clo,
           long long sC0, long long sC1, int ldc,
           int M, int N, int K, int zdiv, int mode, int causal)
{
    const int m0 = blockIdx.y * BM, n0 = blockIdx.x * BN;
    if (causal == 1 && n0 >= m0 + BM) return;
    const int z = blockIdx.z, z0 = z / zdiv, z1 = z % zdiv;
    Ah += z0*sA0 + z1*sA1;  Al += z0*sA0 + z1*sA1;
    Bh += z0*sB0 + z1*sB1;  Bl += z0*sB0 + z1*sB1;
    const long long coff = z0*sC0 + z1*sC1;

    extern __shared__ __align__(1024) char smem[];
    const uint32_t sb = (uint32_t)__cvta_generic_to_shared(smem);
    const int tid = threadIdx.x, wid = tid >> 5, lane = tid & 31;
    const int wm = (wid & 3) * 32;
    const int wn = (wid >> 2) * 64;

    const int Keff = (causal == 2) ? min(K, m0 + BM) : K;
    const int nch = Keff / BKC;

    auto fill = [&](int buf, int k0) {
        const uint32_t bb = sb + buf * BUF_B;
#pragma unroll
        for (int it = 0; it < 16; it++) {
            int idx = tid + it * 256;
            int tile = idx >> 10, r = (idx >> 3) & 127, c16 = idx & 7;
            uint32_t byte = (uint32_t)(r*128 + c16*16);
            uint32_t dst = bb + tile*TILE_B + (byte ^ ((byte >> 3) & 0x70));
            if (tile < 2) {
                const bf16* src = (tile == 0 ? Ah : Al) + (long long)(m0 + r)*lda + k0 + c16*8;
                asm volatile("cp.async.cg.shared.global [%0], [%1], 16;"::"r"(dst),"l"(src):"memory");
            } else if (n0 + r < N) {
                const bf16* src = (tile == 2 ? Bh : Bl) + (long long)(n0 + r)*ldb + k0 + c16*8;
                asm volatile("cp.async.cg.shared.global [%0], [%1], 16;"::"r"(dst),"l"(src):"memory");
            } else {
                asm volatile("st.shared.v4.b32 [%0], {%1,%1,%1,%1};"::"r"(dst),"r"(0u):"memory");
            }
        }
        asm volatile("cp.async.commit_group;" ::: "memory");
    };

    float acc[2][8][4];
#pragma unroll
    for (int i = 0; i < 2; i++)
#pragma unroll
        for (int j = 0; j < 8; j++)
#pragma unroll
            for (int q = 0; q < 4; q++) acc[i][j][q] = 0.f;

    fill(0, 0);
    if (nch > 1) fill(1, BKC);

    for (int ci = 0; ci < nch; ci++) {
        if (ci + 1 < nch) {
            asm volatile("cp.async.wait_group 1;" ::: "memory");
        } else {
            asm volatile("cp.async.wait_group 0;" ::: "memory");
        }
        __syncthreads();
        if (ci + 2 < nch) fill((ci + 2) % NSTAGE, (ci + 2) * BKC);

        const uint32_t bb = sb + (ci % NSTAGE) * BUF_B;
        const uint32_t tAh = bb, tAl = bb + TILE_B, tBh = bb + 2*TILE_B, tBl = bb + 3*TILE_B;
        const int arow = wm + (lane & 15);
        const int brow = wn + (lane & 7) + ((lane >> 4) << 3);

#pragma unroll
        for (int ks = 0; ks < 4; ks++) {
            const int akb = ks*2 + (lane >> 4);
            const int bkb = ks*2 + ((lane >> 3) & 1);
            uint32_t ah[2][4], al[2][4], bh[4][4], bl[4][4];
#pragma unroll
            for (int mi = 0; mi < 2; mi++) {
                ldsm4(ah[mi], swz(tAh, arow + mi*16, akb));
                ldsm4(al[mi], swz(tAl, arow + mi*16, akb));
            }
#pragma unroll
            for (int nj = 0; nj < 4; nj++) {
                ldsm4(bh[nj], swz(tBh, brow + nj*16, bkb));
                ldsm4(bl[nj], swz(tBl, brow + nj*16, bkb));
            }
#pragma unroll
            for (int mi = 0; mi < 2; mi++)
#pragma unroll
                for (int nj = 0; nj < 4; nj++) {
                    mma16816(acc[mi][2*nj],   ah[mi], &bh[nj][0]);
                    mma16816(acc[mi][2*nj+1], ah[mi], &bh[nj][2]);
                    mma16816(acc[mi][2*nj],   ah[mi], &bl[nj][0]);
                    mma16816(acc[mi][2*nj+1], ah[mi], &bl[nj][2]);
                    mma16816(acc[mi][2*nj],   al[mi], &bh[nj][0]);
                    mma16816(acc[mi][2*nj+1], al[mi], &bh[nj][2]);
                }
        }
        __syncthreads();
    }

#pragma unroll
    for (int mi = 0; mi < 2; mi++) {
        const int r0 = m0 + wm + mi*16 + (lane >> 2);
#pragma unroll
        for (int nb = 0; nb < 8; nb++) {
            const int c = n0 + wn + nb*8 + (lane & 3)*2;
            if (c < N) {
                const float* a = acc[mi][nb];
                const int cc = (mode == 2) ? ((c >> 7) * QKD + (c & 127)) : c;
                const long long off0 = coff + (long long)r0 * ldc + cc;
                const long long off1 = off0 + 8LL * ldc;
                if (mode == 0) {
                    *(float2*)(C + off0) = make_float2(a[0], a[1]);
                    *(float2*)(C + off1) = make_float2(a[2], a[3]);
                } else {
                    bf16 h0,l0,h1,l1;
                    split2(a[0],h0,l0); split2(a[1],h1,l1);
                    *(__nv_bfloat162*)(Chi+off0) = __halves2bfloat162(h0,h1);
                    *(__nv_bfloat162*)(Clo+off0) = __halves2bfloat162(l0,l1);
                    split2(a[2],h0,l0); split2(a[3],h1,l1);
                    *(__nv_bfloat162*)(Chi+off1) = __halves2bfloat162(h0,h1);
                    *(__nv_bfloat162*)(Clo+off1) = __halves2bfloat162(l0,l1);
                }
            }
        }
    }
}

// ---- fused online-softmax + P@vT ----
// grid (8, 64): x = 128-row t-tile, y = b*16+h. out[b][t][h*128+c] fp32.
constexpr int SMEM_FUSED = 2*32768 + 2*32768 + 1024;   // vT(2stg) + P(2stg) + stats

__global__ __launch_bounds__(256, 1)
void fused_pv(const float* __restrict__ S, const bf16* __restrict__ vTh,
              const bf16* __restrict__ vTl, float* __restrict__ out)
{
    const int bh = blockIdx.y, b = bh >> 4, h = bh & 15;
    const int m0 = blockIdx.x * 128;
    S   += (long long)bh * (1024*1024) + (long long)m0 * 1024;
    vTh += (long long)bh * 131072;
    vTl += (long long)bh * 131072;
    out += (long long)b * (1024*2048) + (long long)m0 * 2048 + h * 128;

    extern __shared__ __align__(1024) char smem[];
    const uint32_t sb = (uint32_t)__cvta_generic_to_shared(smem);
    float* fbuf = (float*)(smem + 131072);        // per-row rescale factor
    float* sbuf = fbuf + 128;                      // per-row final sum
    const int tid = threadIdx.x, wid = tid >> 5, lane = tid & 31;
    const int wm = (wid & 3) * 32, wn = (wid >> 2) * 64;
    const float scale = 0.07216878364870322f;      // 1/sqrt(192)

    auto VT = [&](int st, int hl){ return sb + (uint32_t)st*32768u + (uint32_t)hl*16384u; };
    auto PT = [&](int st, int hl){ return sb + 65536u + (uint32_t)st*32768u + (uint32_t)hl*16384u; };

    auto fill_vt = [&](int st, int k0) {
#pragma unroll
        for (int it = 0; it < 8; it++) {
            int idx = tid + it*256;
            int hl = idx >> 10, r = (idx >> 3) & 127, c16 = idx & 7;
            uint32_t byte = (uint32_t)(r*128 + c16*16);
            uint32_t dst = VT(st,hl) + (byte ^ ((byte>>3)&0x70));
            const bf16* src = (hl ? vTl : vTh) + r*1024 + k0 + c16*8;
            asm volatile("cp.async.cg.shared.global [%0], [%1], 16;"::"r"(dst),"l"(src):"memory");
        }
        asm volatile("cp.async.commit_group;" ::: "memory");
    };

    float acc[2][8][4];
#pragma unroll
    for (int i = 0; i < 2; i++)
#pragma unroll
        for (int j = 0; j < 8; j++)
#pragma unroll
            for (int q = 0; q < 4; q++) acc[i][j][q] = 0.f;

    float m8[8], s8[8];
#pragma unroll
    for (int i = 0; i < 8; i++) { m8[i] = -1e30f; s8[i] = 0.f; }

    const int nch = (m0 + 128) / 64;
    const int myrow0 = tid >> 4;       // rows myrow0 + it*16 belong to this 16-lane group
    const int c4 = tid & 15;           // 4-col group within 64-wide chunk
    fill_vt(0, 0);

    for (int ci = 0; ci < nch; ci++) {
        const int k0 = ci * 64;
        const int st = ci & 1;
        // ---- load S chunk, online softmax, write split P to smem ----
#pragma unroll
        for (int it = 0; it < 8; it++) {
            const int row = myrow0 + it*16;
            const int tg = m0 + row;
            const int sg = k0 + c4*4;
            float4 v = *(const float4*)(S + (long long)row*1024 + sg);
            float e0 = (sg+0 <= tg) ? v.x*scale : -1e30f;
            float e1 = (sg+1 <= tg) ? v.y*scale : -1e30f;
            float e2 = (sg+2 <= tg) ? v.z*scale : -1e30f;
            float e3 = (sg+3 <= tg) ? v.w*scale : -1e30f;
            float cm = fmaxf(fmaxf(e0,e1), fmaxf(e2,e3));
#pragma unroll
            for (int o = 1; o < 16; o <<= 1)
                cm = fmaxf(cm, __shfl_xor_sync(0xffffffffu, cm, o));
            const float om = m8[it];
            const float nm = fmaxf(om, cm);
            const float f  = __expf(om - nm);
            e0 = __expf(e0 - nm); e1 = __expf(e1 - nm);
            e2 = __expf(e2 - nm); e3 = __expf(e3 - nm);
            float cs = e0 + e1 + e2 + e3;
#pragma unroll
            for (int o = 1; o < 16; o <<= 1)
                cs += __shfl_xor_sync(0xffffffffu, cs, o);
            s8[it] = s8[it]*f + cs;
            m8[it] = nm;
            if (c4 == 0) fbuf[row] = f;
            bf16 h0,l0,h1,l1,h2,l2,h3,l3;
            split2(e0,h0,l0); split2(e1,h1,l1); split2(e2,h2,l2); split2(e3,h3,l3);
            uint32_t byte = (uint32_t)(row*128 + c4*8);
            uint32_t sw = byte ^ ((byte>>3)&0x70);
            asm volatile("st.shared.v2.b32 [%0], {%1,%2};"
                         ::"r"(PT(st,0)+sw),"r"(packbf2(h0,h1)),"r"(packbf2(h2,h3)):"memory");
            asm volatile("st.shared.v2.b32 [%0], {%1,%2};"
                         ::"r"(PT(st,1)+sw),"r"(packbf2(l0,l1)),"r"(packbf2(l2,l3)):"memory");
        }
        __syncthreads();                 // stats + P visible; also fences prior MMA
        // ---- rescale accumulator ----
#pragma unroll
        for (int mi = 0; mi < 2; mi++) {
            const int r0 = wm + mi*16 + (lane>>2);
            const float fa = fbuf[r0], fb = fbuf[r0+8];
#pragma unroll
            for (int nb = 0; nb < 8; nb++) {
                acc[mi][nb][0]*=fa; acc[mi][nb][1]*=fa;
                acc[mi][nb][2]*=fb; acc[mi][nb][3]*=fb;
            }
        }
        if (ci + 1 < nch) {
            fill_vt((ci+1)&1, k0+64);
            asm volatile("cp.async.wait_group 1;" ::: "memory");
        } else {
            asm volatile("cp.async.wait_group 0;" ::: "memory");
        }
        __syncthreads();                 // vT chunk visible to all
        // ---- MMA: acc += Ph·Bh + Ph·Bl + Pl·Bh ----
        const uint32_t tAh = PT(st,0), tAl = PT(st,1), tBh = VT(st,0), tBl = VT(st,1);
        const int arow = wm + (lane & 15);
        const int brow = wn + (lane & 7) + ((lane >> 4) << 3);
#pragma unroll
        for (int ks = 0; ks < 4; ks++) {
            const int akb = ks*2 + (lane >> 4);
            const int bkb = ks*2 + ((lane >> 3) & 1);
            uint32_t ah[2][4], al[2][4], bh[4][4], bl[4][4];
#pragma unroll
            for (int mi = 0; mi < 2; mi++) {
                ldsm4(ah[mi], swz(tAh, arow + mi*16, akb));
                ldsm4(al[mi], swz(tAl, arow + mi*16, akb));
            }
#pragma unroll
            for (int nj = 0; nj < 4; nj++) {
                ldsm4(bh[nj], swz(tBh, brow + nj*16, bkb));
                ldsm4(bl[nj], swz(tBl, brow + nj*16, bkb));
            }
#pragma unroll
            for (int mi = 0; mi < 2; mi++)
#pragma unroll
                for (int nj = 0; nj < 4; nj++) {
                    mma16816(acc[mi][2*nj],   ah[mi], &bh[nj][0]);
                    mma16816(acc[mi][2*nj+1], ah[mi], &bh[nj][2]);
                    mma16816(acc[mi][2*nj],   ah[mi], &bl[nj][0]);
                    mma16816(acc[mi][2*nj+1], ah[mi], &bl[nj][2]);
                    mma16816(acc[mi][2*nj],   al[mi], &bh[nj][0]);
                    mma16816(acc[mi][2*nj+1], al[mi], &bh[nj][2]);
                }
        }
    }

    // ---- epilogue: divide by row sums, write fp32 ----
    if (c4 == 0) {
#pragma unroll
        for (int it = 0; it < 8; it++) sbuf[myrow0 + it*16] = s8[it];
    }
    __syncthreads();
#pragma unroll
    for (int mi = 0; mi < 2; mi++) {
        const int r0 = wm + mi*16 + (lane >> 2);
        const float ia = 1.0f / sbuf[r0], ib = 1.0f / sbuf[r0+8];
#pragma unroll
        for (int nb = 0; nb < 8; nb++) {
            const int c = wn + nb*8 + (lane & 3)*2;
            const float* a = acc[mi][nb];
            *(float2*)(out + (long long)r0*2048 + c)     = make_float2(a[0]*ia, a[1]*ia);
            *(float2*)(out + (long long)(r0+8)*2048 + c) = make_float2(a[2]*ib, a[3]*ib);
        }
    }
}

// ---- prep kernels ----
__global__ void split_copy4(const float4* __restrict__ s, __nv_bfloat162* __restrict__ h,
                            __nv_bfloat162* __restrict__ l, long long n4)
{
    long long i = (long long)blockIdx.x*256 + threadIdx.x;
    if (i >= n4) return;
    float4 v = s[i];
    bf16 h0,l0,h1,l1;
    split2(v.x,h0,l0); split2(v.y,h1,l1);
    h[2*i]   = __halves2bfloat162(h0,h1);
    l[2*i]   = __halves2bfloat162(l0,l1);
    split2(v.z,h0,l0); split2(v.w,h1,l1);
    h[2*i+1] = __halves2bfloat162(h0,h1);
    l[2*i+1] = __halves2bfloat162(l0,l1);
}

__global__ void split_transpose(const float* __restrict__ src, bf16* __restrict__ hi,
                                bf16* __restrict__ lo, int R, int C,
                                long long sIn, long long sOut)
{
    __shared__ float t[32][33];
    int b = blockIdx.z, c0 = blockIdx.x*32, r0 = blockIdx.y*32;
    int tx = threadIdx.x, ty = threadIdx.y;
    const float* s = src + (long long)b*sIn;
#pragma unroll
    for (int j = 0; j < 4; j++)
        t[ty + j*8][tx] = s[(long long)(r0 + ty + j*8)*C + c0 + tx];
    __syncthreads();
#pragma unroll
    for (int j = 0; j < 4; j++) {
        long long o = (long long)b*sOut + (long long)(c0 + ty + j*8)*R + r0 + tx;
        bf16 h, l; split2(t[tx][ty + j*8], h, l);
        hi[o] = h; lo[o] = l;
    }
}

__global__ void rope_q_kernel(const float* __restrict__ cqr, const float* __restrict__ fc,
                              const float* __restrict__ fs, bf16* __restrict__ QHh,
                              bf16* __restrict__ QHl)
{
    int idx = blockIdx.x*256 + threadIdx.x;
    if (idx >= BATCH*SEQ*NHEAD*32) return;
    int j = idx & 31, h = (idx >> 5) & 15, bt = idx >> 9;
    int t = bt & (SEQ-1);
    long long src = (long long)bt*(NHEAD*DHR) + h*DHR + 2*j;
    float re = cqr[src], im = cqr[src+1];
    float c = fc[t*32 + j], s = fs[t*32 + j];
    long long row = (long long)bt*(NHEAD*QKD) + h*QKD + 128 + 2*j;
    bf16 h0,l0,h1,l1;
    split2(re*c - im*s, h0, l0); split2(re*s + im*c, h1, l1);
    QHh[row] = h0; QHl[row] = l0; QHh[row+1] = h1; QHl[row+1] = l1;
}

__global__ void rope_k_kernel(const float* __restrict__ ckr, const float* __restrict__ fc,
                              const float* __restrict__ fs, bf16* __restrict__ KHh,
                              bf16* __restrict__ KHl)
{
    int idx = blockIdx.x*256 + threadIdx.x;
    if (idx >= BATCH*SEQ*32) return;
    int j = idx & 31, bt = idx >> 5, t = bt & (SEQ-1);
    long long src = (long long)bt*DHR + 2*j;
    float re = ckr[src], im = ckr[src+1];
    float c = fc[t*32 + j], s = fs[t*32 + j];
    bf16 h0,l0,h1,l1;
    split2(re*c - im*s, h0, l0); split2(re*s + im*c, h1, l1);
    long long base = (long long)bt*(NHEAD*QKD) + 128 + 2*j;
#pragma unroll
    for (int h = 0; h < NHEAD; h++) {
        long long row = base + h*QKD;
        KHh[row] = h0; KHl[row] = l0; KHh[row+1] = h1; KHl[row+1] = l1;
    }
}

// ---- launch ----
extern "C" void kernel_launch(void* const* d_in, const int* in_sizes, int n_in,
                              void* d_out, int out_size)
{
    const float* x     = (const float*)d_in[0];
    const float* W_dq  = (const float*)d_in[1];
    const float* W_uq  = (const float*)d_in[2];
    const float* W_dkv = (const float*)d_in[3];
    const float* W_uk  = (const float*)d_in[4];
    const float* W_uv  = (const float*)d_in[5];
    const float* W_o   = (const float*)d_in[6];
    const float* W_qr  = (const float*)d_in[7];
    const float* W_kr  = (const float*)d_in[8];
    const float* fc    = (const float*)d_in[9];
    const float* fs    = (const float*)d_in[10];
    float* out = (float*)d_out;

    cudaFuncSetAttribute(gemm3, cudaFuncAttributeMaxDynamicSharedMemorySize, SMEM_GEMM);
    cudaFuncSetAttribute(fused_pv, cudaFuncAttributeMaxDynamicSharedMemorySize, SMEM_FUSED);

#define SYM(v, s) cudaGetSymbolAddress((void**)&v, s)
    bf16 *xh,*xl,*dqh,*dql,*dkvh,*dkvl,*krh,*krl,*qrh,*qrl,*uqTh,*uqTl,*ukh,*ukl;
    bf16 *woh,*wol,*uvTh,*uvTl,*Zh,*Zl,*cqh,*cql,*KCh,*KCl,*QHh,*QHl,*KHh,*KHl;
    bf16 *vTh,*vTl;
    float *cqr,*ckr,*S;
    SYM(xh,g_x_h); SYM(xl,g_x_l); SYM(dqh,g_Wdq_h); SYM(dql,g_Wdq_l);
    SYM(dkvh,g_Wdkv_h); SYM(dkvl,g_Wdkv_l); SYM(krh,g_Wkr_h); SYM(krl,g_Wkr_l);
    SYM(qrh,g_Wqr_h); SYM(qrl,g_Wqr_l); SYM(uqTh,g_WuqT_h); SYM(uqTl,g_WuqT_l);
    SYM(ukh,g_Wuk_h); SYM(ukl,g_Wuk_l);
    SYM(woh,g_Wo_h); SYM(wol,g_Wo_l); SYM(uvTh,g_WuvT_h); SYM(uvTl,g_WuvT_l);
    SYM(Zh,g_Z_h); SYM(Zl,g_Z_l); SYM(cqh,g_cq_h); SYM(cql,g_cq_l);
    SYM(KCh,g_KC_h); SYM(KCl,g_KC_l); SYM(QHh,g_QH_h); SYM(QHl,g_QH_l);
    SYM(KHh,g_KH_h); SYM(KHl,g_KH_l);
    SYM(vTh,g_vT_h); SYM(vTl,g_vT_l);
    SYM(cqr,g_cqr); SYM(ckr,g_ckr); SYM(S,g_S);
#undef SYM

    auto SC = [](const float* s, bf16* h, bf16* l, long long n) {
        split_copy4<<<(unsigned)((n/4 + 255)/256), 256>>>(
            (const float4*)s, (__nv_bfloat162*)h, (__nv_bfloat162*)l, n/4);
    };
    dim3 blk(256);
    const int LDH = NHEAD * QKD;                   // 3072
    const long long SB = (long long)SEQ * LDH;     // per-batch stride

    // ---- splits / transposes ----
    SC(x, xh, xl, 8388608);
    SC(W_dq, dqh, dql, 1048576);
    SC(W_dkv, dkvh, dkvl, 1048576);
    SC(W_kr, krh, krl, 131072);
    SC(W_qr, qrh, qrl, 524288);
    SC(W_uk, ukh, ukl, 1048576);
    SC(W_o, woh, wol, 4194304);
    split_transpose<<<dim3(64, 16, 1), dim3(32, 8)>>>(W_uq, uqTh, uqTl, 512, 2048, 0, 0);
    split_transpose<<<dim3(16, 64, 1), dim3(32, 8)>>>(W_uv, uvTh, uvTl, 2048, 512, 0, 0);

    // ---- GEMMs ----
    // c_q = x @ W_dq^T -> split
    gemm3<<<dim3(4, 32, 1), blk, SMEM_GEMM>>>(xh, xl, 0, 0, 2048, dqh, dql, 0, 0, 2048,
        nullptr, cqh, cql, 0, 0, 512, 4096, 512, 2048, 1, 1, 0);
    // c_kv -> KC split (ldc=576)
    gemm3<<<dim3(4, 32, 1), blk, SMEM_GEMM>>>(xh, xl, 0, 0, 2048, dkvh, dkvl, 0, 0, 2048,
        nullptr, KCh, KCl, 0, 0, 576, 4096, 512, 2048, 1, 1, 0);
    // Z = W_o @ W_uv -> split
    gemm3<<<dim3(4, 16, 1), blk, SMEM_GEMM>>>(woh, wol, 0, 0, 2048, uvTh, uvTl, 0, 0, 2048,
        nullptr, Zh, Zl, 0, 0, 512, 2048, 512, 2048, 1, 1, 0);
    // vT[b,h] = Z_h @ c_kv[b]^T -> split (128x1024)
    gemm3<<<dim3(8, 1, 64), blk, SMEM_GEMM>>>(Zh, Zl, 0, 65536, 512,
        KCh, KCl, 589824, 0, 576,
        nullptr, vTh, vTl, 2097152, 131072, 1024, 128, 1024, 512, 16, 1, 0);
    // c_kr = x @ W_kr^T -> fp32
    gemm3<<<dim3(1, 32, 1), blk, SMEM_GEMM>>>(xh, xl, 0, 0, 2048, krh, krl, 0, 0, 2048,
        ckr, nullptr, nullptr, 0, 0, 64, 4096, 64, 2048, 1, 0, 0);
    // c_qr = c_q @ W_qr^T -> fp32
    gemm3<<<dim3(8, 32, 1), blk, SMEM_GEMM>>>(cqh, cql, 0, 0, 512, qrh, qrl, 0, 0, 512,
        cqr, nullptr, nullptr, 0, 0, 1024, 4096, 1024, 512, 1, 0, 0);
    // Q = c_q @ WuqT^T -> QH split, col remap, ldc=3072
    gemm3<<<dim3(16, 32, 1), blk, SMEM_GEMM>>>(cqh, cql, 0, 0, 512, uqTh, uqTl, 0, 0, 512,
        nullptr, QHh, QHl, 0, 0, LDH, 4096, 2048, 512, 1, 2, 0);
    // KH[b,h] = c_kv[b] @ W_uk_h^T -> split, ldc=3072
    gemm3<<<dim3(1, 8, 64), blk, SMEM_GEMM>>>(KCh, KCl, 589824, 0, 576,
        ukh, ukl, 0, 65536, 512,
        nullptr, KHh, KHl, SB, QKD, LDH, 1024, 128, 512, 16, 1, 0);
    // RoPE tails
    rope_q_kernel<<<(BATCH*SEQ*NHEAD*32 + 255)/256, 256>>>(cqr, fc, fs, QHh, QHl);
    rope_k_kernel<<<(BATCH*SEQ*32 + 255)/256, 256>>>(ckr, fc, fs, KHh, KHl);
    // S[b,h] = QH[b,h] @ KH[b,h]^T (K=192), causal skip -> fp32
    gemm3<<<dim3(8, 8, 64), blk, SMEM_GEMM>>>(QHh, QHl, SB, QKD, LDH,
        KHh, KHl, SB, QKD, LDH,
        S, nullptr, nullptr, 16777216, 1048576, 1024, 1024, 1024, QKD, 16, 0, 1);
    // fused softmax + P@vT -> out
    fused_pv<<<dim3(8, 64, 1), blk, SMEM_FUSED>>>(S, vTh, vTl, out);
}

// round 12
// speedup vs baseline: 3.0021x; 1.0591x over previous
#include <cuda_runtime.h>
#include <cuda_bf16.h>
#include <stdint.h>
#include <math.h>

using bf16 = __nv_bfloat16;

constexpr int BATCH = 4, SEQ = 1024, CDIM = 2048, NHEAD = 16, HS = 128;
constexpr int NLQ = 512, NLKV = 512, DHR = 64, QKD = 192;   // per-head [k_h | rope]

// ---- scratch (hi/lo bf16 split pairs) ----
__device__ __align__(128) bf16 g_x_h[8388608],   g_x_l[8388608];
__device__ __align__(128) bf16 g_Wdq_h[1048576], g_Wdq_l[1048576];
__device__ __align__(128) bf16 g_Wdkv_h[1048576],g_Wdkv_l[1048576];
__device__ __align__(128) bf16 g_Wkr_h[131072],  g_Wkr_l[131072];
__device__ __align__(128) bf16 g_Wqr_h[524288],  g_Wqr_l[524288];
__device__ __align__(128) bf16 g_WuqT_h[1048576],g_WuqT_l[1048576];  // (2048x512)
__device__ __align__(128) bf16 g_Wuk_h[1048576], g_Wuk_l[1048576];   // raw [h][128][512]
__device__ __align__(128) bf16 g_Wo_h[4194304],  g_Wo_l[4194304];
__device__ __align__(128) bf16 g_WuvT_h[1048576],g_WuvT_l[1048576];
__device__ __align__(128) bf16 g_Z_h[1048576],   g_Z_l[1048576];
__device__ __align__(128) bf16 g_cq_h[2097152],  g_cq_l[2097152];
__device__ __align__(128) bf16 g_KC_h[2359296],  g_KC_l[2359296];    // [b][s][576] c_kv
__device__ __align__(128) bf16 g_QH_h[12582912], g_QH_l[12582912];   // [b][t][h][192]
__device__ __align__(128) bf16 g_KH_h[12582912], g_KH_l[12582912];   // [b][s][h][192]
__device__ __align__(128) bf16 g_vT_h[8388608],  g_vT_l[8388608];    // [b,h] 128x1024
__device__ __align__(128) float g_cqr[4194304], g_ckr[262144];

// ---- helpers ----
__device__ __forceinline__ void split2(float v, bf16& h, bf16& l) {
    h = __float2bfloat16(v);
    l = __float2bfloat16(v - __bfloat162float(h));
}
__device__ __forceinline__ uint32_t packbf2(bf16 a, bf16 b) {
    __nv_bfloat162 p = __halves2bfloat162(a, b);
    return *reinterpret_cast<uint32_t*>(&p);
}
__device__ __forceinline__ void ldsm4(uint32_t* r, uint32_t addr) {
    asm volatile("ldmatrix.sync.aligned.m8n8.x4.shared.b16 {%0,%1,%2,%3}, [%4];"
        : "=r"(r[0]), "=r"(r[1]), "=r"(r[2]), "=r"(r[3]) : "r"(addr));
}
__device__ __forceinline__ void mma16816(float* d, const uint32_t* a, const uint32_t* b) {
    asm volatile("mma.sync.aligned.m16n8k16.row.col.f32.bf16.bf16.f32 "
        "{%0,%1,%2,%3}, {%4,%5,%6,%7}, {%8,%9}, {%0,%1,%2,%3};"
        : "+f"(d[0]), "+f"(d[1]), "+f"(d[2]), "+f"(d[3])
        : "r"(a[0]), "r"(a[1]), "r"(a[2]), "r"(a[3]), "r"(b[0]), "r"(b[1]));
}
__device__ __forceinline__ uint32_t swz(uint32_t tile_base, int r, int kb16) {
    uint32_t byte = (uint32_t)(r * 128 + kb16 * 16);
    return tile_base + (byte ^ ((byte >> 3) & 0x70));
}
#define CPA16(dst, src) \
    asm volatile("cp.async.cg.shared.global [%0], [%1], 16;"::"r"(dst),"l"(src):"memory")
#define CPA_COMMIT() asm volatile("cp.async.commit_group;" ::: "memory")
#define CPA_WAIT(n)  asm volatile("cp.async.wait_group %0;" :: "n"(n) : "memory")

// ---- HMMA batched GEMM: D = (Ah+Al) @ (Bh+Bl)^T (3-term split) ----
constexpr int BM = 128, BN = 128, BKC = 64;
constexpr int TILE_B = 16384;
constexpr int BUF_B  = 4 * TILE_B;
constexpr int NSTAGE = 3;
constexpr int SMEM_GEMM = NSTAGE * BUF_B;     // 192 KB

__global__ __launch_bounds__(256, 1)
void gemm3(const bf16* __restrict__ Ah, const bf16* __restrict__ Al,
           long long sA0, long long sA1, int lda,
           const bf16* __restrict__ Bh, const bf16* __restrict__ Bl,
           long long sB0, long long sB1, int ldb,
           float* __restrict__ C, bf16* __restrict__ Chi, bf16* __restrict__ Clo,
           long long sC0, long long sC1, int ldc,
           int M, int N, int K, int zdiv, int mode, int causal)
{
    const int m0 = blockIdx.y * BM, n0 = blockIdx.x * BN;
    if (causal == 1 && n0 >= m0 + BM) return;
    const int z = blockIdx.z, z0 = z / zdiv, z1 = z % zdiv;
    Ah += z0*sA0 + z1*sA1;  Al += z0*sA0 + z1*sA1;
    Bh += z0*sB0 + z1*sB1;  Bl += z0*sB0 + z1*sB1;
    const long long coff = z0*sC0 + z1*sC1;

    extern __shared__ __align__(1024) char smem[];
    const uint32_t sb = (uint32_t)__cvta_generic_to_shared(smem);
    const int tid = threadIdx.x, wid = tid >> 5, lane = tid & 31;
    const int wm = (wid & 3) * 32;
    const int wn = (wid >> 2) * 64;

    const int Keff = (causal == 2) ? min(K, m0 + BM) : K;
    const int nch = Keff / BKC;

    auto fill = [&](int buf, int k0) {
        const uint32_t bb = sb + buf * BUF_B;
#pragma unroll
        for (int it = 0; it < 16; it++) {
            int idx = tid + it * 256;
            int tile = idx >> 10, r = (idx >> 3) & 127, c16 = idx & 7;
            uint32_t byte = (uint32_t)(r*128 + c16*16);
            uint32_t dst = bb + tile*TILE_B + (byte ^ ((byte >> 3) & 0x70));
            if (tile < 2) {
                const bf16* src = (tile == 0 ? Ah : Al) + (long long)(m0 + r)*lda + k0 + c16*8;
                CPA16(dst, src);
            } else if (n0 + r < N) {
                const bf16* src = (tile == 2 ? Bh : Bl) + (long long)(n0 + r)*ldb + k0 + c16*8;
                CPA16(dst, src);
            } else {
                asm volatile("st.shared.v4.b32 [%0], {%1,%1,%1,%1};"::"r"(dst),"r"(0u):"memory");
            }
        }
        CPA_COMMIT();
    };

    float acc[2][8][4];
#pragma unroll
    for (int i = 0; i < 2; i++)
#pragma unroll
        for (int j = 0; j < 8; j++)
#pragma unroll
            for (int q = 0; q < 4; q++) acc[i][j][q] = 0.f;

    fill(0, 0);
    if (nch > 1) fill(1, BKC);

    for (int ci = 0; ci < nch; ci++) {
        if (ci + 1 < nch) { CPA_WAIT(1); } else { CPA_WAIT(0); }
        __syncthreads();
        if (ci + 2 < nch) fill((ci + 2) % NSTAGE, (ci + 2) * BKC);

        const uint32_t bb = sb + (ci % NSTAGE) * BUF_B;
        const uint32_t tAh = bb, tAl = bb + TILE_B, tBh = bb + 2*TILE_B, tBl = bb + 3*TILE_B;
        const int arow = wm + (lane & 15);
        const int brow = wn + (lane & 7) + ((lane >> 4) << 3);

#pragma unroll
        for (int ks = 0; ks < 4; ks++) {
            const int akb = ks*2 + (lane >> 4);
            const int bkb = ks*2 + ((lane >> 3) & 1);
            uint32_t ah[2][4], al[2][4], bh[4][4], bl[4][4];
#pragma unroll
            for (int mi = 0; mi < 2; mi++) {
                ldsm4(ah[mi], swz(tAh, arow + mi*16, akb));
                ldsm4(al[mi], swz(tAl, arow + mi*16, akb));
            }
#pragma unroll
            for (int nj = 0; nj < 4; nj++) {
                ldsm4(bh[nj], swz(tBh, brow + nj*16, bkb));
                ldsm4(bl[nj], swz(tBl, brow + nj*16, bkb));
            }
#pragma unroll
            for (int mi = 0; mi < 2; mi++)
#pragma unroll
                for (int nj = 0; nj < 4; nj++) {
                    mma16816(acc[mi][2*nj],   ah[mi], &bh[nj][0]);
                    mma16816(acc[mi][2*nj+1], ah[mi], &bh[nj][2]);
                    mma16816(acc[mi][2*nj],   ah[mi], &bl[nj][0]);
                    mma16816(acc[mi][2*nj+1], ah[mi], &bl[nj][2]);
                    mma16816(acc[mi][2*nj],   al[mi], &bh[nj][0]);
                    mma16816(acc[mi][2*nj+1], al[mi], &bh[nj][2]);
                }
        }
        __syncthreads();
    }

#pragma unroll
    for (int mi = 0; mi < 2; mi++) {
        const int r0 = m0 + wm + mi*16 + (lane >> 2);
#pragma unroll
        for (int nb = 0; nb < 8; nb++) {
            const int c = n0 + wn + nb*8 + (lane & 3)*2;
            if (c < N) {
                const float* a = acc[mi][nb];
                const int cc = (mode == 2) ? ((c >> 7) * QKD + (c & 127)) : c;
                const long long off0 = coff + (long long)r0 * ldc + cc;
                const long long off1 = off0 + 8LL * ldc;
                if (mode == 0) {
                    *(float2*)(C + off0) = make_float2(a[0], a[1]);
                    *(float2*)(C + off1) = make_float2(a[2], a[3]);
                } else {
                    bf16 h0,l0,h1,l1;
                    split2(a[0],h0,l0); split2(a[1],h1,l1);
                    *(__nv_bfloat162*)(Chi+off0) = __halves2bfloat162(h0,h1);
                    *(__nv_bfloat162*)(Clo+off0) = __halves2bfloat162(l0,l1);
                    split2(a[2],h0,l0); split2(a[3],h1,l1);
                    *(__nv_bfloat162*)(Chi+off1) = __halves2bfloat162(h0,h1);
                    *(__nv_bfloat162*)(Clo+off1) = __halves2bfloat162(l0,l1);
                }
            }
        }
    }
}

// ---- flash attention: S-MMA + online softmax + P@vT, one kernel ----
// grid (8 mtiles, 64 bh), 256 thr. smem: Q 96K | KH 48K | vT 32K | P 32K | stats
constexpr int FL_Q  = 0;          // 6 x 16384
constexpr int FL_KH = 98304;      // 6 x 8192
constexpr int FL_VT = 147456;     // 2 x 16384
constexpr int FL_P  = 180224;     // 2 x 16384
constexpr int FL_ST = 212992;     // stats (floats)
constexpr int SMEM_FLASH = 212992 + 7*512;

__global__ __launch_bounds__(256, 1)
void flash_pv(const bf16* __restrict__ QHh_, const bf16* __restrict__ QHl_,
              const bf16* __restrict__ KHh_, const bf16* __restrict__ KHl_,
              const bf16* __restrict__ vTh_, const bf16* __restrict__ vTl_,
              float* __restrict__ out)
{
    const int bh = blockIdx.y, b = bh >> 4, h = bh & 15;
    const int m0 = blockIdx.x * 128;
    const long long qkbase = (long long)b*(1024*3072) + h*QKD;
    const bf16* vTh = vTh_ + (long long)bh * 131072;
    const bf16* vTl = vTl_ + (long long)bh * 131072;
    out += (long long)b*(1024*2048) + (long long)m0*2048 + h*128;

    extern __shared__ __align__(1024) char smem[];
    const uint32_t sb = (uint32_t)__cvta_generic_to_shared(smem);
    float* mxA  = (float*)(smem + FL_ST);
    float* mxB  = mxA + 128;
    float* sA   = mxA + 256;
    float* sB   = mxA + 384;
    float* fbuf = mxA + 512;
    float* mrow = mxA + 640;
    float* srow = mxA + 768;

    const int tid = threadIdx.x, wid = tid >> 5, lane = tid & 31;
    const int wm  = (wid & 3) * 32;
    const int wns = (wid >> 2) * 32;
    const int wn  = (wid >> 2) * 64;
    const float scale = 0.07216878364870322f;   // 1/sqrt(192)

    auto QT = [&](int kt, int hl){ return sb + FL_Q  + (uint32_t)(kt*2+hl)*16384u; };
    auto KT = [&](int kt, int hl){ return sb + FL_KH + (uint32_t)(kt*2+hl)*8192u; };
    auto VTb = [&](int hl){ return sb + FL_VT + (uint32_t)hl*16384u; };
    auto PTb = [&](int hl){ return sb + FL_P  + (uint32_t)hl*16384u; };

    if (tid < 128) { mrow[tid] = -1e30f; srow[tid] = 0.f; }

    auto fill_kh = [&](int s0) {
#pragma unroll
        for (int it = 0; it < 12; it++) {
            int idx = tid + it*256;                 // 0..3071
            int tile = idx >> 9, r = (idx >> 3) & 63, c16 = idx & 7;
            int kt = tile >> 1, hl = tile & 1;
            uint32_t byte = (uint32_t)(r*128 + c16*16);
            uint32_t dst = KT(kt,hl) + (byte ^ ((byte>>3)&0x70));
            const bf16* src = (hl ? KHl_ : KHh_) + qkbase + (long long)(s0+r)*3072 + kt*64 + c16*8;
            CPA16(dst, src);
        }
    };
    auto fill_vt = [&](int s0) {
#pragma unroll
        for (int it = 0; it < 8; it++) {
            int idx = tid + it*256;
            int hl = idx >> 10, r = (idx >> 3) & 127, c16 = idx & 7;
            uint32_t byte = (uint32_t)(r*128 + c16*16);
            uint32_t dst = VTb(hl) + (byte ^ ((byte>>3)&0x70));
            const bf16* src = (hl ? vTl : vTh) + r*1024 + s0 + c16*8;
            CPA16(dst, src);
        }
    };

    // prologue: Q tiles + KH_0 (group 1), vT_0 (group 2)
#pragma unroll
    for (int it = 0; it < 24; it++) {
        int idx = tid + it*256;                     // 0..6143
        int tile = idx >> 10, r = (idx >> 3) & 127, c16 = idx & 7;
        int kt = tile >> 1, hl = tile & 1;
        uint32_t byte = (uint32_t)(r*128 + c16*16);
        uint32_t dst = QT(kt,hl) + (byte ^ ((byte>>3)&0x70));
        const bf16* src = (hl ? QHl_ : QHh_) + qkbase + (long long)(m0+r)*3072 + kt*64 + c16*8;
        CPA16(dst, src);
    }
    fill_kh(0);
    CPA_COMMIT();
    fill_vt(0);
    CPA_COMMIT();

    float acc[2][8][4];
#pragma unroll
    for (int i = 0; i < 2; i++)
#pragma unroll
        for (int j = 0; j < 8; j++)
#pragma unroll
            for (int q = 0; q < 4; q++) acc[i][j][q] = 0.f;

    const int nch = m0/64 + 2;
    for (int ci = 0; ci < nch; ci++) {
        const int s0 = ci * 64;
        CPA_WAIT(1);                 // KH_ci (and Q) ready; vT may pend
        __syncthreads();

        // ---- S-MMA: sacc = Q @ KH^T (K=192, 3-term) ----
        float sacc[2][4][4];
#pragma unroll
        for (int i = 0; i < 2; i++)
#pragma unroll
            for (int j = 0; j < 4; j++)
#pragma unroll
                for (int q = 0; q < 4; q++) sacc[i][j][q] = 0.f;

        const int arow = wm + (lane & 15);
        const int brs = wns + (lane & 7) + ((lane >> 4) << 3);
#pragma unroll
        for (int kt = 0; kt < 3; kt++) {
#pragma unroll
            for (int ks = 0; ks < 4; ks++) {
                const int akb = ks*2 + (lane >> 4);
                const int bkb = ks*2 + ((lane >> 3) & 1);
                uint32_t ah[2][4], al[2][4], bhf[2][4], blf[2][4];
#pragma unroll
                for (int mi = 0; mi < 2; mi++) {
                    ldsm4(ah[mi], swz(QT(kt,0), arow + mi*16, akb));
                    ldsm4(al[mi], swz(QT(kt,1), arow + mi*16, akb));
                }
#pragma unroll
                for (int nj = 0; nj < 2; nj++) {
                    ldsm4(bhf[nj], swz(KT(kt,0), brs + nj*16, bkb));
                    ldsm4(blf[nj], swz(KT(kt,1), brs + nj*16, bkb));
                }
#pragma unroll
                for (int mi = 0; mi < 2; mi++)
#pragma unroll
                    for (int nj = 0; nj < 2; nj++) {
                        mma16816(sacc[mi][2*nj],   ah[mi], &bhf[nj][0]);
                        mma16816(sacc[mi][2*nj+1], ah[mi], &bhf[nj][2]);
                        mma16816(sacc[mi][2*nj],   ah[mi], &blf[nj][0]);
                        mma16816(sacc[mi][2*nj+1], ah[mi], &blf[nj][2]);
                        mma16816(sacc[mi][2*nj],   al[mi], &bhf[nj][0]);
                        mma16816(sacc[mi][2*nj+1], al[mi], &bhf[nj][2]);
                    }
            }
        }

        // ---- mask + scale + chunk row-max ----
#pragma unroll
        for (int mi = 0; mi < 2; mi++)
#pragma unroll
            for (int rh = 0; rh < 2; rh++) {
                const int rl = wm + mi*16 + (lane >> 2) + rh*8;
                const int rg = m0 + rl;
                float mx = -1e30f;
#pragma unroll
                for (int nb = 0; nb < 4; nb++) {
                    const int cg = s0 + wns + nb*8 + (lane & 3)*2;
                    float* a = sacc[mi][nb];
                    float v0 = (cg   <= rg) ? a[rh*2+0]*scale : -1e30f;
                    float v1 = (cg+1 <= rg) ? a[rh*2+1]*scale : -1e30f;
                    a[rh*2+0] = v0; a[rh*2+1] = v1;
                    mx = fmaxf(mx, fmaxf(v0, v1));
                }
                mx = fmaxf(mx, __shfl_xor_sync(0xffffffffu, mx, 1));
                mx = fmaxf(mx, __shfl_xor_sync(0xffffffffu, mx, 2));
                if ((lane & 3) == 0) ((wid >> 2) ? mxB : mxA)[rl] = mx;
            }
        __syncthreads();             // S-MMA done (KH free), mx slots visible
        if (ci + 1 < nch) fill_kh(s0 + 64);
        CPA_COMMIT();

        // ---- online softmax: exp + split-P writes + partial sums ----
        float fv[2][2], nmv[2][2];
#pragma unroll
        for (int mi = 0; mi < 2; mi++)
#pragma unroll
            for (int rh = 0; rh < 2; rh++) {
                const int rl = wm + mi*16 + (lane >> 2) + rh*8;
                const float nm = fmaxf(mrow[rl], fmaxf(mxA[rl], mxB[rl]));
                const float f  = __expf(mrow[rl] - nm);
                nmv[mi][rh] = nm; fv[mi][rh] = f;
                float ps = 0.f;
#pragma unroll
                for (int nb = 0; nb < 4; nb++) {
                    const float* a = sacc[mi][nb];
                    float e0 = __expf(a[rh*2+0] - nm);
                    float e1 = __expf(a[rh*2+1] - nm);
                    ps += e0 + e1;
                    bf16 h0,l0,h1,l1;
                    split2(e0,h0,l0); split2(e1,h1,l1);
                    uint32_t byte = (uint32_t)(rl*128 + (wns + nb*8 + (lane & 3)*2)*2);
                    uint32_t sw = byte ^ ((byte>>3)&0x70);
                    asm volatile("st.shared.b32 [%0], %1;"::"r"(PTb(0)+sw),"r"(packbf2(h0,h1)):"memory");
                    asm volatile("st.shared.b32 [%0], %1;"::"r"(PTb(1)+sw),"r"(packbf2(l0,l1)):"memory");
                }
                ps += __shfl_xor_sync(0xffffffffu, ps, 1);
                ps += __shfl_xor_sync(0xffffffffu, ps, 2);
                if ((lane & 3) == 0) {
                    ((wid >> 2) ? sB : sA)[rl] = ps;
                    if ((wid >> 2) == 0) fbuf[rl] = f;
                }
            }
        __syncthreads();             // P, sums, fbuf visible

        // ---- update running stats; rescale out-acc ----
        if ((lane & 3) == 0 && (wid >> 2) == 0) {
#pragma unroll
            for (int mi = 0; mi < 2; mi++)
#pragma unroll
                for (int rh = 0; rh < 2; rh++) {
                    const int rl = wm + mi*16 + (lane >> 2) + rh*8;
                    srow[rl] = srow[rl]*fv[mi][rh] + sA[rl] + sB[rl];
                    mrow[rl] = nmv[mi][rh];
                }
        }
#pragma unroll
        for (int mi = 0; mi < 2; mi++) {
            const int r0 = wm + mi*16 + (lane >> 2);
            const float fa = fbuf[r0], fb = fbuf[r0+8];
#pragma unroll
            for (int nb = 0; nb < 8; nb++) {
                acc[mi][nb][0]*=fa; acc[mi][nb][1]*=fa;
                acc[mi][nb][2]*=fb; acc[mi][nb][3]*=fb;
            }
        }

        CPA_WAIT(1);                 // vT_ci ready (KH_{ci+1} may pend)
        __syncthreads();

        // ---- PV MMA: acc += P @ vT^T (3-term) ----
        const int brow = wn + (lane & 7) + ((lane >> 4) << 3);
#pragma unroll
        for (int ks = 0; ks < 4; ks++) {
            const int akb = ks*2 + (lane >> 4);
            const int bkb = ks*2 + ((lane >> 3) & 1);
            uint32_t ah[2][4], al[2][4], bhf[4][4], blf[4][4];
#pragma unroll
            for (int mi = 0; mi < 2; mi++) {
                ldsm4(ah[mi], swz(PTb(0), arow + mi*16, akb));
                ldsm4(al[mi], swz(PTb(1), arow + mi*16, akb));
            }
#pragma unroll
            for (int nj = 0; nj < 4; nj++) {
                ldsm4(bhf[nj], swz(VTb(0), brow + nj*16, bkb));
                ldsm4(blf[nj], swz(VTb(1), brow + nj*16, bkb));
            }
#pragma unroll
            for (int mi = 0; mi < 2; mi++)
#pragma unroll
                for (int nj = 0; nj < 4; nj++) {
                    mma16816(acc[mi][2*nj],   ah[mi], &bhf[nj][0]);
                    mma16816(acc[mi][2*nj+1], ah[mi], &bhf[nj][2]);
                    mma16816(acc[mi][2*nj],   ah[mi], &blf[nj][0]);
                    mma16816(acc[mi][2*nj+1], ah[mi], &blf[nj][2]);
                    mma16816(acc[mi][2*nj],   al[mi], &bhf[nj][0]);
                    mma16816(acc[mi][2*nj+1], al[mi], &bhf[nj][2]);
                }
        }
        __syncthreads();             // PV done (vT + P free)
        if (ci + 1 < nch) fill_vt(s0 + 64);
        CPA_COMMIT();
    }

    // ---- epilogue: divide by row sums, write fp32 ----
    __syncthreads();
#pragma unroll
    for (int mi = 0; mi < 2; mi++) {
        const int r0 = wm + mi*16 + (lane >> 2);
        const float ia = 1.0f / srow[r0], ib = 1.0f / srow[r0+8];
#pragma unroll
        for (int nb = 0; nb < 8; nb++) {
            const int c = wn + nb*8 + (lane & 3)*2;
            const float* a = acc[mi][nb];
            *(float2*)(out + (long long)r0*2048 + c)     = make_float2(a[0]*ia, a[1]*ia);
            *(float2*)(out + (long long)(r0+8)*2048 + c) = make_float2(a[2]*ib, a[3]*ib);
        }
    }
}

// ---- prep kernels ----
__global__ void split_copy4(const float4* __restrict__ s, __nv_bfloat162* __restrict__ h,
                            __nv_bfloat162* __restrict__ l, long long n4)
{
    long long i = (long long)blockIdx.x*256 + threadIdx.x;
    if (i >= n4) return;
    float4 v = s[i];
    bf16 h0,l0,h1,l1;
    split2(v.x,h0,l0); split2(v.y,h1,l1);
    h[2*i]   = __halves2bfloat162(h0,h1);
    l[2*i]   = __halves2bfloat162(l0,l1);
    split2(v.z,h0,l0); split2(v.w,h1,l1);
    h[2*i+1] = __halves2bfloat162(h0,h1);
    l[2*i+1] = __halves2bfloat162(l0,l1);
}

__global__ void split_transpose(const float* __restrict__ src, bf16* __restrict__ hi,
                                bf16* __restrict__ lo, int R, int C,
                                long long sIn, long long sOut)
{
    __shared__ float t[32][33];
    int b = blockIdx.z, c0 = blockIdx.x*32, r0 = blockIdx.y*32;
    int tx = threadIdx.x, ty = threadIdx.y;
    const float* s = src + (long long)b*sIn;
#pragma unroll
    for (int j = 0; j < 4; j++)
        t[ty + j*8][tx] = s[(long long)(r0 + ty + j*8)*C + c0 + tx];
    __syncthreads();
#pragma unroll
    for (int j = 0; j < 4; j++) {
        long long o = (long long)b*sOut + (long long)(c0 + ty + j*8)*R + r0 + tx;
        bf16 h, l; split2(t[tx][ty + j*8], h, l);
        hi[o] = h; lo[o] = l;
    }
}

__global__ void rope_q_kernel(const float* __restrict__ cqr, const float* __restrict__ fc,
                              const float* __restrict__ fs, bf16* __restrict__ QHh,
                              bf16* __restrict__ QHl)
{
    int idx = blockIdx.x*256 + threadIdx.x;
    if (idx >= BATCH*SEQ*NHEAD*32) return;
    int j = idx & 31, h = (idx >> 5) & 15, bt = idx >> 9;
    int t = bt & (SEQ-1);
    long long src = (long long)bt*(NHEAD*DHR) + h*DHR + 2*j;
    float re = cqr[src], im = cqr[src+1];
    float c = fc[t*32 + j], s = fs[t*32 + j];
    long long row = (long long)bt*(NHEAD*QKD) + h*QKD + 128 + 2*j;
    bf16 h0,l0,h1,l1;
    split2(re*c - im*s, h0, l0); split2(re*s + im*c, h1, l1);
    QHh[row] = h0; QHl[row] = l0; QHh[row+1] = h1; QHl[row+1] = l1;
}

__global__ void rope_k_kernel(const float* __restrict__ ckr, const float* __restrict__ fc,
                              const float* __restrict__ fs, bf16* __restrict__ KHh,
                              bf16* __restrict__ KHl)
{
    int idx = blockIdx.x*256 + threadIdx.x;
    if (idx >= BATCH*SEQ*32) return;
    int j = idx & 31, bt = idx >> 5, t = bt & (SEQ-1);
    long long src = (long long)bt*DHR + 2*j;
    float re = ckr[src], im = ckr[src+1];
    float c = fc[t*32 + j], s = fs[t*32 + j];
    bf16 h0,l0,h1,l1;
    split2(re*c - im*s, h0, l0); split2(re*s + im*c, h1, l1);
    long long base = (long long)bt*(NHEAD*QKD) + 128 + 2*j;
#pragma unroll
    for (int h = 0; h < NHEAD; h++) {
        long long row = base + h*QKD;
        KHh[row] = h0; KHl[row] = l0; KHh[row+1] = h1; KHl[row+1] = l1;
    }
}

// ---- launch ----
extern "C" void kernel_launch(void* const* d_in, const int* in_sizes, int n_in,
                              void* d_out, int out_size)
{
    const float* x     = (const float*)d_in[0];
    const float* W_dq  = (const float*)d_in[1];
    const float* W_uq  = (const float*)d_in[2];
    const float* W_dkv = (const float*)d_in[3];
    const float* W_uk  = (const float*)d_in[4];
    const float* W_uv  = (const float*)d_in[5];
    const float* W_o   = (const float*)d_in[6];
    const float* W_qr  = (const float*)d_in[7];
    const float* W_kr  = (const float*)d_in[8];
    const float* fc    = (const float*)d_in[9];
    const float* fs    = (const float*)d_in[10];
    float* out = (float*)d_out;

    cudaFuncSetAttribute(gemm3, cudaFuncAttributeMaxDynamicSharedMemorySize, SMEM_GEMM);
    cudaFuncSetAttribute(flash_pv, cudaFuncAttributeMaxDynamicSharedMemorySize, SMEM_FLASH);

#define SYM(v, s) cudaGetSymbolAddress((void**)&v, s)
    bf16 *xh,*xl,*dqh,*dql,*dkvh,*dkvl,*krh,*krl,*qrh,*qrl,*uqTh,*uqTl,*ukh,*ukl;
    bf16 *woh,*wol,*uvTh,*uvTl,*Zh,*Zl,*cqh,*cql,*KCh,*KCl,*QHh,*QHl,*KHh,*KHl;
    bf16 *vTh,*vTl;
    float *cqr,*ckr;
    SYM(xh,g_x_h); SYM(xl,g_x_l); SYM(dqh,g_Wdq_h); SYM(dql,g_Wdq_l);
    SYM(dkvh,g_Wdkv_h); SYM(dkvl,g_Wdkv_l); SYM(krh,g_Wkr_h); SYM(krl,g_Wkr_l);
    SYM(qrh,g_Wqr_h); SYM(qrl,g_Wqr_l); SYM(uqTh,g_WuqT_h); SYM(uqTl,g_WuqT_l);
    SYM(ukh,g_Wuk_h); SYM(ukl,g_Wuk_l);
    SYM(woh,g_Wo_h); SYM(wol,g_Wo_l); SYM(uvTh,g_WuvT_h); SYM(uvTl,g_WuvT_l);
    SYM(Zh,g_Z_h); SYM(Zl,g_Z_l); SYM(cqh,g_cq_h); SYM(cql,g_cq_l);
    SYM(KCh,g_KC_h); SYM(KCl,g_KC_l); SYM(QHh,g_QH_h); SYM(QHl,g_QH_l);
    SYM(KHh,g_KH_h); SYM(KHl,g_KH_l);
    SYM(vTh,g_vT_h); SYM(vTl,g_vT_l);
    SYM(cqr,g_cqr); SYM(ckr,g_ckr);
#undef SYM

    auto SC = [](const float* s, bf16* h, bf16* l, long long n) {
        split_copy4<<<(unsigned)((n/4 + 255)/256), 256>>>(
            (const float4*)s, (__nv_bfloat162*)h, (__nv_bfloat162*)l, n/4);
    };
    dim3 blk(256);
    const int LDH = NHEAD * QKD;                   // 3072
    const long long SB = (long long)SEQ * LDH;     // per-batch stride

    // ---- splits / transposes ----
    SC(x, xh, xl, 8388608);
    SC(W_dq, dqh, dql, 1048576);
    SC(W_dkv, dkvh, dkvl, 1048576);
    SC(W_kr, krh, krl, 131072);
    SC(W_qr, qrh, qrl, 524288);
    SC(W_uk, ukh, ukl, 1048576);
    SC(W_o, woh, wol, 4194304);
    split_transpose<<<dim3(64, 16, 1), dim3(32, 8)>>>(W_uq, uqTh, uqTl, 512, 2048, 0, 0);
    split_transpose<<<dim3(16, 64, 1), dim3(32, 8)>>>(W_uv, uvTh, uvTl, 2048, 512, 0, 0);

    // ---- GEMMs ----
    gemm3<<<dim3(4, 32, 1), blk, SMEM_GEMM>>>(xh, xl, 0, 0, 2048, dqh, dql, 0, 0, 2048,
        nullptr, cqh, cql, 0, 0, 512, 4096, 512, 2048, 1, 1, 0);
    gemm3<<<dim3(4, 32, 1), blk, SMEM_GEMM>>>(xh, xl, 0, 0, 2048, dkvh, dkvl, 0, 0, 2048,
        nullptr, KCh, KCl, 0, 0, 576, 4096, 512, 2048, 1, 1, 0);
    gemm3<<<dim3(4, 16, 1), blk, SMEM_GEMM>>>(woh, wol, 0, 0, 2048, uvTh, uvTl, 0, 0, 2048,
        nullptr, Zh, Zl, 0, 0, 512, 2048, 512, 2048, 1, 1, 0);
    gemm3<<<dim3(8, 1, 64), blk, SMEM_GEMM>>>(Zh, Zl, 0, 65536, 512,
        KCh, KCl, 589824, 0, 576,
        nullptr, vTh, vTl, 2097152, 131072, 1024, 128, 1024, 512, 16, 1, 0);
    gemm3<<<dim3(1, 32, 1), blk, SMEM_GEMM>>>(xh, xl, 0, 0, 2048, krh, krl, 0, 0, 2048,
        ckr, nullptr, nullptr, 0, 0, 64, 4096, 64, 2048, 1, 0, 0);
    gemm3<<<dim3(8, 32, 1), blk, SMEM_GEMM>>>(cqh, cql, 0, 0, 512, qrh, qrl, 0, 0, 512,
        cqr, nullptr, nullptr, 0, 0, 1024, 4096, 1024, 512, 1, 0, 0);
    gemm3<<<dim3(16, 32, 1), blk, SMEM_GEMM>>>(cqh, cql, 0, 0, 512, uqTh, uqTl, 0, 0, 512,
        nullptr, QHh, QHl, 0, 0, LDH, 4096, 2048, 512, 1, 2, 0);
    gemm3<<<dim3(1, 8, 64), blk, SMEM_GEMM>>>(KCh, KCl, 589824, 0, 576,
        ukh, ukl, 0, 65536, 512,
        nullptr, KHh, KHl, SB, QKD, LDH, 1024, 128, 512, 16, 1, 0);
    rope_q_kernel<<<(BATCH*SEQ*NHEAD*32 + 255)/256, 256>>>(cqr, fc, fs, QHh, QHl);
    rope_k_kernel<<<(BATCH*SEQ*32 + 255)/256, 256>>>(ckr, fc, fs, KHh, KHl);

    // ---- flash attention (S + softmax + PV fused) ----
    flash_pv<<<dim3(8, 64, 1), blk, SMEM_FLASH>>>(QHh, QHl, KHh, KHl, vTh, vTl, out);
}

// round 14
// speedup vs baseline: 3.0543x; 1.0174x over previous
#include <cuda_runtime.h>
#include <cuda_bf16.h>
#include <stdint.h>
#include <math.h>

using bf16 = __nv_bfloat16;

constexpr int BATCH = 4, SEQ = 1024, CDIM = 2048, NHEAD = 16, HS = 128;
constexpr int NLQ = 512, NLKV = 512, DHR = 64, QKD = 192;   // per-head [k_h | rope]

// ---- scratch (hi/lo bf16 split pairs) ----
__device__ __align__(128) bf16 g_x_h[8388608],   g_x_l[8388608];
__device__ __align__(128) bf16 g_Wdq_h[1048576], g_Wdq_l[1048576];
__device__ __align__(128) bf16 g_Wckv_h[1179648],g_Wckv_l[1179648]; // [Wdkv(512)|Wkr(64)]x2048
__device__ __align__(128) bf16 g_Wqr_h[524288],  g_Wqr_l[524288];
__device__ __align__(128) bf16 g_WuqT_h[1048576],g_WuqT_l[1048576];  // (2048x512)
__device__ __align__(128) bf16 g_Wuk_h[1048576], g_Wuk_l[1048576];   // raw [h][128][512]
__device__ __align__(128) bf16 g_Wo_h[4194304],  g_Wo_l[4194304];
__device__ __align__(128) bf16 g_WuvT_h[1048576],g_WuvT_l[1048576];
__device__ __align__(128) bf16 g_Z_h[1048576],   g_Z_l[1048576];
__device__ __align__(128) bf16 g_cq_h[2097152],  g_cq_l[2097152];
__device__ __align__(128) bf16 g_KC_h[2359296],  g_KC_l[2359296];    // [b][s][576] c_kv|c_kr
__device__ __align__(128) bf16 g_QH_h[12582912], g_QH_l[12582912];   // [b][t][h][192]
__device__ __align__(128) bf16 g_KH_h[12582912], g_KH_l[12582912];   // [b][s][h][192]
__device__ __align__(128) bf16 g_vT_h[8388608],  g_vT_l[8388608];    // [b,h] 128x1024
__device__ __align__(128) float g_cqr[4194304];

// ---- helpers ----
__device__ __forceinline__ void split2(float v, bf16& h, bf16& l) {
    h = __float2bfloat16(v);
    l = __float2bfloat16(v - __bfloat162float(h));
}
__device__ __forceinline__ uint32_t packbf2(bf16 a, bf16 b) {
    __nv_bfloat162 p = __halves2bfloat162(a, b);
    return *reinterpret_cast<uint32_t*>(&p);
}
__device__ __forceinline__ void ldsm4(uint32_t* r, uint32_t addr) {
    asm volatile("ldmatrix.sync.aligned.m8n8.x4.shared.b16 {%0,%1,%2,%3}, [%4];"
        : "=r"(r[0]), "=r"(r[1]), "=r"(r[2]), "=r"(r[3]) : "r"(addr));
}
__device__ __forceinline__ void mma16816(float* d, const uint32_t* a, const uint32_t* b) {
    asm volatile("mma.sync.aligned.m16n8k16.row.col.f32.bf16.bf16.f32 "
        "{%0,%1,%2,%3}, {%4,%5,%6,%7}, {%8,%9}, {%0,%1,%2,%3};"
        : "+f"(d[0]), "+f"(d[1]), "+f"(d[2]), "+f"(d[3])
        : "r"(a[0]), "r"(a[1]), "r"(a[2]), "r"(a[3]), "r"(b[0]), "r"(b[1]));
}
__device__ __forceinline__ uint32_t swz(uint32_t tile_base, int r, int kb16) {
    uint32_t byte = (uint32_t)(r * 128 + kb16 * 16);
    return tile_base + (byte ^ ((byte >> 3) & 0x70));
}
#define CPA16(dst, src) \
    asm volatile("cp.async.cg.shared.global [%0], [%1], 16;"::"r"(dst),"l"(src):"memory")
#define CPA_COMMIT() asm volatile("cp.async.commit_group;" ::: "memory")
#define CPA_WAIT(n)  asm volatile("cp.async.wait_group %0;" :: "n"(n) : "memory")

// ---- HMMA batched GEMM: D = (Ah+Al) @ (Bh+Bl)^T (3-term split) ----
constexpr int BM = 128, BN = 128, BKC = 64;
constexpr int TILE_B = 16384;
constexpr int BUF_B  = 4 * TILE_B;
constexpr int NSTAGE = 3;
constexpr int SMEM_GEMM = NSTAGE * BUF_B;     // 192 KB

__global__ __launch_bounds__(256, 1)
void gemm3(const bf16* __restrict__ Ah, const bf16* __restrict__ Al,
           long long sA0, long long sA1, int lda,
           const bf16* __restrict__ Bh, const bf16* __restrict__ Bl,
           long long sB0, long long sB1, int ldb,
           float* __restrict__ C, bf16* __restrict__ Chi, bf16* __restrict__ Clo,
           long long sC0, long long sC1, int ldc,
           int M, int N, int K, int zdiv, int mode, int causal)
{
    const int m0 = blockIdx.y * BM, n0 = blockIdx.x * BN;
    if (causal == 1 && n0 >= m0 + BM) return;
    const int z = blockIdx.z, z0 = z / zdiv, z1 = z % zdiv;
    Ah += z0*sA0 + z1*sA1;  Al += z0*sA0 + z1*sA1;
    Bh += z0*sB0 + z1*sB1;  Bl += z0*sB0 + z1*sB1;
    const long long coff = z0*sC0 + z1*sC1;

    extern __shared__ __align__(1024) char smem[];
    const uint32_t sb = (uint32_t)__cvta_generic_to_shared(smem);
    const int tid = threadIdx.x, wid = tid >> 5, lane = tid & 31;
    const int wm = (wid & 3) * 32;
    const int wn = (wid >> 2) * 64;

    const int Keff = (causal == 2) ? min(K, m0 + BM) : K;
    const int nch = Keff / BKC;

    auto fill = [&](int buf, int k0) {
        const uint32_t bb = sb + buf * BUF_B;
#pragma unroll
        for (int it = 0; it < 16; it++) {
            int idx = tid + it * 256;
            int tile = idx >> 10, r = (idx >> 3) & 127, c16 = idx & 7;
            uint32_t byte = (uint32_t)(r*128 + c16*16);
            uint32_t dst = bb + tile*TILE_B + (byte ^ ((byte >> 3) & 0x70));
            if (tile < 2) {
                const bf16* src = (tile == 0 ? Ah : Al) + (long long)(m0 + r)*lda + k0 + c16*8;
                CPA16(dst, src);
            } else if (n0 + r < N) {
                const bf16* src = (tile == 2 ? Bh : Bl) + (long long)(n0 + r)*ldb + k0 + c16*8;
                CPA16(dst, src);
            } else {
                asm volatile("st.shared.v4.b32 [%0], {%1,%1,%1,%1};"::"r"(dst),"r"(0u):"memory");
            }
        }
        CPA_COMMIT();
    };

    float acc[2][8][4];
#pragma unroll
    for (int i = 0; i < 2; i++)
#pragma unroll
        for (int j = 0; j < 8; j++)
#pragma unroll
            for (int q = 0; q < 4; q++) acc[i][j][q] = 0.f;

    fill(0, 0);
    if (nch > 1) fill(1, BKC);

    for (int ci = 0; ci < nch; ci++) {
        if (ci + 1 < nch) { CPA_WAIT(1); } else { CPA_WAIT(0); }
        __syncthreads();
        if (ci + 2 < nch) fill((ci + 2) % NSTAGE, (ci + 2) * BKC);

        const uint32_t bb = sb + (ci % NSTAGE) * BUF_B;
        const uint32_t tAh = bb, tAl = bb + TILE_B, tBh = bb + 2*TILE_B, tBl = bb + 3*TILE_B;
        const int arow = wm + (lane & 15);
        const int brow = wn + (lane & 7) + ((lane >> 4) << 3);

#pragma unroll
        for (int ks = 0; ks < 4; ks++) {
            const int akb = ks*2 + (lane >> 4);
            const int bkb = ks*2 + ((lane >> 3) & 1);
            uint32_t ah[2][4], al[2][4], bh[4][4], bl[4][4];
#pragma unroll
            for (int mi = 0; mi < 2; mi++) {
                ldsm4(ah[mi], swz(tAh, arow + mi*16, akb));
                ldsm4(al[mi], swz(tAl, arow + mi*16, akb));
            }
#pragma unroll
            for (int nj = 0; nj < 4; nj++) {
                ldsm4(bh[nj], swz(tBh, brow + nj*16, bkb));
                ldsm4(bl[nj], swz(tBl, brow + nj*16, bkb));
            }
#pragma unroll
            for (int mi = 0; mi < 2; mi++)
#pragma unroll
                for (int nj = 0; nj < 4; nj++) {
                    mma16816(acc[mi][2*nj],   ah[mi], &bh[nj][0]);
                    mma16816(acc[mi][2*nj+1], ah[mi], &bh[nj][2]);
                    mma16816(acc[mi][2*nj],   ah[mi], &bl[nj][0]);
                    mma16816(acc[mi][2*nj+1], ah[mi], &bl[nj][2]);
                    mma16816(acc[mi][2*nj],   al[mi], &bh[nj][0]);
                    mma16816(acc[mi][2*nj+1], al[mi], &bh[nj][2]);
                }
        }
        // NOTE: no trailing barrier needed — a warp reaches the next top barrier
        // only after all its MMAs (hence ldsm reads) are issued; the stage being
        // overwritten next is 3 chunks ahead.
    }

#pragma unroll
    for (int mi = 0; mi < 2; mi++) {
        const int r0 = m0 + wm + mi*16 + (lane >> 2);
#pragma unroll
        for (int nb = 0; nb < 8; nb++) {
            const int c = n0 + wn + nb*8 + (lane & 3)*2;
            if (c < N) {
                const float* a = acc[mi][nb];
                const int cc = (mode == 2) ? ((c >> 7) * QKD + (c & 127)) : c;
                const long long off0 = coff + (long long)r0 * ldc + cc;
                const long long off1 = off0 + 8LL * ldc;
                if (mode == 0) {
                    *(float2*)(C + off0) = make_float2(a[0], a[1]);
                    *(float2*)(C + off1) = make_float2(a[2], a[3]);
                } else {
                    bf16 h0,l0,h1,l1;
                    split2(a[0],h0,l0); split2(a[1],h1,l1);
                    *(__nv_bfloat162*)(Chi+off0) = __halves2bfloat162(h0,h1);
                    *(__nv_bfloat162*)(Clo+off0) = __halves2bfloat162(l0,l1);
                    split2(a[2],h0,l0); split2(a[3],h1,l1);
                    *(__nv_bfloat162*)(Chi+off1) = __halves2bfloat162(h0,h1);
                    *(__nv_bfloat162*)(Clo+off1) = __halves2bfloat162(l0,l1);
                }
            }
        }
    }
}

// ---- flash attention: S-MMA + online softmax + P@vT, one kernel ----
constexpr int FL_Q  = 0;          // 6 x 16384
constexpr int FL_KH = 98304;      // 6 x 8192
constexpr int FL_VT = 147456;     // 2 x 16384
constexpr int FL_P  = 180224;     // 2 x 16384
constexpr int FL_ST = 212992;     // stats (floats)
constexpr int SMEM_FLASH = 212992 + 7*512;

__global__ __launch_bounds__(256, 1)
void flash_pv(const bf16* __restrict__ QHh_, const bf16* __restrict__ QHl_,
              const bf16* __restrict__ KHh_, const bf16* __restrict__ KHl_,
              const bf16* __restrict__ vTh_, const bf16* __restrict__ vTl_,
              float* __restrict__ out)
{
    const int bh = blockIdx.y, b = bh >> 4, h = bh & 15;
    const int m0 = (gridDim.x - 1 - blockIdx.x) * 128;   // heavy tiles first
    const long long qkbase = (long long)b*(1024*3072) + h*QKD;
    const bf16* vTh = vTh_ + (long long)bh * 131072;
    const bf16* vTl = vTl_ + (long long)bh * 131072;
    out += (long long)b*(1024*2048) + (long long)m0*2048 + h*128;

    extern __shared__ __align__(1024) char smem[];
    const uint32_t sb = (uint32_t)__cvta_generic_to_shared(smem);
    float* mxA  = (float*)(smem + FL_ST);
    float* mxB  = mxA + 128;
    float* sA   = mxA + 256;
    float* sB   = mxA + 384;
    float* fbuf = mxA + 512;
    float* mrow = mxA + 640;
    float* srow = mxA + 768;

    const int tid = threadIdx.x, wid = tid >> 5, lane = tid & 31;
    const int wm  = (wid & 3) * 32;
    const int wns = (wid >> 2) * 32;
    const int wn  = (wid >> 2) * 64;
    const float scale = 0.07216878364870322f;   // 1/sqrt(192)

    auto QT = [&](int kt, int hl){ return sb + FL_Q  + (uint32_t)(kt*2+hl)*16384u; };
    auto KT = [&](int kt, int hl){ return sb + FL_KH + (uint32_t)(kt*2+hl)*8192u; };
    auto VTb = [&](int hl){ return sb + FL_VT + (uint32_t)hl*16384u; };
    auto PTb = [&](int hl){ return sb + FL_P  + (uint32_t)hl*16384u; };

    if (tid < 128) { mrow[tid] = -1e30f; srow[tid] = 0.f; }

    auto fill_kh = [&](int s0) {
#pragma unroll
        for (int it = 0; it < 12; it++) {
            int idx = tid + it*256;
            int tile = idx >> 9, r = (idx >> 3) & 63, c16 = idx & 7;
            int kt = tile >> 1, hl = tile & 1;
            uint32_t byte = (uint32_t)(r*128 + c16*16);
            uint32_t dst = KT(kt,hl) + (byte ^ ((byte>>3)&0x70));
            const bf16* src = (hl ? KHl_ : KHh_) + qkbase + (long long)(s0+r)*3072 + kt*64 + c16*8;
            CPA16(dst, src);
        }
    };
    auto fill_vt = [&](int s0) {
#pragma unroll
        for (int it = 0; it < 8; it++) {
            int idx = tid + it*256;
            int hl = idx >> 10, r = (idx >> 3) & 127, c16 = idx & 7;
            uint32_t byte = (uint32_t)(r*128 + c16*16);
            uint32_t dst = VTb(hl) + (byte ^ ((byte>>3)&0x70));
            const bf16* src = (hl ? vTl : vTh) + r*1024 + s0 + c16*8;
            CPA16(dst, src);
        }
    };

#pragma unroll
    for (int it = 0; it < 24; it++) {
        int idx = tid + it*256;
        int tile = idx >> 10, r = (idx >> 3) & 127, c16 = idx & 7;
        int kt = tile >> 1, hl = tile & 1;
        uint32_t byte = (uint32_t)(r*128 + c16*16);
        uint32_t dst = QT(kt,hl) + (byte ^ ((byte>>3)&0x70));
        const bf16* src = (hl ? QHl_ : QHh_) + qkbase + (long long)(m0+r)*3072 + kt*64 + c16*8;
        CPA16(dst, src);
    }
    fill_kh(0);
    CPA_COMMIT();
    fill_vt(0);
    CPA_COMMIT();

    float acc[2][8][4];
#pragma unroll
    for (int i = 0; i < 2; i++)
#pragma unroll
        for (int j = 0; j < 8; j++)
#pragma unroll
            for (int q = 0; q < 4; q++) acc[i][j][q] = 0.f;

    const int nch = m0/64 + 2;
    for (int ci = 0; ci < nch; ci++) {
        const int s0 = ci * 64;
        CPA_WAIT(1);
        __syncthreads();

        // ---- S-MMA ----
        float sacc[2][4][4];
#pragma unroll
        for (int i = 0; i < 2; i++)
#pragma unroll
            for (int j = 0; j < 4; j++)
#pragma unroll
                for (int q = 0; q < 4; q++) sacc[i][j][q] = 0.f;

        const int arow = wm + (lane & 15);
        const int brs = wns + (lane & 7) + ((lane >> 4) << 3);
#pragma unroll
        for (int kt = 0; kt < 3; kt++) {
#pragma unroll
            for (int ks = 0; ks < 4; ks++) {
                const int akb = ks*2 + (lane >> 4);
                const int bkb = ks*2 + ((lane >> 3) & 1);
                uint32_t ah[2][4], al[2][4], bhf[2][4], blf[2][4];
#pragma unroll
                for (int mi = 0; mi < 2; mi++) {
                    ldsm4(ah[mi], swz(QT(kt,0), arow + mi*16, akb));
                    ldsm4(al[mi], swz(QT(kt,1), arow + mi*16, akb));
                }
#pragma unroll
                for (int nj = 0; nj < 2; nj++) {
                    ldsm4(bhf[nj], swz(KT(kt,0), brs + nj*16, bkb));
                    ldsm4(blf[nj], swz(KT(kt,1), brs + nj*16, bkb));
                }
#pragma unroll
                for (int mi = 0; mi < 2; mi++)
#pragma unroll
                    for (int nj = 0; nj < 2; nj++) {
                        mma16816(sacc[mi][2*nj],   ah[mi], &bhf[nj][0]);
                        mma16816(sacc[mi][2*nj+1], ah[mi], &bhf[nj][2]);
                        mma16816(sacc[mi][2*nj],   ah[mi], &blf[nj][0]);
                        mma16816(sacc[mi][2*nj+1], ah[mi], &blf[nj][2]);
                        mma16816(sacc[mi][2*nj],   al[mi], &bhf[nj][0]);
                        mma16816(sacc[mi][2*nj+1], al[mi], &bhf[nj][2]);
                    }
            }
        }

        // ---- mask + scale + chunk row-max ----
#pragma unroll
        for (int mi = 0; mi < 2; mi++)
#pragma unroll
            for (int rh = 0; rh < 2; rh++) {
                const int rl = wm + mi*16 + (lane >> 2) + rh*8;
                const int rg = m0 + rl;
                float mx = -1e30f;
#pragma unroll
                for (int nb = 0; nb < 4; nb++) {
                    const int cg = s0 + wns + nb*8 + (lane & 3)*2;
                    float* a = sacc[mi][nb];
                    float v0 = (cg   <= rg) ? a[rh*2+0]*scale : -1e30f;
                    float v1 = (cg+1 <= rg) ? a[rh*2+1]*scale : -1e30f;
                    a[rh*2+0] = v0; a[rh*2+1] = v1;
                    mx = fmaxf(mx, fmaxf(v0, v1));
                }
                mx = fmaxf(mx, __shfl_xor_sync(0xffffffffu, mx, 1));
                mx = fmaxf(mx, __shfl_xor_sync(0xffffffffu, mx, 2));
                if ((lane & 3) == 0) ((wid >> 2) ? mxB : mxA)[rl] = mx;
            }
        __syncthreads();
        if (ci + 1 < nch) fill_kh(s0 + 64);
        CPA_COMMIT();

        // ---- online softmax ----
        float fv[2][2], nmv[2][2];
#pragma unroll
        for (int mi = 0; mi < 2; mi++)
#pragma unroll
            for (int rh = 0; rh < 2; rh++) {
                const int rl = wm + mi*16 + (lane >> 2) + rh*8;
                const float nm = fmaxf(mrow[rl], fmaxf(mxA[rl], mxB[rl]));
                const float f  = __expf(mrow[rl] - nm);
                nmv[mi][rh] = nm; fv[mi][rh] = f;
                float ps = 0.f;
#pragma unroll
                for (int nb = 0; nb < 4; nb++) {
                    const float* a = sacc[mi][nb];
                    float e0 = __expf(a[rh*2+0] - nm);
                    float e1 = __expf(a[rh*2+1] - nm);
                    ps += e0 + e1;
                    bf16 h0,l0,h1,l1;
                    split2(e0,h0,l0); split2(e1,h1,l1);
                    uint32_t byte = (uint32_t)(rl*128 + (wns + nb*8 + (lane & 3)*2)*2);
                    uint32_t sw = byte ^ ((byte>>3)&0x70);
                    asm volatile("st.shared.b32 [%0], %1;"::"r"(PTb(0)+sw),"r"(packbf2(h0,h1)):"memory");
                    asm volatile("st.shared.b32 [%0], %1;"::"r"(PTb(1)+sw),"r"(packbf2(l0,l1)):"memory");
                }
                ps += __shfl_xor_sync(0xffffffffu, ps, 1);
                ps += __shfl_xor_sync(0xffffffffu, ps, 2);
                if ((lane & 3) == 0) {
                    ((wid >> 2) ? sB : sA)[rl] = ps;
                    if ((wid >> 2) == 0) fbuf[rl] = f;
                }
            }
        __syncthreads();

        // ---- update running stats; rescale out-acc ----
        if ((lane & 3) == 0 && (wid >> 2) == 0) {
#pragma unroll
            for (int mi = 0; mi < 2; mi++)
#pragma unroll
                for (int rh = 0; rh < 2; rh++) {
                    const int rl = wm + mi*16 + (lane >> 2) + rh*8;
                    srow[rl] = srow[rl]*fv[mi][rh] + sA[rl] + sB[rl];
                    mrow[rl] = nmv[mi][rh];
                }
        }
#pragma unroll
        for (int mi = 0; mi < 2; mi++) {
            const int r0 = wm + mi*16 + (lane >> 2);
            const float fa = fbuf[r0], fb = fbuf[r0+8];
#pragma unroll
            for (int nb = 0; nb < 8; nb++) {
                acc[mi][nb][0]*=fa; acc[mi][nb][1]*=fa;
                acc[mi][nb][2]*=fb; acc[mi][nb][3]*=fb;
            }
        }

        CPA_WAIT(1);
        __syncthreads();

        // ---- PV MMA ----
        const int brow = wn + (lane & 7) + ((lane >> 4) << 3);
#pragma unroll
        for (int ks = 0; ks < 4; ks++) {
            const int akb = ks*2 + (lane >> 4);
            const int bkb = ks*2 + ((lane >> 3) & 1);
            uint32_t ah[2][4], al[2][4], bhf[4][4], blf[4][4];
#pragma unroll
            for (int mi = 0; mi < 2; mi++) {
                ldsm4(ah[mi], swz(PTb(0), arow + mi*16, akb));
                ldsm4(al[mi], swz(PTb(1), arow + mi*16, akb));
            }
#pragma unroll
            for (int nj = 0; nj < 4; nj++) {
                ldsm4(bhf[nj], swz(VTb(0), brow + nj*16, bkb));
                ldsm4(blf[nj], swz(VTb(1), brow + nj*16, bkb));
            }
#pragma unroll
            for (int mi = 0; mi < 2; mi++)
#pragma unroll
                for (int nj = 0; nj < 4; nj++) {
                    mma16816(acc[mi][2*nj],   ah[mi], &bhf[nj][0]);
                    mma16816(acc[mi][2*nj+1], ah[mi], &bhf[nj][2]);
                    mma16816(acc[mi][2*nj],   ah[mi], &blf[nj][0]);
                    mma16816(acc[mi][2*nj+1], ah[mi], &blf[nj][2]);
                    mma16816(acc[mi][2*nj],   al[mi], &bhf[nj][0]);
                    mma16816(acc[mi][2*nj+1], al[mi], &bhf[nj][2]);
                }
        }
        __syncthreads();
        if (ci + 1 < nch) fill_vt(s0 + 64);
        CPA_COMMIT();
    }

    // ---- epilogue ----
    __syncthreads();
#pragma unroll
    for (int mi = 0; mi < 2; mi++) {
        const int r0 = wm + mi*16 + (lane >> 2);
        const float ia = 1.0f / srow[r0], ib = 1.0f / srow[r0+8];
#pragma unroll
        for (int nb = 0; nb < 8; nb++) {
            const int c = wn + nb*8 + (lane & 3)*2;
            const float* a = acc[mi][nb];
            *(float2*)(out + (long long)r0*2048 + c)     = make_float2(a[0]*ia, a[1]*ia);
            *(float2*)(out + (long long)(r0+8)*2048 + c) = make_float2(a[2]*ib, a[3]*ib);
        }
    }
}

// ---- prep kernels ----
__global__ void split_copy4(const float4* __restrict__ s, __nv_bfloat162* __restrict__ h,
                            __nv_bfloat162* __restrict__ l, long long n4)
{
    long long i = (long long)blockIdx.x*256 + threadIdx.x;
    if (i >= n4) return;
    float4 v = s[i];
    bf16 h0,l0,h1,l1;
    split2(v.x,h0,l0); split2(v.y,h1,l1);
    h[2*i]   = __halves2bfloat162(h0,h1);
    l[2*i]   = __halves2bfloat162(l0,l1);
    split2(v.z,h0,l0); split2(v.w,h1,l1);
    h[2*i+1] = __halves2bfloat162(h0,h1);
    l[2*i+1] = __halves2bfloat162(l0,l1);
}

__global__ void split_transpose(const float* __restrict__ src, bf16* __restrict__ hi,
                                bf16* __restrict__ lo, int R, int C,
                                long long sIn, long long sOut)
{
    __shared__ float t[32][33];
    int b = blockIdx.z, c0 = blockIdx.x*32, r0 = blockIdx.y*32;
    int tx = threadIdx.x, ty = threadIdx.y;
    const float* s = src + (long long)b*sIn;
#pragma unroll
    for (int j = 0; j < 4; j++)
        t[ty + j*8][tx] = s[(long long)(r0 + ty + j*8)*C + c0 + tx];
    __syncthreads();
#pragma unroll
    for (int j = 0; j < 4; j++) {
        long long o = (long long)b*sOut + (long long)(c0 + ty + j*8)*R + r0 + tx;
        bf16 h, l; split2(t[tx][ty + j*8], h, l);
        hi[o] = h; lo[o] = l;
    }
}

__global__ void rope_q_kernel(const float* __restrict__ cqr, const float* __restrict__ fc,
                              const float* __restrict__ fs, bf16* __restrict__ QHh,
                              bf16* __restrict__ QHl)
{
    int idx = blockIdx.x*256 + threadIdx.x;
    if (idx >= BATCH*SEQ*NHEAD*32) return;
    int j = idx & 31, h = (idx >> 5) & 15, bt = idx >> 9;
    int t = bt & (SEQ-1);
    long long src = (long long)bt*(NHEAD*DHR) + h*DHR + 2*j;
    float re = cqr[src], im = cqr[src+1];
    float c = fc[t*32 + j], s = fs[t*32 + j];
    long long row = (long long)bt*(NHEAD*QKD) + h*QKD + 128 + 2*j;
    bf16 h0,l0,h1,l1;
    split2(re*c - im*s, h0, l0); split2(re*s + im*c, h1, l1);
    QHh[row] = h0; QHl[row] = l0; QHh[row+1] = h1; QHl[row+1] = l1;
}

// rope k: c_kr lives in KC cols [512..576) (hi+lo) -> KH[b][s][h][128+2j] for all h
__global__ void rope_k_kernel(const bf16* __restrict__ KCh, const bf16* __restrict__ KCl,
                              const float* __restrict__ fc, const float* __restrict__ fs,
                              bf16* __restrict__ KHh, bf16* __restrict__ KHl)
{
    int idx = blockIdx.x*256 + threadIdx.x;
    if (idx >= BATCH*SEQ*32) return;
    int j = idx & 31, bt = idx >> 5, t = bt & (SEQ-1);
    long long src = (long long)bt*576 + 512 + 2*j;
    float re = __bfloat162float(KCh[src])   + __bfloat162float(KCl[src]);
    float im = __bfloat162float(KCh[src+1]) + __bfloat162float(KCl[src+1]);
    float c = fc[t*32 + j], s = fs[t*32 + j];
    bf16 h0,l0,h1,l1;
    split2(re*c - im*s, h0, l0); split2(re*s + im*c, h1, l1);
    long long base = (long long)bt*(NHEAD*QKD) + 128 + 2*j;
#pragma unroll
    for (int h = 0; h < NHEAD; h++) {
        long long row = base + h*QKD;
        KHh[row] = h0; KHl[row] = l0; KHh[row+1] = h1; KHl[row+1] = l1;
    }
}

// ---- launch ----
extern "C" void kernel_launch(void* const* d_in, const int* in_sizes, int n_in,
                              void* d_out, int out_size)
{
    const float* x     = (const float*)d_in[0];
    const float* W_dq  = (const float*)d_in[1];
    const float* W_uq  = (const float*)d_in[2];
    const float* W_dkv = (const float*)d_in[3];
    const float* W_uk  = (const float*)d_in[4];
    const float* W_uv  = (const float*)d_in[5];
    const float* W_o   = (const float*)d_in[6];
    const float* W_qr  = (const float*)d_in[7];
    const float* W_kr  = (const float*)d_in[8];
    const float* fc    = (const float*)d_in[9];
    const float* fs    = (const float*)d_in[10];
    float* out = (float*)d_out;

    cudaFuncSetAttribute(gemm3, cudaFuncAttributeMaxDynamicSharedMemorySize, SMEM_GEMM);
    cudaFuncSetAttribute(flash_pv, cudaFuncAttributeMaxDynamicSharedMemorySize, SMEM_FLASH);

#define SYM(v, s) cudaGetSymbolAddress((void**)&v, s)
    bf16 *xh,*xl,*dqh,*dql,*ckvh,*ckvl,*qrh,*qrl,*uqTh,*uqTl,*ukh,*ukl;
    bf16 *woh,*wol,*uvTh,*uvTl,*Zh,*Zl,*cqh,*cql,*KCh,*KCl,*QHh,*QHl,*KHh,*KHl;
    bf16 *vTh,*vTl;
    float *cqr;
    SYM(xh,g_x_h); SYM(xl,g_x_l); SYM(dqh,g_Wdq_h); SYM(dql,g_Wdq_l);
    SYM(ckvh,g_Wckv_h); SYM(ckvl,g_Wckv_l);
    SYM(qrh,g_Wqr_h); SYM(qrl,g_Wqr_l); SYM(uqTh,g_WuqT_h); SYM(uqTl,g_WuqT_l);
    SYM(ukh,g_Wuk_h); SYM(ukl,g_Wuk_l);
    SYM(woh,g_Wo_h); SYM(wol,g_Wo_l); SYM(uvTh,g_WuvT_h); SYM(uvTl,g_WuvT_l);
    SYM(Zh,g_Z_h); SYM(Zl,g_Z_l); SYM(cqh,g_cq_h); SYM(cql,g_cq_l);
    SYM(KCh,g_KC_h); SYM(KCl,g_KC_l); SYM(QHh,g_QH_h); SYM(QHl,g_QH_l);
    SYM(KHh,g_KH_h); SYM(KHl,g_KH_l);
    SYM(vTh,g_vT_h); SYM(vTl,g_vT_l);
    SYM(cqr,g_cqr);
#undef SYM

    auto SC = [](const float* s, bf16* h, bf16* l, long long n) {
        split_copy4<<<(unsigned)((n/4 + 255)/256), 256>>>(
            (const float4*)s, (__nv_bfloat162*)h, (__nv_bfloat162*)l, n/4);
    };
    dim3 blk(256);
    const int LDH = NHEAD * QKD;                   // 3072
    const long long SB = (long long)SEQ * LDH;     // per-batch stride

    // ---- splits / transposes ----
    SC(x, xh, xl, 8388608);
    SC(W_dq, dqh, dql, 1048576);
    SC(W_dkv, ckvh, ckvl, 1048576);                     // rows 0-511 of combined
    SC(W_kr, ckvh + 1048576, ckvl + 1048576, 131072);   // rows 512-575
    SC(W_qr, qrh, qrl, 524288);
    SC(W_uk, ukh, ukl, 1048576);
    SC(W_o, woh, wol, 4194304);
    split_transpose<<<dim3(64, 16, 1), dim3(32, 8)>>>(W_uq, uqTh, uqTl, 512, 2048, 0, 0);
    split_transpose<<<dim3(16, 64, 1), dim3(32, 8)>>>(W_uv, uvTh, uvTl, 2048, 512, 0, 0);

    // ---- GEMMs ----
    // c_q = x @ W_dq^T -> split
    gemm3<<<dim3(4, 32, 1), blk, SMEM_GEMM>>>(xh, xl, 0, 0, 2048, dqh, dql, 0, 0, 2048,
        nullptr, cqh, cql, 0, 0, 512, 4096, 512, 2048, 1, 1, 0);
    // [c_kv | c_kr] = x @ Wckv^T -> KC split (N=576, ldc=576)
    gemm3<<<dim3(5, 32, 1), blk, SMEM_GEMM>>>(xh, xl, 0, 0, 2048, ckvh, ckvl, 0, 0, 2048,
        nullptr, KCh, KCl, 0, 0, 576, 4096, 576, 2048, 1, 1, 0);
    // Z = W_o @ W_uv -> split
    gemm3<<<dim3(4, 16, 1), blk, SMEM_GEMM>>>(woh, wol, 0, 0, 2048, uvTh, uvTl, 0, 0, 2048,
        nullptr, Zh, Zl, 0, 0, 512, 2048, 512, 2048, 1, 1, 0);
    // vT[b,h] = Z_h @ c_kv[b]^T -> split (128x1024)
    gemm3<<<dim3(8, 1, 64), blk, SMEM_GEMM>>>(Zh, Zl, 0, 65536, 512,
        KCh, KCl, 589824, 0, 576,
        nullptr, vTh, vTl, 2097152, 131072, 1024, 128, 1024, 512, 16, 1, 0);
    // c_qr = c_q @ W_qr^T -> fp32
    gemm3<<<dim3(8, 32, 1), blk, SMEM_GEMM>>>(cqh, cql, 0, 0, 512, qrh, qrl, 0, 0, 512,
        cqr, nullptr, nullptr, 0, 0, 1024, 4096, 1024, 512, 1, 0, 0);
    // Q = c_q @ WuqT^T -> QH split, col remap, ldc=3072
    gemm3<<<dim3(16, 32, 1), blk, SMEM_GEMM>>>(cqh, cql, 0, 0, 512, uqTh, uqTl, 0, 0, 512,
        nullptr, QHh, QHl, 0, 0, LDH, 4096, 2048, 512, 1, 2, 0);
    // KH[b,h] = c_kv[b] @ W_uk_h^T -> split, ldc=3072
    gemm3<<<dim3(1, 8, 64), blk, SMEM_GEMM>>>(KCh, KCl, 589824, 0, 576,
        ukh, ukl, 0, 65536, 512,
        nullptr, KHh, KHl, SB, QKD, LDH, 1024, 128, 512, 16, 1, 0);
    // RoPE tails
    rope_q_kernel<<<(BATCH*SEQ*NHEAD*32 + 255)/256, 256>>>(cqr, fc, fs, QHh, QHl);
    rope_k_kernel<<<(BATCH*SEQ*32 + 255)/256, 256>>>(KCh, KCl, fc, fs, KHh, KHl);

    // ---- flash attention (S + softmax + PV fused) ----
    flash_pv<<<dim3(8, 64, 1), blk, SMEM_FLASH>>>(QHh, QHl, KHh, KHl, vTh, vTl, out);
}

// round 15
// speedup vs baseline: 3.0590x; 1.0015x over previous
#include <cuda_runtime.h>
#include <cuda_bf16.h>
#include <stdint.h>
#include <math.h>

using bf16 = __nv_bfloat16;

constexpr int BATCH = 4, SEQ = 1024, CDIM = 2048, NHEAD = 16, HS = 128;
constexpr int NLQ = 512, NLKV = 512, DHR = 64, QKD = 192;   // per-head [k_h | rope]

// ---- scratch (hi/lo bf16 split pairs) ----
__device__ __align__(128) bf16 g_x_h[8388608],   g_x_l[8388608];
__device__ __align__(128) bf16 g_Wdq_h[1048576], g_Wdq_l[1048576];
__device__ __align__(128) bf16 g_Wckv_h[1179648],g_Wckv_l[1179648]; // [Wdkv(512)|Wkr(64)]x2048
__device__ __align__(128) bf16 g_Wqr_h[524288],  g_Wqr_l[524288];
__device__ __align__(128) bf16 g_WuqT_h[1048576],g_WuqT_l[1048576];  // (2048x512)
__device__ __align__(128) bf16 g_Wuk_h[1048576], g_Wuk_l[1048576];   // raw [h][128][512]
__device__ __align__(128) bf16 g_Wo_h[4194304],  g_Wo_l[4194304];
__device__ __align__(128) bf16 g_WuvT_h[1048576],g_WuvT_l[1048576];
__device__ __align__(128) bf16 g_Z_h[1048576],   g_Z_l[1048576];
__device__ __align__(128) bf16 g_cq_h[2097152],  g_cq_l[2097152];
__device__ __align__(128) bf16 g_KC_h[2359296],  g_KC_l[2359296];    // [b][s][576] c_kv|c_kr
__device__ __align__(128) bf16 g_QH_h[12582912], g_QH_l[12582912];   // [b][t][h][192]
__device__ __align__(128) bf16 g_KH_h[12582912], g_KH_l[12582912];   // [b][s][h][192]
__device__ __align__(128) bf16 g_vT_h[8388608],  g_vT_l[8388608];    // [b,h] 128x1024
__device__ __align__(128) float g_cqr[4194304];

// ---- helpers ----
__device__ __forceinline__ void split2(float v, bf16& h, bf16& l) {
    h = __float2bfloat16(v);
    l = __float2bfloat16(v - __bfloat162float(h));
}
__device__ __forceinline__ uint32_t packbf2(bf16 a, bf16 b) {
    __nv_bfloat162 p = __halves2bfloat162(a, b);
    return *reinterpret_cast<uint32_t*>(&p);
}
__device__ __forceinline__ void ldsm4(uint32_t* r, uint32_t addr) {
    asm volatile("ldmatrix.sync.aligned.m8n8.x4.shared.b16 {%0,%1,%2,%3}, [%4];"
        : "=r"(r[0]), "=r"(r[1]), "=r"(r[2]), "=r"(r[3]) : "r"(addr));
}
__device__ __forceinline__ void mma16816(float* d, const uint32_t* a, const uint32_t* b) {
    asm volatile("mma.sync.aligned.m16n8k16.row.col.f32.bf16.bf16.f32 "
        "{%0,%1,%2,%3}, {%4,%5,%6,%7}, {%8,%9}, {%0,%1,%2,%3};"
        : "+f"(d[0]), "+f"(d[1]), "+f"(d[2]), "+f"(d[3])
        : "r"(a[0]), "r"(a[1]), "r"(a[2]), "r"(a[3]), "r"(b[0]), "r"(b[1]));
}
__device__ __forceinline__ uint32_t swz(uint32_t tile_base, int r, int kb16) {
    uint32_t byte = (uint32_t)(r * 128 + kb16 * 16);
    return tile_base + (byte ^ ((byte >> 3) & 0x70));
}
#define CPA16(dst, src) \
    asm volatile("cp.async.cg.shared.global [%0], [%1], 16;"::"r"(dst),"l"(src):"memory")
#define CPA_COMMIT() asm volatile("cp.async.commit_group;" ::: "memory")
#define CPA_WAIT(n)  asm volatile("cp.async.wait_group %0;" :: "n"(n) : "memory")

// ---- HMMA batched GEMM: D = (Ah+Al) @ (Bh+Bl)^T (3-term split) ----
constexpr int BM = 128, BN = 128, BKC = 64;
constexpr int TILE_B = 16384;
constexpr int BUF_B  = 4 * TILE_B;
constexpr int NSTAGE = 3;
constexpr int SMEM_GEMM = NSTAGE * BUF_B;     // 192 KB

__global__ __launch_bounds__(256, 1)
void gemm3(const bf16* __restrict__ Ah, const bf16* __restrict__ Al,
           long long sA0, long long sA1, int lda,
           const bf16* __restrict__ Bh, const bf16* __restrict__ Bl,
           long long sB0, long long sB1, int ldb,
           float* __restrict__ C, bf16* __restrict__ Chi, bf16* __restrict__ Clo,
           long long sC0, long long sC1, int ldc,
           int M, int N, int K, int zdiv, int mode, int causal)
{
    const int m0 = blockIdx.y * BM, n0 = blockIdx.x * BN;
    if (causal == 1 && n0 >= m0 + BM) return;
    const int z = blockIdx.z, z0 = z / zdiv, z1 = z % zdiv;
    Ah += z0*sA0 + z1*sA1;  Al += z0*sA0 + z1*sA1;
    Bh += z0*sB0 + z1*sB1;  Bl += z0*sB0 + z1*sB1;
    const long long coff = z0*sC0 + z1*sC1;

    extern __shared__ __align__(1024) char smem[];
    const uint32_t sb = (uint32_t)__cvta_generic_to_shared(smem);
    const int tid = threadIdx.x, wid = tid >> 5, lane = tid & 31;
    const int wm = (wid & 3) * 32;
    const int wn = (wid >> 2) * 64;

    const int Keff = (causal == 2) ? min(K, m0 + BM) : K;
    const int nch = Keff / BKC;

    auto fill = [&](int buf, int k0) {
        const uint32_t bb = sb + buf * BUF_B;
#pragma unroll
        for (int it = 0; it < 16; it++) {
            int idx = tid + it * 256;
            int tile = idx >> 10, r = (idx >> 3) & 127, c16 = idx & 7;
            uint32_t byte = (uint32_t)(r*128 + c16*16);
            uint32_t dst = bb + tile*TILE_B + (byte ^ ((byte >> 3) & 0x70));
            if (tile < 2) {
                const bf16* src = (tile == 0 ? Ah : Al) + (long long)(m0 + r)*lda + k0 + c16*8;
                CPA16(dst, src);
            } else if (n0 + r < N) {
                const bf16* src = (tile == 2 ? Bh : Bl) + (long long)(n0 + r)*ldb + k0 + c16*8;
                CPA16(dst, src);
            } else {
                asm volatile("st.shared.v4.b32 [%0], {%1,%1,%1,%1};"::"r"(dst),"r"(0u):"memory");
            }
        }
        CPA_COMMIT();
    };

    float acc[2][8][4];
#pragma unroll
    for (int i = 0; i < 2; i++)
#pragma unroll
        for (int j = 0; j < 8; j++)
#pragma unroll
            for (int q = 0; q < 4; q++) acc[i][j][q] = 0.f;

    fill(0, 0);
    if (nch > 1) fill(1, BKC);

    for (int ci = 0; ci < nch; ci++) {
        if (ci + 1 < nch) { CPA_WAIT(1); } else { CPA_WAIT(0); }
        __syncthreads();
        if (ci + 2 < nch) fill((ci + 2) % NSTAGE, (ci + 2) * BKC);

        const uint32_t bb = sb + (ci % NSTAGE) * BUF_B;
        const uint32_t tAh = bb, tAl = bb + TILE_B, tBh = bb + 2*TILE_B, tBl = bb + 3*TILE_B;
        const int arow = wm + (lane & 15);
        const int brow = wn + (lane & 7) + ((lane >> 4) << 3);

#pragma unroll
        for (int ks = 0; ks < 4; ks++) {
            const int akb = ks*2 + (lane >> 4);
            const int bkb = ks*2 + ((lane >> 3) & 1);
            uint32_t ah[2][4], al[2][4], bh[4][4], bl[4][4];
#pragma unroll
            for (int mi = 0; mi < 2; mi++) {
                ldsm4(ah[mi], swz(tAh, arow + mi*16, akb));
                ldsm4(al[mi], swz(tAl, arow + mi*16, akb));
            }
#pragma unroll
            for (int nj = 0; nj < 4; nj++) {
                ldsm4(bh[nj], swz(tBh, brow + nj*16, bkb));
                ldsm4(bl[nj], swz(tBl, brow + nj*16, bkb));
            }
#pragma unroll
            for (int mi = 0; mi < 2; mi++)
#pragma unroll
                for (int nj = 0; nj < 4; nj++) {
                    mma16816(acc[mi][2*nj],   ah[mi], &bh[nj][0]);
                    mma16816(acc[mi][2*nj+1], ah[mi], &bh[nj][2]);
                    mma16816(acc[mi][2*nj],   ah[mi], &bl[nj][0]);
                    mma16816(acc[mi][2*nj+1], ah[mi], &bl[nj][2]);
                    mma16816(acc[mi][2*nj],   al[mi], &bh[nj][0]);
                    mma16816(acc[mi][2*nj+1], al[mi], &bh[nj][2]);
                }
        }
        // NOTE: no trailing barrier needed — a warp reaches the next top barrier
        // only after all its MMAs (hence ldsm reads) are issued; the stage being
        // overwritten next is 3 chunks ahead.
    }

#pragma unroll
    for (int mi = 0; mi < 2; mi++) {
        const int r0 = m0 + wm + mi*16 + (lane >> 2);
#pragma unroll
        for (int nb = 0; nb < 8; nb++) {
            const int c = n0 + wn + nb*8 + (lane & 3)*2;
            if (c < N) {
                const float* a = acc[mi][nb];
                const int cc = (mode == 2) ? ((c >> 7) * QKD + (c & 127)) : c;
                const long long off0 = coff + (long long)r0 * ldc + cc;
                const long long off1 = off0 + 8LL * ldc;
                if (mode == 0) {
                    *(float2*)(C + off0) = make_float2(a[0], a[1]);
                    *(float2*)(C + off1) = make_float2(a[2], a[3]);
                } else {
                    bf16 h0,l0,h1,l1;
                    split2(a[0],h0,l0); split2(a[1],h1,l1);
                    *(__nv_bfloat162*)(Chi+off0) = __halves2bfloat162(h0,h1);
                    *(__nv_bfloat162*)(Clo+off0) = __halves2bfloat162(l0,l1);
                    split2(a[2],h0,l0); split2(a[3],h1,l1);
                    *(__nv_bfloat162*)(Chi+off1) = __halves2bfloat162(h0,h1);
                    *(__nv_bfloat162*)(Clo+off1) = __halves2bfloat162(l0,l1);
                }
            }
        }
    }
}

// ---- flash attention: S-MMA + online softmax + P@vT, one kernel ----
constexpr int FL_Q  = 0;          // 6 x 16384
constexpr int FL_KH = 98304;      // 6 x 8192
constexpr int FL_VT = 147456;     // 2 x 16384
constexpr int FL_P  = 180224;     // 2 x 16384
constexpr int FL_ST = 212992;     // stats (floats)
constexpr int SMEM_FLASH = 212992 + 7*512;

__global__ __launch_bounds__(256, 1)
void flash_pv(const bf16* __restrict__ QHh_, const bf16* __restrict__ QHl_,
              const bf16* __restrict__ KHh_, const bf16* __restrict__ KHl_,
              const bf16* __restrict__ vTh_, const bf16* __restrict__ vTl_,
              float* __restrict__ out)
{
    const int bh = blockIdx.y, b = bh >> 4, h = bh & 15;
    const int m0 = (gridDim.x - 1 - blockIdx.x) * 128;   // heavy tiles first
    const long long qkbase = (long long)b*(1024*3072) + h*QKD;
    const bf16* vTh = vTh_ + (long long)bh * 131072;
    const bf16* vTl = vTl_ + (long long)bh * 131072;
    out += (long long)b*(1024*2048) + (long long)m0*2048 + h*128;

    extern __shared__ __align__(1024) char smem[];
    const uint32_t sb = (uint32_t)__cvta_generic_to_shared(smem);
    float* mxA  = (float*)(smem + FL_ST);
    float* mxB  = mxA + 128;
    float* sA   = mxA + 256;
    float* sB   = mxA + 384;
    float* fbuf = mxA + 512;
    float* mrow = mxA + 640;
    float* srow = mxA + 768;

    const int tid = threadIdx.x, wid = tid >> 5, lane = tid & 31;
    const int wm  = (wid & 3) * 32;
    const int wns = (wid >> 2) * 32;
    const int wn  = (wid >> 2) * 64;
    const float scale = 0.07216878364870322f;   // 1/sqrt(192)

    auto QT = [&](int kt, int hl){ return sb + FL_Q  + (uint32_t)(kt*2+hl)*16384u; };
    auto KT = [&](int kt, int hl){ return sb + FL_KH + (uint32_t)(kt*2+hl)*8192u; };
    auto VTb = [&](int hl){ return sb + FL_VT + (uint32_t)hl*16384u; };
    auto PTb = [&](int hl){ return sb + FL_P  + (uint32_t)hl*16384u; };

    if (tid < 128) { mrow[tid] = -1e30f; srow[tid] = 0.f; }

    auto fill_kh = [&](int s0) {
#pragma unroll
        for (int it = 0; it < 12; it++) {
            int idx = tid + it*256;
            int tile = idx >> 9, r = (idx >> 3) & 63, c16 = idx & 7;
            int kt = tile >> 1, hl = tile & 1;
            uint32_t byte = (uint32_t)(r*128 + c16*16);
            uint32_t dst = KT(kt,hl) + (byte ^ ((byte>>3)&0x70));
            const bf16* src = (hl ? KHl_ : KHh_) + qkbase + (long long)(s0+r)*3072 + kt*64 + c16*8;
            CPA16(dst, src);
        }
    };
    auto fill_vt = [&](int s0) {
#pragma unroll
        for (int it = 0; it < 8; it++) {
            int idx = tid + it*256;
            int hl = idx >> 10, r = (idx >> 3) & 127, c16 = idx & 7;
            uint32_t byte = (uint32_t)(r*128 + c16*16);
            uint32_t dst = VTb(hl) + (byte ^ ((byte>>3)&0x70));
            const bf16* src = (hl ? vTl : vTh) + r*1024 + s0 + c16*8;
            CPA16(dst, src);
        }
    };

#pragma unroll
    for (int it = 0; it < 24; it++) {
        int idx = tid + it*256;
        int tile = idx >> 10, r = (idx >> 3) & 127, c16 = idx & 7;
        int kt = tile >> 1, hl = tile & 1;
        uint32_t byte = (uint32_t)(r*128 + c16*16);
        uint32_t dst = QT(kt,hl) + (byte ^ ((byte>>3)&0x70));
        const bf16* src = (hl ? QHl_ : QHh_) + qkbase + (long long)(m0+r)*3072 + kt*64 + c16*8;
        CPA16(dst, src);
    }
    fill_kh(0);
    CPA_COMMIT();
    fill_vt(0);
    CPA_COMMIT();

    float acc[2][8][4];
#pragma unroll
    for (int i = 0; i < 2; i++)
#pragma unroll
        for (int j = 0; j < 8; j++)
#pragma unroll
            for (int q = 0; q < 4; q++) acc[i][j][q] = 0.f;

    const int nch = m0/64 + 2;
    for (int ci = 0; ci < nch; ci++) {
        const int s0 = ci * 64;
        CPA_WAIT(1);
        __syncthreads();

        // ---- S-MMA ----
        float sacc[2][4][4];
#pragma unroll
        for (int i = 0; i < 2; i++)
#pragma unroll
            for (int j = 0; j < 4; j++)
#pragma unroll
                for (int q = 0; q < 4; q++) sacc[i][j][q] = 0.f;

        const int arow = wm + (lane & 15);
        const int brs = wns + (lane & 7) + ((lane >> 4) << 3);
#pragma unroll
        for (int kt = 0; kt < 3; kt++) {
#pragma unroll
            for (int ks = 0; ks < 4; ks++) {
                const int akb = ks*2 + (lane >> 4);
                const int bkb = ks*2 + ((lane >> 3) & 1);
                uint32_t ah[2][4], al[2][4], bhf[2][4], blf[2][4];
#pragma unroll
                for (int mi = 0; mi < 2; mi++) {
                    ldsm4(ah[mi], swz(QT(kt,0), arow + mi*16, akb));
                    ldsm4(al[mi], swz(QT(kt,1), arow + mi*16, akb));
                }
#pragma unroll
                for (int nj = 0; nj < 2; nj++) {
                    ldsm4(bhf[nj], swz(KT(kt,0), brs + nj*16, bkb));
                    ldsm4(blf[nj], swz(KT(kt,1), brs + nj*16, bkb));
                }
#pragma unroll
                for (int mi = 0; mi < 2; mi++)
#pragma unroll
                    for (int nj = 0; nj < 2; nj++) {
                        mma16816(sacc[mi][2*nj],   ah[mi], &bhf[nj][0]);
                        mma16816(sacc[mi][2*nj+1], ah[mi], &bhf[nj][2]);
                        mma16816(sacc[mi][2*nj],   ah[mi], &blf[nj][0]);
                        mma16816(sacc[mi][2*nj+1], ah[mi], &blf[nj][2]);
                        mma16816(sacc[mi][2*nj],   al[mi], &bhf[nj][0]);
                        mma16816(sacc[mi][2*nj+1], al[mi], &bhf[nj][2]);
                    }
            }
        }

        // ---- mask + scale + chunk row-max ----
#pragma unroll
        for (int mi = 0; mi < 2; mi++)
#pragma unroll
            for (int rh = 0; rh < 2; rh++) {
                const int rl = wm + mi*16 + (lane >> 2) + rh*8;
                const int rg = m0 + rl;
                float mx = -1e30f;
#pragma unroll
                for (int nb = 0; nb < 4; nb++) {
                    const int cg = s0 + wns + nb*8 + (lane & 3)*2;
                    float* a = sacc[mi][nb];
                    float v0 = (cg   <= rg) ? a[rh*2+0]*scale : -1e30f;
                    float v1 = (cg+1 <= rg) ? a[rh*2+1]*scale : -1e30f;
                    a[rh*2+0] = v0; a[rh*2+1] = v1;
                    mx = fmaxf(mx, fmaxf(v0, v1));
                }
                mx = fmaxf(mx, __shfl_xor_sync(0xffffffffu, mx, 1));
                mx = fmaxf(mx, __shfl_xor_sync(0xffffffffu, mx, 2));
                if ((lane & 3) == 0) ((wid >> 2) ? mxB : mxA)[rl] = mx;
            }
        __syncthreads();
        if (ci + 1 < nch) fill_kh(s0 + 64);
        CPA_COMMIT();

        // ---- online softmax ----
        float fv[2][2], nmv[2][2];
#pragma unroll
        for (int mi = 0; mi < 2; mi++)
#pragma unroll
            for (int rh = 0; rh < 2; rh++) {
                const int rl = wm + mi*16 + (lane >> 2) + rh*8;
                const float nm = fmaxf(mrow[rl], fmaxf(mxA[rl], mxB[rl]));
                const float f  = __expf(mrow[rl] - nm);
                nmv[mi][rh] = nm; fv[mi][rh] = f;
                float ps = 0.f;
#pragma unroll
                for (int nb = 0; nb < 4; nb++) {
                    const float* a = sacc[mi][nb];
                    float e0 = __expf(a[rh*2+0] - nm);
                    float e1 = __expf(a[rh*2+1] - nm);
                    ps += e0 + e1;
                    bf16 h0,l0,h1,l1;
                    split2(e0,h0,l0); split2(e1,h1,l1);
                    uint32_t byte = (uint32_t)(rl*128 + (wns + nb*8 + (lane & 3)*2)*2);
                    uint32_t sw = byte ^ ((byte>>3)&0x70);
                    asm volatile("st.shared.b32 [%0], %1;"::"r"(PTb(0)+sw),"r"(packbf2(h0,h1)):"memory");
                    asm volatile("st.shared.b32 [%0], %1;"::"r"(PTb(1)+sw),"r"(packbf2(l0,l1)):"memory");
                }
                ps += __shfl_xor_sync(0xffffffffu, ps, 1);
                ps += __shfl_xor_sync(0xffffffffu, ps, 2);
                if ((lane & 3) == 0) {
                    ((wid >> 2) ? sB : sA)[rl] = ps;
                    if ((wid >> 2) == 0) fbuf[rl] = f;
                }
            }
        __syncthreads();

        // ---- update running stats; rescale out-acc ----
        if ((lane & 3) == 0 && (wid >> 2) == 0) {
#pragma unroll
            for (int mi = 0; mi < 2; mi++)
#pragma unroll
                for (int rh = 0; rh < 2; rh++) {
                    const int rl = wm + mi*16 + (lane >> 2) + rh*8;
                    srow[rl] = srow[rl]*fv[mi][rh] + sA[rl] + sB[rl];
                    mrow[rl] = nmv[mi][rh];
                }
        }
#pragma unroll
        for (int mi = 0; mi < 2; mi++) {
            const int r0 = wm + mi*16 + (lane >> 2);
            const float fa = fbuf[r0], fb = fbuf[r0+8];
#pragma unroll
            for (int nb = 0; nb < 8; nb++) {
                acc[mi][nb][0]*=fa; acc[mi][nb][1]*=fa;
                acc[mi][nb][2]*=fb; acc[mi][nb][3]*=fb;
            }
        }

        CPA_WAIT(1);
        __syncthreads();

        // ---- PV MMA ----
        const int brow = wn + (lane & 7) + ((lane >> 4) << 3);
#pragma unroll
        for (int ks = 0; ks < 4; ks++) {
            const int akb = ks*2 + (lane >> 4);
            const int bkb = ks*2 + ((lane >> 3) & 1);
            uint32_t ah[2][4], al[2][4], bhf[4][4], blf[4][4];
#pragma unroll
            for (int mi = 0; mi < 2; mi++) {
                ldsm4(ah[mi], swz(PTb(0), arow + mi*16, akb));
                ldsm4(al[mi], swz(PTb(1), arow + mi*16, akb));
            }
#pragma unroll
            for (int nj = 0; nj < 4; nj++) {
                ldsm4(bhf[nj], swz(VTb(0), brow + nj*16, bkb));
                ldsm4(blf[nj], swz(VTb(1), brow + nj*16, bkb));
            }
#pragma unroll
            for (int mi = 0; mi < 2; mi++)
#pragma unroll
                for (int nj = 0; nj < 4; nj++) {
                    mma16816(acc[mi][2*nj],   ah[mi], &bhf[nj][0]);
                    mma16816(acc[mi][2*nj+1], ah[mi], &bhf[nj][2]);
                    mma16816(acc[mi][2*nj],   ah[mi], &blf[nj][0]);
                    mma16816(acc[mi][2*nj+1], ah[mi], &blf[nj][2]);
                    mma16816(acc[mi][2*nj],   al[mi], &bhf[nj][0]);
                    mma16816(acc[mi][2*nj+1], al[mi], &bhf[nj][2]);
                }
        }
        __syncthreads();
        if (ci + 1 < nch) fill_vt(s0 + 64);
        CPA_COMMIT();
    }

    // ---- epilogue ----
    __syncthreads();
#pragma unroll
    for (int mi = 0; mi < 2; mi++) {
        const int r0 = wm + mi*16 + (lane >> 2);
        const float ia = 1.0f / srow[r0], ib = 1.0f / srow[r0+8];
#pragma unroll
        for (int nb = 0; nb < 8; nb++) {
            const int c = wn + nb*8 + (lane & 3)*2;
            const float* a = acc[mi][nb];
            *(float2*)(out + (long long)r0*2048 + c)     = make_float2(a[0]*ia, a[1]*ia);
            *(float2*)(out + (long long)(r0+8)*2048 + c) = make_float2(a[2]*ib, a[3]*ib);
        }
    }
}

// ---- prep kernels ----
__global__ void split_copy4(const float4* __restrict__ s, __nv_bfloat162* __restrict__ h,
                            __nv_bfloat162* __restrict__ l, long long n4)
{
    long long i = (long long)blockIdx.x*256 + threadIdx.x;
    if (i >= n4) return;
    float4 v = s[i];
    bf16 h0,l0,h1,l1;
    split2(v.x,h0,l0); split2(v.y,h1,l1);
    h[2*i]   = __halves2bfloat162(h0,h1);
    l[2*i]   = __halves2bfloat162(l0,l1);
    split2(v.z,h0,l0); split2(v.w,h1,l1);
    h[2*i+1] = __halves2bfloat162(h0,h1);
    l[2*i+1] = __halves2bfloat162(l0,l1);
}

__global__ void split_transpose(const float* __restrict__ src, bf16* __restrict__ hi,
                                bf16* __restrict__ lo, int R, int C,
                                long long sIn, long long sOut)
{
    __shared__ float t[32][33];
    int b = blockIdx.z, c0 = blockIdx.x*32, r0 = blockIdx.y*32;
    int tx = threadIdx.x, ty = threadIdx.y;
    const float* s = src + (long long)b*sIn;
#pragma unroll
    for (int j = 0; j < 4; j++)
        t[ty + j*8][tx] = s[(long long)(r0 + ty + j*8)*C + c0 + tx];
    __syncthreads();
#pragma unroll
    for (int j = 0; j < 4; j++) {
        long long o = (long long)b*sOut + (long long)(c0 + ty + j*8)*R + r0 + tx;
        bf16 h, l; split2(t[tx][ty + j*8], h, l);
        hi[o] = h; lo[o] = l;
    }
}

__global__ void rope_q_kernel(const float* __restrict__ cqr, const float* __restrict__ fc,
                              const float* __restrict__ fs, bf16* __restrict__ QHh,
                              bf16* __restrict__ QHl)
{
    int idx = blockIdx.x*256 + threadIdx.x;
    if (idx >= BATCH*SEQ*NHEAD*32) return;
    int j = idx & 31, h = (idx >> 5) & 15, bt = idx >> 9;
    int t = bt & (SEQ-1);
    long long src = (long long)bt*(NHEAD*DHR) + h*DHR + 2*j;
    float re = cqr[src], im = cqr[src+1];
    float c = fc[t*32 + j], s = fs[t*32 + j];
    long long row = (long long)bt*(NHEAD*QKD) + h*QKD + 128 + 2*j;
    bf16 h0,l0,h1,l1;
    split2(re*c - im*s, h0, l0); split2(re*s + im*c, h1, l1);
    QHh[row] = h0; QHl[row] = l0; QHh[row+1] = h1; QHl[row+1] = l1;
}

// rope k: c_kr lives in KC cols [512..576) (hi+lo) -> KH[b][s][h][128+2j] for all h
__global__ void rope_k_kernel(const bf16* __restrict__ KCh, const bf16* __restrict__ KCl,
                              const float* __restrict__ fc, const float* __restrict__ fs,
                              bf16* __restrict__ KHh, bf16* __restrict__ KHl)
{
    int idx = blockIdx.x*256 + threadIdx.x;
    if (idx >= BATCH*SEQ*32) return;
    int j = idx & 31, bt = idx >> 5, t = bt & (SEQ-1);
    long long src = (long long)bt*576 + 512 + 2*j;
    float re = __bfloat162float(KCh[src])   + __bfloat162float(KCl[src]);
    float im = __bfloat162float(KCh[src+1]) + __bfloat162float(KCl[src+1]);
    float c = fc[t*32 + j], s = fs[t*32 + j];
    bf16 h0,l0,h1,l1;
    split2(re*c - im*s, h0, l0); split2(re*s + im*c, h1, l1);
    long long base = (long long)bt*(NHEAD*QKD) + 128 + 2*j;
#pragma unroll
    for (int h = 0; h < NHEAD; h++) {
        long long row = base + h*QKD;
        KHh[row] = h0; KHl[row] = l0; KHh[row+1] = h1; KHl[row+1] = l1;
    }
}

// ---- launch ----
extern "C" void kernel_launch(void* const* d_in, const int* in_sizes, int n_in,
                              void* d_out, int out_size)
{
    const float* x     = (const float*)d_in[0];
    const float* W_dq  = (const float*)d_in[1];
    const float* W_uq  = (const float*)d_in[2];
    const float* W_dkv = (const float*)d_in[3];
    const float* W_uk  = (const float*)d_in[4];
    const float* W_uv  = (const float*)d_in[5];
    const float* W_o   = (const float*)d_in[6];
    const float* W_qr  = (const float*)d_in[7];
    const float* W_kr  = (const float*)d_in[8];
    const float* fc    = (const float*)d_in[9];
    const float* fs    = (const float*)d_in[10];
    float* out = (float*)d_out;

    cudaFuncSetAttribute(gemm3, cudaFuncAttributeMaxDynamicSharedMemorySize, SMEM_GEMM);
    cudaFuncSetAttribute(flash_pv, cudaFuncAttributeMaxDynamicSharedMemorySize, SMEM_FLASH);

#define SYM(v, s) cudaGetSymbolAddress((void**)&v, s)
    bf16 *xh,*xl,*dqh,*dql,*ckvh,*ckvl,*qrh,*qrl,*uqTh,*uqTl,*ukh,*ukl;
    bf16 *woh,*wol,*uvTh,*uvTl,*Zh,*Zl,*cqh,*cql,*KCh,*KCl,*QHh,*QHl,*KHh,*KHl;
    bf16 *vTh,*vTl;
    float *cqr;
    SYM(xh,g_x_h); SYM(xl,g_x_l); SYM(dqh,g_Wdq_h); SYM(dql,g_Wdq_l);
    SYM(ckvh,g_Wckv_h); SYM(ckvl,g_Wckv_l);
    SYM(qrh,g_Wqr_h); SYM(qrl,g_Wqr_l); SYM(uqTh,g_WuqT_h); SYM(uqTl,g_WuqT_l);
    SYM(ukh,g_Wuk_h); SYM(ukl,g_Wuk_l);
    SYM(woh,g_Wo_h); SYM(wol,g_Wo_l); SYM(uvTh,g_WuvT_h); SYM(uvTl,g_WuvT_l);
    SYM(Zh,g_Z_h); SYM(Zl,g_Z_l); SYM(cqh,g_cq_h); SYM(cql,g_cq_l);
    SYM(KCh,g_KC_h); SYM(KCl,g_KC_l); SYM(QHh,g_QH_h); SYM(QHl,g_QH_l);
    SYM(KHh,g_KH_h); SYM(KHl,g_KH_l);
    SYM(vTh,g_vT_h); SYM(vTl,g_vT_l);
    SYM(cqr,g_cqr);
#undef SYM

    auto SC = [](const float* s, bf16* h, bf16* l, long long n) {
        split_copy4<<<(unsigned)((n/4 + 255)/256), 256>>>(
            (const float4*)s, (__nv_bfloat162*)h, (__nv_bfloat162*)l, n/4);
    };
    dim3 blk(256);
    const int LDH = NHEAD * QKD;                   // 3072
    const long long SB = (long long)SEQ * LDH;     // per-batch stride

    // ---- splits / transposes ----
    SC(x, xh, xl, 8388608);
    SC(W_dq, dqh, dql, 1048576);
    SC(W_dkv, ckvh, ckvl, 1048576);                     // rows 0-511 of combined
    SC(W_kr, ckvh + 1048576, ckvl + 1048576, 131072);   // rows 512-575
    SC(W_qr, qrh, qrl, 524288);
    SC(W_uk, ukh, ukl, 1048576);
    SC(W_o, woh, wol, 4194304);
    split_transpose<<<dim3(64, 16, 1), dim3(32, 8)>>>(W_uq, uqTh, uqTl, 512, 2048, 0, 0);
    split_transpose<<<dim3(16, 64, 1), dim3(32, 8)>>>(W_uv, uvTh, uvTl, 2048, 512, 0, 0);

    // ---- GEMMs ----
    // c_q = x @ W_dq^T -> split
    gemm3<<<dim3(4, 32, 1), blk, SMEM_GEMM>>>(xh, xl, 0, 0, 2048, dqh, dql, 0, 0, 2048,
        nullptr, cqh, cql, 0, 0, 512, 4096, 512, 2048, 1, 1, 0);
    // [c_kv | c_kr] = x @ Wckv^T -> KC split (N=576, ldc=576)
    gemm3<<<dim3(5, 32, 1), blk, SMEM_GEMM>>>(xh, xl, 0, 0, 2048, ckvh, ckvl, 0, 0, 2048,
        nullptr, KCh, KCl, 0, 0, 576, 4096, 576, 2048, 1, 1, 0);
    // Z = W_o @ W_uv -> split
    gemm3<<<dim3(4, 16, 1), blk, SMEM_GEMM>>>(woh, wol, 0, 0, 2048, uvTh, uvTl, 0, 0, 2048,
        nullptr, Zh, Zl, 0, 0, 512, 2048, 512, 2048, 1, 1, 0);
    // vT[b,h] = Z_h @ c_kv[b]^T -> split (128x1024)
    gemm3<<<dim3(8, 1, 64), blk, SMEM_GEMM>>>(Zh, Zl, 0, 65536, 512,
        KCh, KCl, 589824, 0, 576,
        nullptr, vTh, vTl, 2097152, 131072, 1024, 128, 1024, 512, 16, 1, 0);
    // c_qr = c_q @ W_qr^T -> fp32
    gemm3<<<dim3(8, 32, 1), blk, SMEM_GEMM>>>(cqh, cql, 0, 0, 512, qrh, qrl, 0, 0, 512,
        cqr, nullptr, nullptr, 0, 0, 1024, 4096, 1024, 512, 1, 0, 0);
    // Q = c_q @ WuqT^T -> QH split, col remap, ldc=3072
    gemm3<<<dim3(16, 32, 1), blk, SMEM_GEMM>>>(cqh, cql, 0, 0, 512, uqTh, uqTl, 0, 0, 512,
        nullptr, QHh, QHl, 0, 0, LDH, 4096, 2048, 512, 1, 2, 0);
    // KH[b,h] = c_kv[b] @ W_uk_h^T -> split, ldc=3072
    gemm3<<<dim3(1, 8, 64), blk, SMEM_GEMM>>>(KCh, KCl, 589824, 0, 576,
        ukh, ukl, 0, 65536, 512,
        nullptr, KHh, KHl, SB, QKD, LDH, 1024, 128, 512, 16, 1, 0);
    // RoPE tails
    rope_q_kernel<<<(BATCH*SEQ*NHEAD*32 + 255)/256, 256>>>(cqr, fc, fs, QHh, QHl);
    rope_k_kernel<<<(BATCH*SEQ*32 + 255)/256, 256>>>(KCh, KCl, fc, fs, KHh, KHl);

    // ---- flash attention (S + softmax + PV fused) ----
    flash_pv<<<dim3(8, 64, 1), blk, SMEM_FLASH>>>(QHh, QHl, KHh, KHl, vTh, vTl, out);
}